// round 12
// baseline (speedup 1.0000x reference)
#include <cuda_runtime.h>
#include <cuda_bf16.h>
#include <math.h>

// Problem constants
#define Bsz 256
#define Nn  128
#define Ff  133
#define Hh  8
#define NHID 64
#define HID 300
#define FP_DIM 1489
#define FP2 512
#define HD (Hh*NHID)     // 512
#define ALPHA 0.2f

#define K1P   160        // Ff padded so 3*K1P % 32 == 0
#define K1T   (3*K1P)    // 480
#define K3T   (3*HD)     // 1536
#define N3P   384        // HID padded to 3 tiles of 128
#define KF    1536       // FP_DIM padded
#define KFT   (3*KF)     // 4608
#define FS1   12         // fc1 split-K
#define KC1   (KFT/FS1)  // 384

// ---------------- scratch (device globals) ----------------------------------------
__device__ __nv_bfloat16 g_Apk [(size_t)Bsz*Nn * K1T];
__device__ __nv_bfloat16 g_Bpk1[(size_t)HD * K1T];
__device__ float         g_Wh  [(size_t)Bsz*Nn * HD];
__device__ __nv_bfloat16 g_hpk [(size_t)Bsz*Nn * K3T];
__device__ __nv_bfloat16 g_Bpk3[(size_t)N3P * K3T];
__device__ float g_Wh2 [(size_t)Bsz*Nn * HID];
__device__ float g_ss2 [Bsz * Nn];
__device__ float g_dd2 [Bsz * Nn];
__device__ float g_O   [(size_t)Bsz*Nn * HID];
__device__ float g_gat [Bsz * HID];
__device__ __nv_bfloat16 g_fpk [(size_t)Bsz * KFT];
__device__ __nv_bfloat16 g_w1k [(size_t)FP2 * KFT];
__device__ float g_part[(size_t)FS1 * Bsz * FP2];
__device__ float g_t1  [Bsz * FP2];

// ---------------- helpers ----------------
__device__ __forceinline__ float warp_sum(float v) {
    #pragma unroll
    for (int o = 16; o; o >>= 1) v += __shfl_down_sync(0xffffffffu, v, o);
    return v;
}
__device__ __forceinline__ float warp_max(float v) {
    #pragma unroll
    for (int o = 16; o; o >>= 1) v = fmaxf(v, __shfl_down_sync(0xffffffffu, v, o));
    return v;
}
__device__ __forceinline__ unsigned smem_u32(const void* p) {
    unsigned a;
    asm("{ .reg .u64 t; cvta.to.shared.u64 t, %1; cvt.u32.u64 %0, t; }" : "=r"(a) : "l"(p));
    return a;
}
__device__ __forceinline__ void ldsm4(const __nv_bfloat16* p,
                                      unsigned& r0, unsigned& r1, unsigned& r2, unsigned& r3) {
    unsigned a = smem_u32(p);
    asm volatile("ldmatrix.sync.aligned.m8n8.x4.shared.b16 {%0,%1,%2,%3}, [%4];"
                 : "=r"(r0), "=r"(r1), "=r"(r2), "=r"(r3) : "r"(a));
}
#define MMA16816(acc, a0, a1, a2, a3, b0, b1) \
    asm volatile("mma.sync.aligned.m16n8k16.row.col.f32.bf16.bf16.f32 " \
                 "{%0,%1,%2,%3}, {%4,%5,%6,%7}, {%8,%9}, {%0,%1,%2,%3};" \
                 : "+f"((acc)[0]), "+f"((acc)[1]), "+f"((acc)[2]), "+f"((acc)[3]) \
                 : "r"(a0), "r"(a1), "r"(a2), "r"(a3), "r"(b0), "r"(b1))

// ================= mma_gemm: bf16 HMMA GEMM, 128x128 tile, KC=32, ldmatrix ======
#define MSTR 40
__global__ __launch_bounds__(256) void mma_gemm(
    const __nv_bfloat16* __restrict__ A, const __nv_bfloat16* __restrict__ B,
    float* __restrict__ C, int Ktot, int lda, int ldb, int Nreal, int ldc,
    long long bA, long long bB, long long bC)
{
    __shared__ __align__(16) __nv_bfloat16 As[2][128][MSTR];
    __shared__ __align__(16) __nv_bfloat16 Bs[2][128][MSTR];

    A += (long long)blockIdx.z * bA;
    B += (long long)blockIdx.z * bB;
    C += (long long)blockIdx.z * bC;

    const int tid = threadIdx.x;
    const int wid = tid >> 5, lane = tid & 31;
    const int wy = wid & 3, wx = wid >> 2;
    const int lq = lane & 7, lg8 = (lane >> 3) & 1, lg16 = lane >> 4;
    const int fgid = lane >> 2, ftig = lane & 3;
    const int row0 = blockIdx.y * 128, col0 = blockIdx.x * 128;

    const int lr0 = tid >> 2;
    const int lcq = (tid & 3) << 3;

    uint4 va0, va1, vb0, vb1;
    auto load_g = [&](int k0) {
        va0 = *reinterpret_cast<const uint4*>(A + (size_t)(row0 + lr0) * lda + k0 + lcq);
        va1 = *reinterpret_cast<const uint4*>(A + (size_t)(row0 + lr0 + 64) * lda + k0 + lcq);
        vb0 = *reinterpret_cast<const uint4*>(B + (size_t)(col0 + lr0) * ldb + k0 + lcq);
        vb1 = *reinterpret_cast<const uint4*>(B + (size_t)(col0 + lr0 + 64) * ldb + k0 + lcq);
    };
    auto store_s = [&](int buf) {
        *reinterpret_cast<uint4*>(&As[buf][lr0][lcq])      = va0;
        *reinterpret_cast<uint4*>(&As[buf][lr0 + 64][lcq]) = va1;
        *reinterpret_cast<uint4*>(&Bs[buf][lr0][lcq])      = vb0;
        *reinterpret_cast<uint4*>(&Bs[buf][lr0 + 64][lcq]) = vb1;
    };

    float acc[2][8][4];
    #pragma unroll
    for (int mt = 0; mt < 2; mt++)
        #pragma unroll
        for (int nt = 0; nt < 8; nt++)
            #pragma unroll
            for (int q = 0; q < 4; q++) acc[mt][nt][q] = 0.f;

    const int nsteps = Ktot >> 5;
    load_g(0);
    store_s(0);
    __syncthreads();

    for (int s = 0; s < nsteps; s++) {
        const int cur = s & 1;
        if (s + 1 < nsteps) load_g((s + 1) << 5);

        #pragma unroll
        for (int kk = 0; kk < 32; kk += 16) {
            unsigned af[2][4], bfr[8][2];
            #pragma unroll
            for (int mt = 0; mt < 2; mt++) {
                const int r = wy * 32 + mt * 16 + lq + 8 * lg8;
                ldsm4(&As[cur][r][kk + 8 * lg16],
                      af[mt][0], af[mt][1], af[mt][2], af[mt][3]);
            }
            #pragma unroll
            for (int p = 0; p < 4; p++) {
                const int r = wx * 64 + p * 16 + lq + 8 * lg8;
                unsigned r0, r1, r2, r3;
                ldsm4(&Bs[cur][r][kk + 8 * lg16], r0, r1, r2, r3);
                bfr[2 * p][0] = r0; bfr[2 * p + 1][0] = r1;
                bfr[2 * p][1] = r2; bfr[2 * p + 1][1] = r3;
            }
            #pragma unroll
            for (int mt = 0; mt < 2; mt++)
                #pragma unroll
                for (int nt = 0; nt < 8; nt++)
                    MMA16816(acc[mt][nt], af[mt][0], af[mt][1], af[mt][2], af[mt][3],
                             bfr[nt][0], bfr[nt][1]);
        }

        if (s + 1 < nsteps) store_s(cur ^ 1);
        __syncthreads();
    }

    #pragma unroll
    for (int mt = 0; mt < 2; mt++) {
        const int r0 = row0 + wy * 32 + mt * 16 + fgid;
        #pragma unroll
        for (int nt = 0; nt < 8; nt++) {
            const int c = col0 + wx * 64 + nt * 8 + 2 * ftig;
            if (c < Nreal) {
                *reinterpret_cast<float2*>(C + (size_t)r0 * ldc + c) =
                    make_float2(acc[mt][nt][0], acc[mt][nt][1]);
                *reinterpret_cast<float2*>(C + (size_t)(r0 + 8) * ldc + c) =
                    make_float2(acc[mt][nt][2], acc[mt][nt][3]);
            }
        }
    }
}

// ---------------- packing kernels ------------------------------------------------
__global__ void pack_atoms(const float* __restrict__ src) {
    int t = blockIdx.x * blockDim.x + threadIdx.x;
    if (t >= Bsz * Nn * K1P) return;
    int k = t % K1P, r = t / K1P;
    float x = (k < Ff) ? src[(size_t)r * Ff + k] : 0.f;
    __nv_bfloat16 hi = __float2bfloat16(x);
    __nv_bfloat16 lo = __float2bfloat16(x - __bfloat162float(hi));
    __nv_bfloat16* row = g_Apk + (size_t)r * K1T;
    row[k] = hi; row[K1P + k] = hi; row[2 * K1P + k] = lo;
}
__global__ void pack_B1(const float* __restrict__ W_heads) {
    int t = blockIdx.x * blockDim.x + threadIdx.x;
    if (t >= HD * K1P) return;
    int k = t % K1P, n = t / K1P;
    int h = n >> 6, d = n & 63;
    float x = (k < Ff) ? W_heads[((size_t)h * Ff + k) * NHID + d] : 0.f;
    __nv_bfloat16 hi = __float2bfloat16(x);
    __nv_bfloat16 lo = __float2bfloat16(x - __bfloat162float(hi));
    __nv_bfloat16* row = g_Bpk1 + (size_t)n * K1T;
    row[k] = hi; row[K1P + k] = lo; row[2 * K1P + k] = hi;
}
__global__ void pack_B3(const float* __restrict__ W_out) {
    int t = blockIdx.x * blockDim.x + threadIdx.x;
    if (t >= N3P * HD) return;
    int k = t % HD, n = t / HD;
    float x = (n < HID) ? W_out[(size_t)k * HID + n] : 0.f;
    __nv_bfloat16 hi = __float2bfloat16(x);
    __nv_bfloat16 lo = __float2bfloat16(x - __bfloat162float(hi));
    __nv_bfloat16* row = g_Bpk3 + (size_t)n * K3T;
    row[k] = hi; row[HD + k] = lo; row[2 * HD + k] = hi;
}
__global__ void pack_fp(const float* __restrict__ fp) {
    int t = blockIdx.x * blockDim.x + threadIdx.x;
    if (t >= Bsz * KF) return;
    int k = t % KF, r = t / KF;
    float x = (k < FP_DIM) ? fp[(size_t)r * FP_DIM + k] : 0.f;
    __nv_bfloat16 hi = __float2bfloat16(x);
    __nv_bfloat16 lo = __float2bfloat16(x - __bfloat162float(hi));
    __nv_bfloat16* row = g_fpk + (size_t)r * KFT;
    row[k] = hi; row[KF + k] = hi; row[2 * KF + k] = lo;
}
__global__ void pack_w1k(const float* __restrict__ w) {
    int t = blockIdx.x * blockDim.x + threadIdx.x;
    if (t >= FP2 * KF) return;
    int k = t % KF, n = t / KF;
    float x = (k < FP_DIM) ? w[(size_t)k * FP2 + n] : 0.f;
    __nv_bfloat16 hi = __float2bfloat16(x);
    __nv_bfloat16 lo = __float2bfloat16(x - __bfloat162float(hi));
    __nv_bfloat16* row = g_w1k + (size_t)n * KFT;
    row[k] = hi; row[KF + k] = lo; row[2 * KF + k] = hi;
}

// ---------------- fc1 reduce ------------------------------------------------------
__global__ void fc1_reduce(const float* __restrict__ fc1_b) {
    int t = blockIdx.x * blockDim.x + threadIdx.x;
    if (t >= Bsz * FP2) return;
    float s = 0.f;
    #pragma unroll
    for (int z = 0; z < FS1; z++) s += g_part[(size_t)z * Bsz * FP2 + t];
    g_t1[t] = fmaxf(s + fc1_b[t & (FP2 - 1)], 0.f);
}

// ============ fused attention on HMMA: shared layout ==============================
// Ph[128][PSTR], Pl[128][PSTR] : split softmax numerators (row=i, col=j)
// Vh[64][PSTR],  Vl[64][PSTR]  : split V^T (row=d, col=j)
// 3 passes: Ph*Vh + Ph*Vl + Pl*Vh  -> exact to ~2^-17
#define PSTR 136
#define ATT_SMEM ((128*PSTR*2 + 64*PSTR*2) * 2 + 3 * 128 * 4)

// ---------------- gat1_mma: per (b,h) --------------------------------------------
__global__ __launch_bounds__(256) void gat1_mma(const float* __restrict__ a_heads,
                                                const int* __restrict__ adj)
{
    extern __shared__ __align__(16) char smraw[];
    __nv_bfloat16* Ph = reinterpret_cast<__nv_bfloat16*>(smraw);
    __nv_bfloat16* Pl = Ph + 128 * PSTR;
    __nv_bfloat16* Vh = Pl + 128 * PSTR;
    __nv_bfloat16* Vl = Vh + 64 * PSTR;
    float* ss   = reinterpret_cast<float*>(Vl + 64 * PSTR);
    float* dd   = ss + 128;
    float* rsum = dd + 128;

    const int z = blockIdx.x;
    const int b = z >> 3, h = z & 7;
    const int tid = threadIdx.x, wid = tid >> 5, lane = tid & 31;
    const float* whbase = g_Wh + ((size_t)b * Nn) * HD + h * NHID;

    if (tid < 128) rsum[tid] = 0.f;

    // scores (from f32 global)
    const float* a1 = a_heads + h * (2 * NHID);
    const float* a2v = a1 + NHID;
    for (int j = wid; j < 128; j += 8) {
        const float w0 = whbase[(size_t)j * HD + lane];
        const float w1 = whbase[(size_t)j * HD + lane + 32];
        float s1 = fmaf(w0, a1[lane], w1 * a1[lane + 32]);
        float s2 = fmaf(w0, a2v[lane], w1 * a2v[lane + 32]);
        s1 = warp_sum(s1); s2 = warp_sum(s2);
        if (lane == 0) { ss[j] = s1; dd[j] = s2; }
    }
    // V^T split: Vh/Vl[d][j]
    for (int t = tid; t < 64 * 128; t += 256) {
        const int j = t >> 6, d = t & 63;
        float x = whbase[(size_t)j * HD + d];
        __nv_bfloat16 hi = __float2bfloat16(x);
        Vh[d * PSTR + j] = hi;
        Vl[d * PSTR + j] = __float2bfloat16(x - __bfloat162float(hi));
    }
    __syncthreads();

    // generate split probs + row sums
    const int* adjb = adj + (size_t)b * Nn * Nn;
    const int am = tid >> 2, aq = (tid & 3) << 2;
    const float sm0 = ss[am], sm1 = ss[am + 64];
    float rs0 = 0.f, rs1 = 0.f;
    for (int jb = 0; jb < 8; jb++) {
        const int k0 = jb << 4;
        int mm0[4], mm1[4];
        *reinterpret_cast<int4*>(mm0) = *reinterpret_cast<const int4*>(adjb + am * Nn + k0 + aq);
        *reinterpret_cast<int4*>(mm1) = *reinterpret_cast<const int4*>(adjb + (am + 64) * Nn + k0 + aq);
        #pragma unroll
        for (int q = 0; q < 4; q++) {
            const int j = k0 + aq + q;
            const float dv = dd[j];
            float e0 = sm0 + dv; e0 = (e0 > 0.f) ? e0 : ALPHA * e0;
            float e1 = sm1 + dv; e1 = (e1 > 0.f) ? e1 : ALPHA * e1;
            float p0 = (mm0[q] > 0) ? __expf(e0) : 0.f;
            float p1 = (mm1[q] > 0) ? __expf(e1) : 0.f;
            rs0 += p0; rs1 += p1;
            __nv_bfloat16 h0 = __float2bfloat16(p0);
            __nv_bfloat16 h1 = __float2bfloat16(p1);
            Ph[am * PSTR + j] = h0;
            Pl[am * PSTR + j] = __float2bfloat16(p0 - __bfloat162float(h0));
            Ph[(am + 64) * PSTR + j] = h1;
            Pl[(am + 64) * PSTR + j] = __float2bfloat16(p1 - __bfloat162float(h1));
        }
    }
    atomicAdd(&rsum[am], rs0);
    atomicAdd(&rsum[am + 64], rs1);
    __syncthreads();

    // MMA: warp grid 4(m) x 2(n), warp tile 32x32
    const int wy = wid & 3, wx = wid >> 2;
    const int lq = lane & 7, lg8 = (lane >> 3) & 1, lg16 = lane >> 4;
    const int fgid = lane >> 2, ftig = lane & 3;

    float acc[2][4][4];
    #pragma unroll
    for (int mt = 0; mt < 2; mt++)
        #pragma unroll
        for (int nt = 0; nt < 4; nt++)
            #pragma unroll
            for (int q = 0; q < 4; q++) acc[mt][nt][q] = 0.f;

    #pragma unroll
    for (int pass = 0; pass < 3; pass++) {
        const __nv_bfloat16* Ap = (pass < 2) ? Ph : Pl;
        const __nv_bfloat16* Bp = (pass == 1) ? Vl : Vh;
        #pragma unroll
        for (int ks = 0; ks < 8; ks++) {
            unsigned af[2][4], bfr[4][2];
            #pragma unroll
            for (int mt = 0; mt < 2; mt++) {
                const int r = wy * 32 + mt * 16 + lq + 8 * lg8;
                ldsm4(Ap + r * PSTR + ks * 16 + 8 * lg16,
                      af[mt][0], af[mt][1], af[mt][2], af[mt][3]);
            }
            #pragma unroll
            for (int p = 0; p < 2; p++) {
                const int rn = wx * 32 + p * 16 + lq + 8 * lg8;
                unsigned r0, r1, r2, r3;
                ldsm4(Bp + rn * PSTR + ks * 16 + 8 * lg16, r0, r1, r2, r3);
                bfr[2 * p][0] = r0; bfr[2 * p + 1][0] = r1;
                bfr[2 * p][1] = r2; bfr[2 * p + 1][1] = r3;
            }
            #pragma unroll
            for (int mt = 0; mt < 2; mt++)
                #pragma unroll
                for (int nt = 0; nt < 4; nt++)
                    MMA16816(acc[mt][nt], af[mt][0], af[mt][1], af[mt][2], af[mt][3],
                             bfr[nt][0], bfr[nt][1]);
        }
    }

    // epilogue: scale, elu, split-pack into g_hpk
    #pragma unroll
    for (int mt = 0; mt < 2; mt++) {
        const int r = wy * 32 + mt * 16 + fgid;
        const float inv0 = 1.f / rsum[r];
        const float inv8 = 1.f / rsum[r + 8];
        __nv_bfloat16* rp0 = g_hpk + (size_t)(b * Nn + r) * K3T + h * NHID;
        __nv_bfloat16* rp8 = g_hpk + (size_t)(b * Nn + r + 8) * K3T + h * NHID;
        #pragma unroll
        for (int nt = 0; nt < 4; nt++) {
            const int c = wx * 32 + nt * 8 + 2 * ftig;
            float v0 = acc[mt][nt][0] * inv0, v1 = acc[mt][nt][1] * inv0;
            float v2 = acc[mt][nt][2] * inv8, v3 = acc[mt][nt][3] * inv8;
            v0 = (v0 > 0.f) ? v0 : expm1f(v0);
            v1 = (v1 > 0.f) ? v1 : expm1f(v1);
            v2 = (v2 > 0.f) ? v2 : expm1f(v2);
            v3 = (v3 > 0.f) ? v3 : expm1f(v3);
            __nv_bfloat16 h0 = __float2bfloat16(v0), h1 = __float2bfloat16(v1);
            __nv_bfloat16 h2 = __float2bfloat16(v2), h3 = __float2bfloat16(v3);
            unsigned hp0 = (unsigned)__bfloat16_as_ushort(h0) | ((unsigned)__bfloat16_as_ushort(h1) << 16);
            unsigned lp0 = (unsigned)__bfloat16_as_ushort(__float2bfloat16(v0 - __bfloat162float(h0)))
                         | ((unsigned)__bfloat16_as_ushort(__float2bfloat16(v1 - __bfloat162float(h1))) << 16);
            unsigned hp8 = (unsigned)__bfloat16_as_ushort(h2) | ((unsigned)__bfloat16_as_ushort(h3) << 16);
            unsigned lp8 = (unsigned)__bfloat16_as_ushort(__float2bfloat16(v2 - __bfloat162float(h2)))
                         | ((unsigned)__bfloat16_as_ushort(__float2bfloat16(v3 - __bfloat162float(h3))) << 16);
            *reinterpret_cast<unsigned*>(rp0 + c)          = hp0;
            *reinterpret_cast<unsigned*>(rp0 + HD + c)     = hp0;
            *reinterpret_cast<unsigned*>(rp0 + 2 * HD + c) = lp0;
            *reinterpret_cast<unsigned*>(rp8 + c)          = hp8;
            *reinterpret_cast<unsigned*>(rp8 + HD + c)     = hp8;
            *reinterpret_cast<unsigned*>(rp8 + 2 * HD + c) = lp8;
        }
    }
}

// ---------------- score2 ----------------------------------------------------------
__global__ __launch_bounds__(256) void score2_kernel(const float* __restrict__ a_out)
{
    const int b = blockIdx.x;
    const int tid = threadIdx.x, warp = tid >> 5, lane = tid & 31;
    const float* W = g_Wh2 + (size_t)b * Nn * HID;
    for (int j = warp; j < 128; j += 8) {
        float s1 = 0.f, s2 = 0.f;
        #pragma unroll
        for (int t = 0; t < 10; t++) {
            int d = lane + 32 * t;
            if (d < HID) {
                float w = W[(size_t)j * HID + d];
                s1 = fmaf(w, a_out[d], s1);
                s2 = fmaf(w, a_out[HID + d], s2);
            }
        }
        s1 = warp_sum(s1); s2 = warp_sum(s2);
        if (lane == 0) { g_ss2[b * Nn + j] = s1; g_dd2[b * Nn + j] = s2; }
    }
}

// ---------------- av2_mma: per (b, 64-col block), grid (5,1,Bsz) ------------------
__global__ __launch_bounds__(256) void av2_mma(const int* __restrict__ adj)
{
    extern __shared__ __align__(16) char smraw[];
    __nv_bfloat16* Ph = reinterpret_cast<__nv_bfloat16*>(smraw);
    __nv_bfloat16* Pl = Ph + 128 * PSTR;
    __nv_bfloat16* Vh = Pl + 128 * PSTR;
    __nv_bfloat16* Vl = Vh + 64 * PSTR;
    float* ss   = reinterpret_cast<float*>(Vl + 64 * PSTR);
    float* dd   = ss + 128;
    float* rsum = dd + 128;

    const int b = blockIdx.z;
    const int col0 = blockIdx.x * 64;
    const int tid = threadIdx.x, wid = tid >> 5, lane = tid & 31;
    const float* Wb = g_Wh2 + (size_t)b * Nn * HID;

    if (tid < 128) {
        ss[tid] = g_ss2[b * Nn + tid];
        dd[tid] = g_dd2[b * Nn + tid];
        rsum[tid] = 0.f;
    }
    // V^T split for this 64-col slice
    for (int t = tid; t < 64 * 128; t += 256) {
        const int j = t >> 6, d = t & 63;
        const int gc = col0 + d;
        float x = (gc < HID) ? Wb[(size_t)j * HID + gc] : 0.f;
        __nv_bfloat16 hi = __float2bfloat16(x);
        Vh[d * PSTR + j] = hi;
        Vl[d * PSTR + j] = __float2bfloat16(x - __bfloat162float(hi));
    }
    __syncthreads();

    const int* adjb = adj + (size_t)b * Nn * Nn;
    const int am = tid >> 2, aq = (tid & 3) << 2;
    const float sm0 = ss[am], sm1 = ss[am + 64];
    float rs0 = 0.f, rs1 = 0.f;
    for (int jb = 0; jb < 8; jb++) {
        const int k0 = jb << 4;
        int mm0[4], mm1[4];
        *reinterpret_cast<int4*>(mm0) = *reinterpret_cast<const int4*>(adjb + am * Nn + k0 + aq);
        *reinterpret_cast<int4*>(mm1) = *reinterpret_cast<const int4*>(adjb + (am + 64) * Nn + k0 + aq);
        #pragma unroll
        for (int q = 0; q < 4; q++) {
            const int j = k0 + aq + q;
            const float dv = dd[j];
            float e0 = sm0 + dv; e0 = (e0 > 0.f) ? e0 : ALPHA * e0;
            float e1 = sm1 + dv; e1 = (e1 > 0.f) ? e1 : ALPHA * e1;
            float p0 = (mm0[q] > 0) ? __expf(e0) : 0.f;
            float p1 = (mm1[q] > 0) ? __expf(e1) : 0.f;
            rs0 += p0; rs1 += p1;
            __nv_bfloat16 h0 = __float2bfloat16(p0);
            __nv_bfloat16 h1 = __float2bfloat16(p1);
            Ph[am * PSTR + j] = h0;
            Pl[am * PSTR + j] = __float2bfloat16(p0 - __bfloat162float(h0));
            Ph[(am + 64) * PSTR + j] = h1;
            Pl[(am + 64) * PSTR + j] = __float2bfloat16(p1 - __bfloat162float(h1));
        }
    }
    atomicAdd(&rsum[am], rs0);
    atomicAdd(&rsum[am + 64], rs1);
    __syncthreads();

    const int wy = wid & 3, wx = wid >> 2;
    const int lq = lane & 7, lg8 = (lane >> 3) & 1, lg16 = lane >> 4;
    const int fgid = lane >> 2, ftig = lane & 3;

    float acc[2][4][4];
    #pragma unroll
    for (int mt = 0; mt < 2; mt++)
        #pragma unroll
        for (int nt = 0; nt < 4; nt++)
            #pragma unroll
            for (int q = 0; q < 4; q++) acc[mt][nt][q] = 0.f;

    #pragma unroll
    for (int pass = 0; pass < 3; pass++) {
        const __nv_bfloat16* Ap = (pass < 2) ? Ph : Pl;
        const __nv_bfloat16* Bp = (pass == 1) ? Vl : Vh;
        #pragma unroll
        for (int ks = 0; ks < 8; ks++) {
            unsigned af[2][4], bfr[4][2];
            #pragma unroll
            for (int mt = 0; mt < 2; mt++) {
                const int r = wy * 32 + mt * 16 + lq + 8 * lg8;
                ldsm4(Ap + r * PSTR + ks * 16 + 8 * lg16,
                      af[mt][0], af[mt][1], af[mt][2], af[mt][3]);
            }
            #pragma unroll
            for (int p = 0; p < 2; p++) {
                const int rn = wx * 32 + p * 16 + lq + 8 * lg8;
                unsigned r0, r1, r2, r3;
                ldsm4(Bp + rn * PSTR + ks * 16 + 8 * lg16, r0, r1, r2, r3);
                bfr[2 * p][0] = r0; bfr[2 * p + 1][0] = r1;
                bfr[2 * p][1] = r2; bfr[2 * p + 1][1] = r3;
            }
            #pragma unroll
            for (int mt = 0; mt < 2; mt++)
                #pragma unroll
                for (int nt = 0; nt < 4; nt++)
                    MMA16816(acc[mt][nt], af[mt][0], af[mt][1], af[mt][2], af[mt][3],
                             bfr[nt][0], bfr[nt][1]);
        }
    }

    float* Cb = g_O + (size_t)b * Nn * HID;
    #pragma unroll
    for (int mt = 0; mt < 2; mt++) {
        const int r = wy * 32 + mt * 16 + fgid;
        const float inv0 = 1.f / rsum[r];
        const float inv8 = 1.f / rsum[r + 8];
        #pragma unroll
        for (int nt = 0; nt < 4; nt++) {
            const int c = col0 + wx * 32 + nt * 8 + 2 * ftig;
            if (c < HID) {
                float v0 = acc[mt][nt][0] * inv0, v1 = acc[mt][nt][1] * inv0;
                float v2 = acc[mt][nt][2] * inv8, v3 = acc[mt][nt][3] * inv8;
                v0 = (v0 > 0.f) ? v0 : expm1f(v0);
                v1 = (v1 > 0.f) ? v1 : expm1f(v1);
                v2 = (v2 > 0.f) ? v2 : expm1f(v2);
                v3 = (v3 > 0.f) ? v3 : expm1f(v3);
                *reinterpret_cast<float2*>(Cb + (size_t)r * HID + c)       = make_float2(v0, v1);
                *reinterpret_cast<float2*>(Cb + (size_t)(r + 8) * HID + c) = make_float2(v2, v3);
            }
        }
    }
}

// ---------------- ls2 -------------------------------------------------------------
__global__ __launch_bounds__(256) void ls2_kernel()
{
    __shared__ float acc[8 * HID];
    const int b = blockIdx.x;
    const int tid = threadIdx.x, warp = tid >> 5, lane = tid & 31;
    for (int t = tid; t < 8 * HID; t += 256) acc[t] = 0.f;
    __syncthreads();

    const float* O = g_O + (size_t)b * Nn * HID;
    float* accw = acc + warp * HID;
    for (int i = warp; i < 128; i += 8) {
        float o[10];
        #pragma unroll
        for (int t = 0; t < 10; t++) {
            int d = lane + 32 * t;
            o[t] = (d < HID) ? O[(size_t)i * HID + d] : -1e30f;
        }
        float m = o[0];
        #pragma unroll
        for (int t = 1; t < 10; t++) m = fmaxf(m, o[t]);
        m = warp_max(m);
        m = __shfl_sync(0xffffffffu, m, 0);
        float se = 0.f;
        #pragma unroll
        for (int t = 0; t < 10; t++) se += __expf(o[t] - m);
        se = warp_sum(se);
        se = __shfl_sync(0xffffffffu, se, 0);
        const float lse = m + logf(se);
        #pragma unroll
        for (int t = 0; t < 10; t++) {
            int d = lane + 32 * t;
            if (d < HID) accw[d] += o[t] - lse;
        }
    }
    __syncthreads();
    for (int d = tid; d < HID; d += 256) {
        float s = 0.f;
        #pragma unroll
        for (int w = 0; w < 8; w++) s += acc[w * HID + d];
        g_gat[b * HID + d] = s * (1.f / 128.f);
    }
}

// ---------------- head ------------------------------------------------------------
#define HB 4
__global__ __launch_bounds__(256) void head_fused(
    const float* __restrict__ fc2_w, const float* __restrict__ fc2_b,
    const float* __restrict__ Wg,    const float* __restrict__ bg,
    const float* __restrict__ Wf,    const float* __restrict__ bf,
    const float* __restrict__ W1,    const float* __restrict__ b1,
    const float* __restrict__ w2,    const float* __restrict__ b2,
    float* __restrict__ out)
{
    __shared__ float t1s [HB][512];
    __shared__ float gats[HB][HID];
    __shared__ float fpns[HB][HID];
    __shared__ float us  [HB][HID];
    __shared__ float vs  [HB][HID];
    __shared__ float ys  [HB][HID];

    const int b0 = blockIdx.x * HB;
    const int tid = threadIdx.x;

    for (int t = tid; t < HB * 512; t += 256) {
        int r = t >> 9;
        t1s[r][t & 511] = g_t1[(size_t)(b0 + r) * FP2 + (t & 511)];
    }
    for (int t = tid; t < HB * HID; t += 256) {
        int r = t / HID, c = t - r * HID;
        gats[r][c] = g_gat[(size_t)(b0 + r) * HID + c];
    }
    __syncthreads();

    for (int c = tid; c < HID; c += 256) {
        float a[HB] = {};
        #pragma unroll 4
        for (int k = 0; k < 512; k++) {
            float w = fc2_w[(size_t)k * HID + c];
            #pragma unroll
            for (int r = 0; r < HB; r++) a[r] = fmaf(t1s[r][k], w, a[r]);
        }
        float bb = fc2_b[c];
        #pragma unroll
        for (int r = 0; r < HB; r++) fpns[r][c] = a[r] + bb;
    }
    __syncthreads();

    for (int c = tid; c < HID; c += 256) {
        float a[HB] = {}, e[HB] = {};
        #pragma unroll 4
        for (int k = 0; k < HID; k++) {
            float wg = Wg[(size_t)k * HID + c];
            float wf = Wf[(size_t)k * HID + c];
            #pragma unroll
            for (int r = 0; r < HB; r++) {
                a[r] = fmaf(gats[r][k], wg, a[r]);
                e[r] = fmaf(fpns[r][k], wf, e[r]);
            }
        }
        float bbg = bg[c], bbf = bf[c];
        #pragma unroll
        for (int r = 0; r < HB; r++) {
            us[r][c] = fmaxf(a[r] + bbg, 0.f);
            vs[r][c] = fmaxf(e[r] + bbf, 0.f);
        }
    }
    __syncthreads();

    for (int c = tid; c < HID; c += 256) {
        float a[HB] = {};
        #pragma unroll 4
        for (int k = 0; k < HID; k++) {
            float w = W1[(size_t)k * HID + c];
            #pragma unroll
            for (int r = 0; r < HB; r++) a[r] = fmaf(us[r][k], w, a[r]);
        }
        #pragma unroll 4
        for (int k = 0; k < HID; k++) {
            float w = W1[(size_t)(k + HID) * HID + c];
            #pragma unroll
            for (int r = 0; r < HB; r++) a[r] = fmaf(vs[r][k], w, a[r]);
        }
        float bb = b1[c];
        #pragma unroll
        for (int r = 0; r < HB; r++) ys[r][c] = fmaxf(a[r] + bb, 0.f);
    }
    __syncthreads();

    const int warp = tid >> 5, lane = tid & 31;
    if (warp < HB) {
        float s = 0.f;
        for (int k = lane; k < HID; k += 32) s = fmaf(ys[warp][k], w2[k], s);
        s = warp_sum(s);
        if (lane == 0) out[b0 + warp] = 1.f / (1.f + expf(-(s + b2[0])));
    }
}

// ---------------- launch ----------------
extern "C" void kernel_launch(void* const* d_in, const int* in_sizes, int n_in,
                              void* d_out, int out_size)
{
    const float* atom_feats = (const float*)d_in[0];
    const float* fp         = (const float*)d_in[1];
    const float* W_heads    = (const float*)d_in[2];
    const float* a_heads    = (const float*)d_in[3];
    const float* W_out      = (const float*)d_in[4];
    const float* a_out      = (const float*)d_in[5];
    const float* fc1_w      = (const float*)d_in[6];
    const float* fc1_b      = (const float*)d_in[7];
    const float* fc2_w      = (const float*)d_in[8];
    const float* fc2_b      = (const float*)d_in[9];
    const float* fc_gat_w   = (const float*)d_in[10];
    const float* fc_gat_b   = (const float*)d_in[11];
    const float* fc_fpn_w   = (const float*)d_in[12];
    const float* fc_fpn_b   = (const float*)d_in[13];
    const float* ffn_w1     = (const float*)d_in[14];
    const float* ffn_b1     = (const float*)d_in[15];
    const float* ffn_w2     = (const float*)d_in[16];
    const float* ffn_b2     = (const float*)d_in[17];
    const int*   adj        = (const int*)  d_in[18];
    float* out = (float*)d_out;

    __nv_bfloat16 *pApk, *pBpk1, *pHpk, *pBpk3, *pFpk, *pW1k;
    float *pWh, *pWh2, *pPart;
    cudaGetSymbolAddress((void**)&pApk,  g_Apk);
    cudaGetSymbolAddress((void**)&pBpk1, g_Bpk1);
    cudaGetSymbolAddress((void**)&pWh,   g_Wh);
    cudaGetSymbolAddress((void**)&pHpk,  g_hpk);
    cudaGetSymbolAddress((void**)&pBpk3, g_Bpk3);
    cudaGetSymbolAddress((void**)&pWh2,  g_Wh2);
    cudaGetSymbolAddress((void**)&pFpk,  g_fpk);
    cudaGetSymbolAddress((void**)&pW1k,  g_w1k);
    cudaGetSymbolAddress((void**)&pPart, g_part);

    cudaFuncSetAttribute(gat1_mma, cudaFuncAttributeMaxDynamicSharedMemorySize, ATT_SMEM);
    cudaFuncSetAttribute(av2_mma,  cudaFuncAttributeMaxDynamicSharedMemorySize, ATT_SMEM);

    // 1,2: packing for K1
    pack_atoms<<<(Bsz * Nn * K1P + 255) / 256, 256>>>(atom_feats);
    pack_B1<<<(HD * K1P + 255) / 256, 256>>>(W_heads);
    // 3: K1 on HMMA
    mma_gemm<<<dim3(HD / 128, (Bsz * Nn) / 128, 1), 256>>>(
        pApk, pBpk1, pWh, K1T, K1T, K1T, HD, HD, 0, 0, 0);
    // 4: gat1 fused HMMA attention   <-- ncu capture target
    gat1_mma<<<Bsz * Hh, 256, ATT_SMEM>>>(a_heads, adj);
    // 5,6: fc1 packing
    pack_fp<<<(Bsz * KF + 255) / 256, 256>>>(fp);
    pack_w1k<<<(FP2 * KF + 255) / 256, 256>>>(fc1_w);
    // 7,8: fc1 on HMMA split-K + reduce
    mma_gemm<<<dim3(FP2 / 128, Bsz / 128, FS1), 256>>>(
        pFpk, pW1k, pPart, KC1, KFT, KFT, FP2, FP2,
        (long long)KC1, (long long)KC1, (long long)Bsz * FP2);
    fc1_reduce<<<(Bsz * FP2 + 255) / 256, 256>>>(fc1_b);
    // 9: K3 packing (B side)
    pack_B3<<<(N3P * HD + 255) / 256, 256>>>(W_out);
    // 10: K3 on HMMA
    mma_gemm<<<dim3(N3P / 128, (Bsz * Nn) / 128, 1), 256>>>(
        pHpk, pBpk3, pWh2, K3T, K3T, K3T, HID, HID, 0, 0, 0);
    // 11: gat2 scores
    score2_kernel<<<Bsz, 256>>>(a_out);
    // 12: gat2 fused HMMA attention
    av2_mma<<<dim3(5, 1, Bsz), 256, ATT_SMEM>>>(adj);
    // 13: gat2 log_softmax + mean
    ls2_kernel<<<Bsz, 256>>>();
    // 14: fused head
    head_fused<<<Bsz / HB, 256>>>(
        fc2_w, fc2_b, fc_gat_w, fc_gat_b, fc_fpn_w, fc_fpn_b,
        ffn_w1, ffn_b1, ffn_w2, ffn_b2, out);
}

// round 13
// speedup vs baseline: 1.2853x; 1.2853x over previous
#include <cuda_runtime.h>
#include <cuda_bf16.h>
#include <math.h>

// Problem constants
#define Bsz 256
#define Nn  128
#define Ff  133
#define Hh  8
#define NHID 64
#define HID 300
#define FP_DIM 1489
#define FP2 512
#define HD (Hh*NHID)     // 512
#define ALPHA 0.2f

#define K1P   160        // Ff padded so 3*K1P % 32 == 0
#define K1T   (3*K1P)    // 480
#define K3T   (3*HD)     // 1536
#define N3P   384        // HID padded to 3 tiles of 128
#define KF    1536       // FP_DIM padded
#define KFT   (3*KF)     // 4608
#define FS1   12         // fc1 split-K (96 blocks)
#define KC1   (KFT/FS1)  // 384

// ---------------- scratch (device globals) ----------------------------------------
__device__ __nv_bfloat16 g_Apk [(size_t)Bsz*Nn * K1T];
__device__ __nv_bfloat16 g_Bpk1[(size_t)HD * K1T];
__device__ float         g_Wh  [(size_t)Bsz*Nn * HD];
__device__ __nv_bfloat16 g_hpk [(size_t)Bsz*Nn * K3T];
__device__ __nv_bfloat16 g_Bpk3[(size_t)N3P * K3T];
__device__ float g_Wh2 [(size_t)Bsz*Nn * HID];
__device__ float g_ss2 [Bsz * Nn];
__device__ float g_dd2 [Bsz * Nn];
__device__ float g_O   [(size_t)Bsz*Nn * HID];
__device__ float g_gat [Bsz * HID];
__device__ __nv_bfloat16 g_fpk [(size_t)Bsz * KFT];
__device__ __nv_bfloat16 g_w1k [(size_t)FP2 * KFT];
__device__ float g_part[(size_t)FS1 * Bsz * FP2];
__device__ float g_t1  [Bsz * FP2];

// ---------------- helpers ----------------
#define FMA2(acc, a, b) \
    asm("fma.rn.f32x2 %0, %1, %2, %0;" : "+l"(acc) : "l"(a), "l"(b))

__device__ __forceinline__ unsigned long long ld2(const float* p) {
    return *reinterpret_cast<const unsigned long long*>(p);
}
__device__ __forceinline__ unsigned long long dup2(float x) {
    unsigned long long r;
    asm("mov.b64 %0, {%1, %1};" : "=l"(r) : "r"(__float_as_uint(x)));
    return r;
}
__device__ __forceinline__ float lo32(unsigned long long v) {
    return __uint_as_float((unsigned)v);
}
__device__ __forceinline__ float hi32(unsigned long long v) {
    return __uint_as_float((unsigned)(v >> 32));
}
__device__ __forceinline__ float warp_sum(float v) {
    #pragma unroll
    for (int o = 16; o; o >>= 1) v += __shfl_down_sync(0xffffffffu, v, o);
    return v;
}
__device__ __forceinline__ float warp_max(float v) {
    #pragma unroll
    for (int o = 16; o; o >>= 1) v = fmaxf(v, __shfl_down_sync(0xffffffffu, v, o));
    return v;
}
__device__ __forceinline__ unsigned smem_u32(const void* p) {
    unsigned a;
    asm("{ .reg .u64 t; cvta.to.shared.u64 t, %1; cvt.u32.u64 %0, t; }" : "=r"(a) : "l"(p));
    return a;
}
__device__ __forceinline__ void ldsm4(const __nv_bfloat16* p,
                                      unsigned& r0, unsigned& r1, unsigned& r2, unsigned& r3) {
    unsigned a = smem_u32(p);
    asm volatile("ldmatrix.sync.aligned.m8n8.x4.shared.b16 {%0,%1,%2,%3}, [%4];"
                 : "=r"(r0), "=r"(r1), "=r"(r2), "=r"(r3) : "r"(a));
}
#define MMA16816(acc, a0, a1, a2, a3, b0, b1) \
    asm volatile("mma.sync.aligned.m16n8k16.row.col.f32.bf16.bf16.f32 " \
                 "{%0,%1,%2,%3}, {%4,%5,%6,%7}, {%8,%9}, {%0,%1,%2,%3};" \
                 : "+f"((acc)[0]), "+f"((acc)[1]), "+f"((acc)[2]), "+f"((acc)[3]) \
                 : "r"(a0), "r"(a1), "r"(a2), "r"(a3), "r"(b0), "r"(b1))

// ================= mma_gemm: bf16 HMMA GEMM, 128x128 tile, KC=32, ldmatrix ======
#define MSTR 40
__global__ __launch_bounds__(256) void mma_gemm(
    const __nv_bfloat16* __restrict__ A, const __nv_bfloat16* __restrict__ B,
    float* __restrict__ C, int Ktot, int lda, int ldb, int Nreal, int ldc,
    long long bA, long long bB, long long bC)
{
    __shared__ __align__(16) __nv_bfloat16 As[2][128][MSTR];
    __shared__ __align__(16) __nv_bfloat16 Bs[2][128][MSTR];

    A += (long long)blockIdx.z * bA;
    B += (long long)blockIdx.z * bB;
    C += (long long)blockIdx.z * bC;

    const int tid = threadIdx.x;
    const int wid = tid >> 5, lane = tid & 31;
    const int wy = wid & 3, wx = wid >> 2;
    const int lq = lane & 7, lg8 = (lane >> 3) & 1, lg16 = lane >> 4;
    const int fgid = lane >> 2, ftig = lane & 3;
    const int row0 = blockIdx.y * 128, col0 = blockIdx.x * 128;

    const int lr0 = tid >> 2;
    const int lcq = (tid & 3) << 3;

    uint4 va0, va1, vb0, vb1;
    auto load_g = [&](int k0) {
        va0 = *reinterpret_cast<const uint4*>(A + (size_t)(row0 + lr0) * lda + k0 + lcq);
        va1 = *reinterpret_cast<const uint4*>(A + (size_t)(row0 + lr0 + 64) * lda + k0 + lcq);
        vb0 = *reinterpret_cast<const uint4*>(B + (size_t)(col0 + lr0) * ldb + k0 + lcq);
        vb1 = *reinterpret_cast<const uint4*>(B + (size_t)(col0 + lr0 + 64) * ldb + k0 + lcq);
    };
    auto store_s = [&](int buf) {
        *reinterpret_cast<uint4*>(&As[buf][lr0][lcq])      = va0;
        *reinterpret_cast<uint4*>(&As[buf][lr0 + 64][lcq]) = va1;
        *reinterpret_cast<uint4*>(&Bs[buf][lr0][lcq])      = vb0;
        *reinterpret_cast<uint4*>(&Bs[buf][lr0 + 64][lcq]) = vb1;
    };

    float acc[2][8][4];
    #pragma unroll
    for (int mt = 0; mt < 2; mt++)
        #pragma unroll
        for (int nt = 0; nt < 8; nt++)
            #pragma unroll
            for (int q = 0; q < 4; q++) acc[mt][nt][q] = 0.f;

    const int nsteps = Ktot >> 5;
    load_g(0);
    store_s(0);
    __syncthreads();

    for (int s = 0; s < nsteps; s++) {
        const int cur = s & 1;
        if (s + 1 < nsteps) load_g((s + 1) << 5);

        #pragma unroll
        for (int kk = 0; kk < 32; kk += 16) {
            unsigned af[2][4], bfr[8][2];
            #pragma unroll
            for (int mt = 0; mt < 2; mt++) {
                const int r = wy * 32 + mt * 16 + lq + 8 * lg8;
                ldsm4(&As[cur][r][kk + 8 * lg16],
                      af[mt][0], af[mt][1], af[mt][2], af[mt][3]);
            }
            #pragma unroll
            for (int p = 0; p < 4; p++) {
                const int r = wx * 64 + p * 16 + lq + 8 * lg8;
                unsigned r0, r1, r2, r3;
                ldsm4(&Bs[cur][r][kk + 8 * lg16], r0, r1, r2, r3);
                bfr[2 * p][0] = r0; bfr[2 * p + 1][0] = r1;
                bfr[2 * p][1] = r2; bfr[2 * p + 1][1] = r3;
            }
            #pragma unroll
            for (int mt = 0; mt < 2; mt++)
                #pragma unroll
                for (int nt = 0; nt < 8; nt++)
                    MMA16816(acc[mt][nt], af[mt][0], af[mt][1], af[mt][2], af[mt][3],
                             bfr[nt][0], bfr[nt][1]);
        }

        if (s + 1 < nsteps) store_s(cur ^ 1);
        __syncthreads();
    }

    #pragma unroll
    for (int mt = 0; mt < 2; mt++) {
        const int r0 = row0 + wy * 32 + mt * 16 + fgid;
        #pragma unroll
        for (int nt = 0; nt < 8; nt++) {
            const int c = col0 + wx * 64 + nt * 8 + 2 * ftig;
            if (c < Nreal) {
                *reinterpret_cast<float2*>(C + (size_t)r0 * ldc + c) =
                    make_float2(acc[mt][nt][0], acc[mt][nt][1]);
                *reinterpret_cast<float2*>(C + (size_t)(r0 + 8) * ldc + c) =
                    make_float2(acc[mt][nt][2], acc[mt][nt][3]);
            }
        }
    }
}

// ---------------- packing kernels ------------------------------------------------
__global__ void pack_atoms(const float* __restrict__ src) {
    int t = blockIdx.x * blockDim.x + threadIdx.x;
    if (t >= Bsz * Nn * K1P) return;
    int k = t % K1P, r = t / K1P;
    float x = (k < Ff) ? src[(size_t)r * Ff + k] : 0.f;
    __nv_bfloat16 hi = __float2bfloat16(x);
    __nv_bfloat16 lo = __float2bfloat16(x - __bfloat162float(hi));
    __nv_bfloat16* row = g_Apk + (size_t)r * K1T;
    row[k] = hi; row[K1P + k] = hi; row[2 * K1P + k] = lo;
}
__global__ void pack_B1(const float* __restrict__ W_heads) {
    int t = blockIdx.x * blockDim.x + threadIdx.x;
    if (t >= HD * K1P) return;
    int k = t % K1P, n = t / K1P;
    int h = n >> 6, d = n & 63;
    float x = (k < Ff) ? W_heads[((size_t)h * Ff + k) * NHID + d] : 0.f;
    __nv_bfloat16 hi = __float2bfloat16(x);
    __nv_bfloat16 lo = __float2bfloat16(x - __bfloat162float(hi));
    __nv_bfloat16* row = g_Bpk1 + (size_t)n * K1T;
    row[k] = hi; row[K1P + k] = lo; row[2 * K1P + k] = hi;
}
__global__ void pack_B3(const float* __restrict__ W_out) {
    int t = blockIdx.x * blockDim.x + threadIdx.x;
    if (t >= N3P * HD) return;
    int k = t % HD, n = t / HD;
    float x = (n < HID) ? W_out[(size_t)k * HID + n] : 0.f;
    __nv_bfloat16 hi = __float2bfloat16(x);
    __nv_bfloat16 lo = __float2bfloat16(x - __bfloat162float(hi));
    __nv_bfloat16* row = g_Bpk3 + (size_t)n * K3T;
    row[k] = hi; row[HD + k] = lo; row[2 * HD + k] = hi;
}
__global__ void pack_fp(const float* __restrict__ fp) {
    int t = blockIdx.x * blockDim.x + threadIdx.x;
    if (t >= Bsz * KF) return;
    int k = t % KF, r = t / KF;
    float x = (k < FP_DIM) ? fp[(size_t)r * FP_DIM + k] : 0.f;
    __nv_bfloat16 hi = __float2bfloat16(x);
    __nv_bfloat16 lo = __float2bfloat16(x - __bfloat162float(hi));
    __nv_bfloat16* row = g_fpk + (size_t)r * KFT;
    row[k] = hi; row[KF + k] = hi; row[2 * KF + k] = lo;
}
__global__ void pack_w1k(const float* __restrict__ w) {
    int t = blockIdx.x * blockDim.x + threadIdx.x;
    if (t >= FP2 * KF) return;
    int k = t % KF, n = t / KF;
    float x = (k < FP_DIM) ? w[(size_t)k * FP2 + n] : 0.f;
    __nv_bfloat16 hi = __float2bfloat16(x);
    __nv_bfloat16 lo = __float2bfloat16(x - __bfloat162float(hi));
    __nv_bfloat16* row = g_w1k + (size_t)n * KFT;
    row[k] = hi; row[KF + k] = lo; row[2 * KF + k] = hi;
}

// ---------------- fc1 reduce ------------------------------------------------------
__global__ void fc1_reduce(const float* __restrict__ fc1_b) {
    int t = blockIdx.x * blockDim.x + threadIdx.x;
    if (t >= Bsz * FP2) return;
    float s = 0.f;
    #pragma unroll
    for (int z = 0; z < FS1; z++) s += g_part[(size_t)z * Bsz * FP2 + t];
    g_t1[t] = fmaxf(s + fc1_b[t & (FP2 - 1)], 0.f);
}

// ============ gat1_fused: scores + on-the-fly probs + FMA2 AV + elu ==============
__global__ __launch_bounds__(256) void gat1_fused(const float* __restrict__ a_heads,
                                                  const int* __restrict__ adj)
{
    __shared__ __align__(16) float Ws[128 * 68];
    __shared__ __align__(16) float As[2][16][132];
    __shared__ float ss[128], dd[128], rsum[128];

    const int z = blockIdx.x;
    const int b = z >> 3, h = z & 7;
    const int tid = threadIdx.x, warp = tid >> 5, lane = tid & 31;
    const float* whbase = g_Wh + ((size_t)b * Nn) * HD + h * NHID;

    for (int s = tid; s < 2048; s += 256) {
        int j = s >> 4, q = (s & 15) << 2;
        float4 v = *reinterpret_cast<const float4*>(whbase + (size_t)j * HD + q);
        *reinterpret_cast<float4*>(&Ws[j * 68 + q]) = v;
    }
    if (tid < 128) rsum[tid] = 0.f;
    __syncthreads();

    const float* a1 = a_heads + h * (2 * NHID);
    const float* a2v = a1 + NHID;
    for (int j = warp; j < 128; j += 8) {
        const float w0 = Ws[j * 68 + lane];
        const float w1 = Ws[j * 68 + lane + 32];
        float s1 = fmaf(w0, a1[lane], w1 * a1[lane + 32]);
        float s2 = fmaf(w0, a2v[lane], w1 * a2v[lane + 32]);
        s1 = warp_sum(s1); s2 = warp_sum(s2);
        if (lane == 0) { ss[j] = s1; dd[j] = s2; }
    }
    __syncthreads();

    const int* adjb = adj + (size_t)b * Nn * Nn;
    const int am = tid >> 2;
    const int aq = (tid & 3) << 2;
    const float sm0 = ss[am], sm1 = ss[am + 64];
    float rs0 = 0.f, rs1 = 0.f;
    int mm0[4], mm1[4];

    auto loadM = [&](int k0) {
        *reinterpret_cast<int4*>(mm0) = *reinterpret_cast<const int4*>(adjb + am * Nn + k0 + aq);
        *reinterpret_cast<int4*>(mm1) = *reinterpret_cast<const int4*>(adjb + (am + 64) * Nn + k0 + aq);
    };
    auto genStore = [&](int k0, int buf) {
        #pragma unroll
        for (int q = 0; q < 4; q++) {
            const float dv = dd[k0 + aq + q];
            float e0 = sm0 + dv; e0 = (e0 > 0.f) ? e0 : ALPHA * e0;
            float e1 = sm1 + dv; e1 = (e1 > 0.f) ? e1 : ALPHA * e1;
            float p0 = (mm0[q] > 0) ? __expf(e0) : 0.f;
            float p1 = (mm1[q] > 0) ? __expf(e1) : 0.f;
            rs0 += p0; rs1 += p1;
            As[buf][aq + q][am] = p0;
            As[buf][aq + q][am + 64] = p1;
        }
    };

    const int tx = tid & 15, ty = tid >> 4;
    unsigned long long acc[8][2];
    #pragma unroll
    for (int i = 0; i < 8; i++) { acc[i][0] = 0ull; acc[i][1] = 0ull; }

    loadM(0);
    genStore(0, 0);
    __syncthreads();

    for (int s = 0; s < 8; s++) {
        const int cur = s & 1;
        if (s < 7) loadM((s + 1) << 4);
        #pragma unroll
        for (int k = 0; k < 16; k++) {
            unsigned long long aL[8], b2[2];
            #pragma unroll
            for (int ii = 0; ii < 4; ii++) {
                const unsigned long long pr = ld2(&As[cur][k][2 * ty + 32 * ii]);
                aL[2 * ii]     = dup2(lo32(pr));
                aL[2 * ii + 1] = dup2(hi32(pr));
            }
            b2[0] = ld2(&Ws[(s * 16 + k) * 68 + 2 * tx]);
            b2[1] = ld2(&Ws[(s * 16 + k) * 68 + 2 * tx + 32]);
            #pragma unroll
            for (int i = 0; i < 8; i++) {
                FMA2(acc[i][0], aL[i], b2[0]);
                FMA2(acc[i][1], aL[i], b2[1]);
            }
        }
        if (s < 7) genStore((s + 1) << 4, cur ^ 1);
        __syncthreads();
    }

    atomicAdd(&rsum[am], rs0);
    atomicAdd(&rsum[am + 64], rs1);
    __syncthreads();

    #pragma unroll
    for (int i = 0; i < 8; i++) {
        const int r = 2 * ty + 32 * (i >> 1) + (i & 1);
        const float inv = 1.f / rsum[r];
        __nv_bfloat16* rowp = g_hpk + (size_t)(b * Nn + r) * K3T + h * NHID;
        #pragma unroll
        for (int jj = 0; jj < 2; jj++) {
            const int c = 2 * (tx + 16 * jj);
            float v0 = lo32(acc[i][jj]) * inv;
            float v1 = hi32(acc[i][jj]) * inv;
            v0 = (v0 > 0.f) ? v0 : expm1f(v0);
            v1 = (v1 > 0.f) ? v1 : expm1f(v1);
            __nv_bfloat16 h0 = __float2bfloat16(v0);
            __nv_bfloat16 h1 = __float2bfloat16(v1);
            __nv_bfloat16 l0 = __float2bfloat16(v0 - __bfloat162float(h0));
            __nv_bfloat16 l1 = __float2bfloat16(v1 - __bfloat162float(h1));
            unsigned hp = (unsigned)__bfloat16_as_ushort(h0) | ((unsigned)__bfloat16_as_ushort(h1) << 16);
            unsigned lp = (unsigned)__bfloat16_as_ushort(l0) | ((unsigned)__bfloat16_as_ushort(l1) << 16);
            *reinterpret_cast<unsigned*>(rowp + c)           = hp;
            *reinterpret_cast<unsigned*>(rowp + HD + c)      = hp;
            *reinterpret_cast<unsigned*>(rowp + 2 * HD + c)  = lp;
        }
    }
}

// ---------------- score2 ----------------------------------------------------------
__global__ __launch_bounds__(256) void score2_kernel(const float* __restrict__ a_out)
{
    const int b = blockIdx.x;
    const int tid = threadIdx.x, warp = tid >> 5, lane = tid & 31;
    const float* W = g_Wh2 + (size_t)b * Nn * HID;
    for (int j = warp; j < 128; j += 8) {
        float s1 = 0.f, s2 = 0.f;
        #pragma unroll
        for (int t = 0; t < 10; t++) {
            int d = lane + 32 * t;
            if (d < HID) {
                float w = W[(size_t)j * HID + d];
                s1 = fmaf(w, a_out[d], s1);
                s2 = fmaf(w, a_out[HID + d], s2);
            }
        }
        s1 = warp_sum(s1); s2 = warp_sum(s2);
        if (lane == 0) { g_ss2[b * Nn + j] = s1; g_dd2[b * Nn + j] = s2; }
    }
}

// ============ av2f: gat2 on-the-fly probs + FMA2 AV + elu ========================
__global__ __launch_bounds__(256) void av2f(const int* __restrict__ adj)
{
    __shared__ __align__(16) float As[2][16][132];
    __shared__ __align__(16) float Bs[2][16][132];
    __shared__ float ss[128], dd[128], rsum[128];

    const int b = blockIdx.z;
    const int col0 = blockIdx.x * 128;
    const int tid = threadIdx.x;
    const int tx = tid & 15, ty = tid >> 4;
    const int am = tid >> 2, aq = (tid & 3) << 2;
    const int bk = tid >> 4, bn4 = (tid & 15) << 2;

    if (tid < 128) {
        ss[tid] = g_ss2[b * Nn + tid];
        dd[tid] = g_dd2[b * Nn + tid];
        rsum[tid] = 0.f;
    }
    __syncthreads();

    const float* Bp = g_Wh2 + (size_t)b * Nn * HID;
    const int* adjb = adj + (size_t)b * Nn * Nn;
    const float sm0 = ss[am], sm1 = ss[am + 64];
    float rs0 = 0.f, rs1 = 0.f;
    int mm0[4], mm1[4];
    float4 rb[2];

    auto loadM = [&](int k0) {
        *reinterpret_cast<int4*>(mm0) = *reinterpret_cast<const int4*>(adjb + am * Nn + k0 + aq);
        *reinterpret_cast<int4*>(mm1) = *reinterpret_cast<const int4*>(adjb + (am + 64) * Nn + k0 + aq);
    };
    auto loadB = [&](int k0) {
        #pragma unroll
        for (int jj2 = 0; jj2 < 2; jj2++) {
            const int gc = col0 + bn4 + 64 * jj2;
            if (gc + 4 <= HID) {
                rb[jj2] = *reinterpret_cast<const float4*>(Bp + (size_t)(k0 + bk) * HID + gc);
            } else {
                rb[jj2].x = (gc + 0 < HID) ? Bp[(size_t)(k0 + bk) * HID + gc + 0] : 0.f;
                rb[jj2].y = (gc + 1 < HID) ? Bp[(size_t)(k0 + bk) * HID + gc + 1] : 0.f;
                rb[jj2].z = (gc + 2 < HID) ? Bp[(size_t)(k0 + bk) * HID + gc + 2] : 0.f;
                rb[jj2].w = (gc + 3 < HID) ? Bp[(size_t)(k0 + bk) * HID + gc + 3] : 0.f;
            }
        }
    };
    auto genStore = [&](int k0, int buf) {
        #pragma unroll
        for (int q = 0; q < 4; q++) {
            const float dv = dd[k0 + aq + q];
            float e0 = sm0 + dv; e0 = (e0 > 0.f) ? e0 : ALPHA * e0;
            float e1 = sm1 + dv; e1 = (e1 > 0.f) ? e1 : ALPHA * e1;
            float p0 = (mm0[q] > 0) ? __expf(e0) : 0.f;
            float p1 = (mm1[q] > 0) ? __expf(e1) : 0.f;
            rs0 += p0; rs1 += p1;
            As[buf][aq + q][am] = p0;
            As[buf][aq + q][am + 64] = p1;
        }
    };
    auto storeB = [&](int buf) {
        #pragma unroll
        for (int jj2 = 0; jj2 < 2; jj2++)
            *reinterpret_cast<float4*>(&Bs[buf][bk][bn4 + 64 * jj2]) = rb[jj2];
    };

    unsigned long long acc[8][4];
    #pragma unroll
    for (int i = 0; i < 8; i++)
        #pragma unroll
        for (int j = 0; j < 4; j++) acc[i][j] = 0ull;

    loadM(0); loadB(0);
    genStore(0, 0); storeB(0);
    __syncthreads();

    for (int s = 0; s < 8; s++) {
        const int cur = s & 1;
        if (s < 7) { loadM((s + 1) << 4); loadB((s + 1) << 4); }
        #pragma unroll
        for (int k = 0; k < 16; k++) {
            unsigned long long aL[8], b2[4];
            #pragma unroll
            for (int ii = 0; ii < 4; ii++) {
                const unsigned long long pr = ld2(&As[cur][k][2 * ty + 32 * ii]);
                aL[2 * ii]     = dup2(lo32(pr));
                aL[2 * ii + 1] = dup2(hi32(pr));
            }
            #pragma unroll
            for (int jj = 0; jj < 4; jj++) b2[jj] = ld2(&Bs[cur][k][2 * (tx + 16 * jj)]);
            #pragma unroll
            for (int i = 0; i < 8; i++)
                #pragma unroll
                for (int jj = 0; jj < 4; jj++)
                    FMA2(acc[i][jj], aL[i], b2[jj]);
        }
        if (s < 7) { genStore((s + 1) << 4, cur ^ 1); storeB(cur ^ 1); }
        __syncthreads();
    }

    atomicAdd(&rsum[am], rs0);
    atomicAdd(&rsum[am + 64], rs1);
    __syncthreads();

    float* Cb = g_O + (size_t)b * Nn * HID;
    #pragma unroll
    for (int i = 0; i < 8; i++) {
        const int r = 2 * ty + 32 * (i >> 1) + (i & 1);
        const float inv = 1.f / rsum[r];
        #pragma unroll
        for (int jj = 0; jj < 4; jj++) {
            const int c = col0 + 2 * (tx + 16 * jj);
            if (c < HID) {
                float v0 = lo32(acc[i][jj]) * inv;
                float v1 = hi32(acc[i][jj]) * inv;
                v0 = (v0 > 0.f) ? v0 : expm1f(v0);
                v1 = (v1 > 0.f) ? v1 : expm1f(v1);
                *reinterpret_cast<float2*>(Cb + (size_t)r * HID + c) = make_float2(v0, v1);
            }
        }
    }
}

// ---------------- ls2 -------------------------------------------------------------
__global__ __launch_bounds__(256) void ls2_kernel()
{
    __shared__ float acc[8 * HID];
    const int b = blockIdx.x;
    const int tid = threadIdx.x, warp = tid >> 5, lane = tid & 31;
    for (int t = tid; t < 8 * HID; t += 256) acc[t] = 0.f;
    __syncthreads();

    const float* O = g_O + (size_t)b * Nn * HID;
    float* accw = acc + warp * HID;
    for (int i = warp; i < 128; i += 8) {
        float o[10];
        #pragma unroll
        for (int t = 0; t < 10; t++) {
            int d = lane + 32 * t;
            o[t] = (d < HID) ? O[(size_t)i * HID + d] : -1e30f;
        }
        float m = o[0];
        #pragma unroll
        for (int t = 1; t < 10; t++) m = fmaxf(m, o[t]);
        m = warp_max(m);
        m = __shfl_sync(0xffffffffu, m, 0);
        float se = 0.f;
        #pragma unroll
        for (int t = 0; t < 10; t++) se += __expf(o[t] - m);
        se = warp_sum(se);
        se = __shfl_sync(0xffffffffu, se, 0);
        const float lse = m + logf(se);
        #pragma unroll
        for (int t = 0; t < 10; t++) {
            int d = lane + 32 * t;
            if (d < HID) accw[d] += o[t] - lse;
        }
    }
    __syncthreads();
    for (int d = tid; d < HID; d += 256) {
        float s = 0.f;
        #pragma unroll
        for (int w = 0; w < 8; w++) s += acc[w * HID + d];
        g_gat[b * HID + d] = s * (1.f / 128.f);
    }
}

// ---------------- head ------------------------------------------------------------
#define HB 4
__global__ __launch_bounds__(256) void head_fused(
    const float* __restrict__ fc2_w, const float* __restrict__ fc2_b,
    const float* __restrict__ Wg,    const float* __restrict__ bg,
    const float* __restrict__ Wf,    const float* __restrict__ bf,
    const float* __restrict__ W1,    const float* __restrict__ b1,
    const float* __restrict__ w2,    const float* __restrict__ b2,
    float* __restrict__ out)
{
    __shared__ float t1s [HB][512];
    __shared__ float gats[HB][HID];
    __shared__ float fpns[HB][HID];
    __shared__ float us  [HB][HID];
    __shared__ float vs  [HB][HID];
    __shared__ float ys  [HB][HID];

    const int b0 = blockIdx.x * HB;
    const int tid = threadIdx.x;

    for (int t = tid; t < HB * 512; t += 256) {
        int r = t >> 9;
        t1s[r][t & 511] = g_t1[(size_t)(b0 + r) * FP2 + (t & 511)];
    }
    for (int t = tid; t < HB * HID; t += 256) {
        int r = t / HID, c = t - r * HID;
        gats[r][c] = g_gat[(size_t)(b0 + r) * HID + c];
    }
    __syncthreads();

    for (int c = tid; c < HID; c += 256) {
        float a[HB] = {};
        #pragma unroll 4
        for (int k = 0; k < 512; k++) {
            float w = fc2_w[(size_t)k * HID + c];
            #pragma unroll
            for (int r = 0; r < HB; r++) a[r] = fmaf(t1s[r][k], w, a[r]);
        }
        float bb = fc2_b[c];
        #pragma unroll
        for (int r = 0; r < HB; r++) fpns[r][c] = a[r] + bb;
    }
    __syncthreads();

    for (int c = tid; c < HID; c += 256) {
        float a[HB] = {}, e[HB] = {};
        #pragma unroll 4
        for (int k = 0; k < HID; k++) {
            float wg = Wg[(size_t)k * HID + c];
            float wf = Wf[(size_t)k * HID + c];
            #pragma unroll
            for (int r = 0; r < HB; r++) {
                a[r] = fmaf(gats[r][k], wg, a[r]);
                e[r] = fmaf(fpns[r][k], wf, e[r]);
            }
        }
        float bbg = bg[c], bbf = bf[c];
        #pragma unroll
        for (int r = 0; r < HB; r++) {
            us[r][c] = fmaxf(a[r] + bbg, 0.f);
            vs[r][c] = fmaxf(e[r] + bbf, 0.f);
        }
    }
    __syncthreads();

    for (int c = tid; c < HID; c += 256) {
        float a[HB] = {};
        #pragma unroll 4
        for (int k = 0; k < HID; k++) {
            float w = W1[(size_t)k * HID + c];
            #pragma unroll
            for (int r = 0; r < HB; r++) a[r] = fmaf(us[r][k], w, a[r]);
        }
        #pragma unroll 4
        for (int k = 0; k < HID; k++) {
            float w = W1[(size_t)(k + HID) * HID + c];
            #pragma unroll
            for (int r = 0; r < HB; r++) a[r] = fmaf(vs[r][k], w, a[r]);
        }
        float bb = b1[c];
        #pragma unroll
        for (int r = 0; r < HB; r++) ys[r][c] = fmaxf(a[r] + bb, 0.f);
    }
    __syncthreads();

    const int warp = tid >> 5, lane = tid & 31;
    if (warp < HB) {
        float s = 0.f;
        for (int k = lane; k < HID; k += 32) s = fmaf(ys[warp][k], w2[k], s);
        s = warp_sum(s);
        if (lane == 0) out[b0 + warp] = 1.f / (1.f + expf(-(s + b2[0])));
    }
}

// ---------------- launch ----------------
extern "C" void kernel_launch(void* const* d_in, const int* in_sizes, int n_in,
                              void* d_out, int out_size)
{
    const float* atom_feats = (const float*)d_in[0];
    const float* fp         = (const float*)d_in[1];
    const float* W_heads    = (const float*)d_in[2];
    const float* a_heads    = (const float*)d_in[3];
    const float* W_out      = (const float*)d_in[4];
    const float* a_out      = (const float*)d_in[5];
    const float* fc1_w      = (const float*)d_in[6];
    const float* fc1_b      = (const float*)d_in[7];
    const float* fc2_w      = (const float*)d_in[8];
    const float* fc2_b      = (const float*)d_in[9];
    const float* fc_gat_w   = (const float*)d_in[10];
    const float* fc_gat_b   = (const float*)d_in[11];
    const float* fc_fpn_w   = (const float*)d_in[12];
    const float* fc_fpn_b   = (const float*)d_in[13];
    const float* ffn_w1     = (const float*)d_in[14];
    const float* ffn_b1     = (const float*)d_in[15];
    const float* ffn_w2     = (const float*)d_in[16];
    const float* ffn_b2     = (const float*)d_in[17];
    const int*   adj        = (const int*)  d_in[18];
    float* out = (float*)d_out;

    __nv_bfloat16 *pApk, *pBpk1, *pHpk, *pBpk3, *pFpk, *pW1k;
    float *pWh, *pWh2, *pPart;
    cudaGetSymbolAddress((void**)&pApk,  g_Apk);
    cudaGetSymbolAddress((void**)&pBpk1, g_Bpk1);
    cudaGetSymbolAddress((void**)&pWh,   g_Wh);
    cudaGetSymbolAddress((void**)&pHpk,  g_hpk);
    cudaGetSymbolAddress((void**)&pBpk3, g_Bpk3);
    cudaGetSymbolAddress((void**)&pWh2,  g_Wh2);
    cudaGetSymbolAddress((void**)&pFpk,  g_fpk);
    cudaGetSymbolAddress((void**)&pW1k,  g_w1k);
    cudaGetSymbolAddress((void**)&pPart, g_part);

    // 1-3: packing
    pack_atoms<<<(Bsz * Nn * K1P + 255) / 256, 256>>>(atom_feats);
    pack_B1<<<(HD * K1P + 255) / 256, 256>>>(W_heads);
    pack_fp<<<(Bsz * KF + 255) / 256, 256>>>(fp);
    // 4: K1 on HMMA (split bf16, ldmatrix)   <-- ncu capture target
    mma_gemm<<<dim3(HD / 128, (Bsz * Nn) / 128, 1), 256>>>(
        pApk, pBpk1, pWh, K1T, K1T, K1T, HD, HD, 0, 0, 0);
    // 5: gat1 fused (writes packed h)
    gat1_fused<<<Bsz * Hh, 256>>>(a_heads, adj);
    // 6,7: more packing
    pack_B3<<<(N3P * HD + 255) / 256, 256>>>(W_out);
    pack_w1k<<<(FP2 * KF + 255) / 256, 256>>>(fc1_w);
    // 8,9: fc1 on HMMA split-K (96 blocks) + reduce
    mma_gemm<<<dim3(FP2 / 128, Bsz / 128, FS1), 256>>>(
        pFpk, pW1k, pPart, KC1, KFT, KFT, FP2, FP2,
        (long long)KC1, (long long)KC1, (long long)Bsz * FP2);
    fc1_reduce<<<(Bsz * FP2 + 255) / 256, 256>>>(fc1_b);
    // 10: K3 on HMMA
    mma_gemm<<<dim3(N3P / 128, (Bsz * Nn) / 128, 1), 256>>>(
        pHpk, pBpk3, pWh2, K3T, K3T, K3T, HID, HID, 0, 0, 0);
    // 11: gat2 scores
    score2_kernel<<<Bsz, 256>>>(a_out);
    // 12: gat2 fused probs + AV + elu
    av2f<<<dim3(3, 1, Bsz), 256>>>(adj);
    // 13: gat2 log_softmax + mean
    ls2_kernel<<<Bsz, 256>>>();
    // 14: fused head
    head_fused<<<Bsz / HB, 256>>>(
        fc2_w, fc2_b, fc_gat_w, fc_gat_b, fc_fpn_w, fc_fpn_b,
        ffn_w1, ffn_b1, ffn_w2, ffn_b2, out);
}

// round 14
// speedup vs baseline: 1.3007x; 1.0121x over previous
#include <cuda_runtime.h>
#include <cuda_bf16.h>
#include <math.h>

// Problem constants
#define Bsz 256
#define Nn  128
#define Ff  133
#define Hh  8
#define NHID 64
#define HID 300
#define FP_DIM 1489
#define FP2 512
#define HD (Hh*NHID)     // 512
#define ALPHA 0.2f

#define K1P   160
#define K1T   (3*K1P)    // 480
#define K3T   (3*HD)     // 1536
#define N3P   384
#define KF    1536
#define KFT   (3*KF)     // 4608
#define FS1   12
#define KC1   (KFT/FS1)  // 384

// ---------------- scratch (device globals) ----------------------------------------
__device__ __nv_bfloat16 g_Apk [(size_t)Bsz*Nn * K1T];
__device__ __nv_bfloat16 g_Bpk1[(size_t)HD * K1T];
__device__ float         g_Wh  [(size_t)Bsz*Nn * HD];
__device__ __nv_bfloat16 g_hpk [(size_t)Bsz*Nn * K3T];
__device__ __nv_bfloat16 g_Bpk3[(size_t)N3P * K3T];
__device__ float g_Wh2 [(size_t)Bsz*Nn * HID];
__device__ float g_ss2 [Bsz * Nn];
__device__ float g_dd2 [Bsz * Nn];
__device__ float g_O   [(size_t)Bsz*Nn * HID];
__device__ float g_gat [Bsz * HID];
__device__ __nv_bfloat16 g_fpk [(size_t)Bsz * KFT];
__device__ __nv_bfloat16 g_w1k [(size_t)FP2 * KFT];
__device__ float g_part[(size_t)FS1 * Bsz * FP2];
__device__ float g_t1  [Bsz * FP2];

// ---------------- helpers ----------------
__device__ __forceinline__ float warp_sum(float v) {
    #pragma unroll
    for (int o = 16; o; o >>= 1) v += __shfl_down_sync(0xffffffffu, v, o);
    return v;
}
__device__ __forceinline__ float warp_max(float v) {
    #pragma unroll
    for (int o = 16; o; o >>= 1) v = fmaxf(v, __shfl_down_sync(0xffffffffu, v, o));
    return v;
}
__device__ __forceinline__ unsigned smem_u32(const void* p) {
    unsigned a;
    asm("{ .reg .u64 t; cvta.to.shared.u64 t, %1; cvt.u32.u64 %0, t; }" : "=r"(a) : "l"(p));
    return a;
}
__device__ __forceinline__ void ldsm4(const __nv_bfloat16* p,
                                      unsigned& r0, unsigned& r1, unsigned& r2, unsigned& r3) {
    unsigned a = smem_u32(p);
    asm volatile("ldmatrix.sync.aligned.m8n8.x4.shared.b16 {%0,%1,%2,%3}, [%4];"
                 : "=r"(r0), "=r"(r1), "=r"(r2), "=r"(r3) : "r"(a));
}
#define MMA16816(acc, a0, a1, a2, a3, b0, b1) \
    asm volatile("mma.sync.aligned.m16n8k16.row.col.f32.bf16.bf16.f32 " \
                 "{%0,%1,%2,%3}, {%4,%5,%6,%7}, {%8,%9}, {%0,%1,%2,%3};" \
                 : "+f"((acc)[0]), "+f"((acc)[1]), "+f"((acc)[2]), "+f"((acc)[3]) \
                 : "r"(a0), "r"(a1), "r"(a2), "r"(a3), "r"(b0), "r"(b1))
__device__ __forceinline__ unsigned bfus(__nv_bfloat16 x) {
    return (unsigned)__bfloat16_as_ushort(x);
}

// ================= mma_gemm: bf16 HMMA GEMM, 128x128 tile, KC=32, ldmatrix ======
#define MSTR 40
__global__ __launch_bounds__(256) void mma_gemm(
    const __nv_bfloat16* __restrict__ A, const __nv_bfloat16* __restrict__ B,
    float* __restrict__ C, int Ktot, int lda, int ldb, int Nreal, int ldc,
    long long bA, long long bB, long long bC)
{
    __shared__ __align__(16) __nv_bfloat16 As[2][128][MSTR];
    __shared__ __align__(16) __nv_bfloat16 Bs[2][128][MSTR];

    A += (long long)blockIdx.z * bA;
    B += (long long)blockIdx.z * bB;
    C += (long long)blockIdx.z * bC;

    const int tid = threadIdx.x;
    const int wid = tid >> 5, lane = tid & 31;
    const int wy = wid & 3, wx = wid >> 2;
    const int lq = lane & 7, lg8 = (lane >> 3) & 1, lg16 = lane >> 4;
    const int fgid = lane >> 2, ftig = lane & 3;
    const int row0 = blockIdx.y * 128, col0 = blockIdx.x * 128;

    const int lr0 = tid >> 2;
    const int lcq = (tid & 3) << 3;

    uint4 va0, va1, vb0, vb1;
    auto load_g = [&](int k0) {
        va0 = *reinterpret_cast<const uint4*>(A + (size_t)(row0 + lr0) * lda + k0 + lcq);
        va1 = *reinterpret_cast<const uint4*>(A + (size_t)(row0 + lr0 + 64) * lda + k0 + lcq);
        vb0 = *reinterpret_cast<const uint4*>(B + (size_t)(col0 + lr0) * ldb + k0 + lcq);
        vb1 = *reinterpret_cast<const uint4*>(B + (size_t)(col0 + lr0 + 64) * ldb + k0 + lcq);
    };
    auto store_s = [&](int buf) {
        *reinterpret_cast<uint4*>(&As[buf][lr0][lcq])      = va0;
        *reinterpret_cast<uint4*>(&As[buf][lr0 + 64][lcq]) = va1;
        *reinterpret_cast<uint4*>(&Bs[buf][lr0][lcq])      = vb0;
        *reinterpret_cast<uint4*>(&Bs[buf][lr0 + 64][lcq]) = vb1;
    };

    float acc[2][8][4];
    #pragma unroll
    for (int mt = 0; mt < 2; mt++)
        #pragma unroll
        for (int nt = 0; nt < 8; nt++)
            #pragma unroll
            for (int q = 0; q < 4; q++) acc[mt][nt][q] = 0.f;

    const int nsteps = Ktot >> 5;
    load_g(0);
    store_s(0);
    __syncthreads();

    for (int s = 0; s < nsteps; s++) {
        const int cur = s & 1;
        if (s + 1 < nsteps) load_g((s + 1) << 5);

        #pragma unroll
        for (int kk = 0; kk < 32; kk += 16) {
            unsigned af[2][4], bfr[8][2];
            #pragma unroll
            for (int mt = 0; mt < 2; mt++) {
                const int r = wy * 32 + mt * 16 + lq + 8 * lg8;
                ldsm4(&As[cur][r][kk + 8 * lg16],
                      af[mt][0], af[mt][1], af[mt][2], af[mt][3]);
            }
            #pragma unroll
            for (int p = 0; p < 4; p++) {
                const int r = wx * 64 + p * 16 + lq + 8 * lg8;
                unsigned r0, r1, r2, r3;
                ldsm4(&Bs[cur][r][kk + 8 * lg16], r0, r1, r2, r3);
                bfr[2 * p][0] = r0; bfr[2 * p + 1][0] = r1;
                bfr[2 * p][1] = r2; bfr[2 * p + 1][1] = r3;
            }
            #pragma unroll
            for (int mt = 0; mt < 2; mt++)
                #pragma unroll
                for (int nt = 0; nt < 8; nt++)
                    MMA16816(acc[mt][nt], af[mt][0], af[mt][1], af[mt][2], af[mt][3],
                             bfr[nt][0], bfr[nt][1]);
        }

        if (s + 1 < nsteps) store_s(cur ^ 1);
        __syncthreads();
    }

    #pragma unroll
    for (int mt = 0; mt < 2; mt++) {
        const int r0 = row0 + wy * 32 + mt * 16 + fgid;
        #pragma unroll
        for (int nt = 0; nt < 8; nt++) {
            const int c = col0 + wx * 64 + nt * 8 + 2 * ftig;
            if (c < Nreal) {
                *reinterpret_cast<float2*>(C + (size_t)r0 * ldc + c) =
                    make_float2(acc[mt][nt][0], acc[mt][nt][1]);
                *reinterpret_cast<float2*>(C + (size_t)(r0 + 8) * ldc + c) =
                    make_float2(acc[mt][nt][2], acc[mt][nt][3]);
            }
        }
    }
}

// ---------------- packing kernels ------------------------------------------------
__global__ void pack_atoms(const float* __restrict__ src) {
    int t = blockIdx.x * blockDim.x + threadIdx.x;
    if (t >= Bsz * Nn * K1P) return;
    int k = t % K1P, r = t / K1P;
    float x = (k < Ff) ? src[(size_t)r * Ff + k] : 0.f;
    __nv_bfloat16 hi = __float2bfloat16(x);
    __nv_bfloat16 lo = __float2bfloat16(x - __bfloat162float(hi));
    __nv_bfloat16* row = g_Apk + (size_t)r * K1T;
    row[k] = hi; row[K1P + k] = hi; row[2 * K1P + k] = lo;
}
__global__ void pack_B1(const float* __restrict__ W_heads) {
    int t = blockIdx.x * blockDim.x + threadIdx.x;
    if (t >= HD * K1P) return;
    int k = t % K1P, n = t / K1P;
    int h = n >> 6, d = n & 63;
    float x = (k < Ff) ? W_heads[((size_t)h * Ff + k) * NHID + d] : 0.f;
    __nv_bfloat16 hi = __float2bfloat16(x);
    __nv_bfloat16 lo = __float2bfloat16(x - __bfloat162float(hi));
    __nv_bfloat16* row = g_Bpk1 + (size_t)n * K1T;
    row[k] = hi; row[K1P + k] = lo; row[2 * K1P + k] = hi;
}
__global__ void pack_B3(const float* __restrict__ W_out) {
    int t = blockIdx.x * blockDim.x + threadIdx.x;
    if (t >= N3P * HD) return;
    int k = t % HD, n = t / HD;
    float x = (n < HID) ? W_out[(size_t)k * HID + n] : 0.f;
    __nv_bfloat16 hi = __float2bfloat16(x);
    __nv_bfloat16 lo = __float2bfloat16(x - __bfloat162float(hi));
    __nv_bfloat16* row = g_Bpk3 + (size_t)n * K3T;
    row[k] = hi; row[HD + k] = lo; row[2 * HD + k] = hi;
}
__global__ void pack_fp(const float* __restrict__ fp) {
    int t = blockIdx.x * blockDim.x + threadIdx.x;
    if (t >= Bsz * KF) return;
    int k = t % KF, r = t / KF;
    float x = (k < FP_DIM) ? fp[(size_t)r * FP_DIM + k] : 0.f;
    __nv_bfloat16 hi = __float2bfloat16(x);
    __nv_bfloat16 lo = __float2bfloat16(x - __bfloat162float(hi));
    __nv_bfloat16* row = g_fpk + (size_t)r * KFT;
    row[k] = hi; row[KF + k] = hi; row[2 * KF + k] = lo;
}
__global__ void pack_w1k(const float* __restrict__ w) {
    int t = blockIdx.x * blockDim.x + threadIdx.x;
    if (t >= FP2 * KF) return;
    int k = t % KF, n = t / KF;
    float x = (k < FP_DIM) ? w[(size_t)k * FP2 + n] : 0.f;
    __nv_bfloat16 hi = __float2bfloat16(x);
    __nv_bfloat16 lo = __float2bfloat16(x - __bfloat162float(hi));
    __nv_bfloat16* row = g_w1k + (size_t)n * KFT;
    row[k] = hi; row[KF + k] = lo; row[2 * KF + k] = hi;
}

// ---------------- fc1 reduce ------------------------------------------------------
__global__ void fc1_reduce(const float* __restrict__ fc1_b) {
    int t = blockIdx.x * blockDim.x + threadIdx.x;
    if (t >= Bsz * FP2) return;
    float s = 0.f;
    #pragma unroll
    for (int z = 0; z < FS1; z++) s += g_part[(size_t)z * Bsz * FP2 + t];
    g_t1[t] = fmaxf(s + fc1_b[t & (FP2 - 1)], 0.f);
}

// ============ HMMA fused attention v2 ============================================
// Resident split V^T (Vh/Vl[64][PS]); P generated as split bf16 16-j tiles,
// double-buffered; gen overlapped with 3-pass MMA (Ph*Vh + Ph*Vl + Pl*Vh).
#define PS   136
#define AS2  24
#define ATT_SM (64*PS*2*2 + 2*128*AS2*2*2 + 3*128*4)   // 60,928 B

// ---------------- gat1_hmma: per (b,h) -------------------------------------------
__global__ __launch_bounds__(256) void gat1_hmma(const float* __restrict__ a_heads,
                                                 const int* __restrict__ adj)
{
    extern __shared__ __align__(16) char smraw[];
    __nv_bfloat16* Vh = reinterpret_cast<__nv_bfloat16*>(smraw);
    __nv_bfloat16* Vl = Vh + 64 * PS;
    __nv_bfloat16* Ph = Vl + 64 * PS;        // [buf][128*AS2]
    __nv_bfloat16* Pl = Ph + 2 * 128 * AS2;
    float* ss   = reinterpret_cast<float*>(Pl + 2 * 128 * AS2);
    float* dd   = ss + 128;
    float* rsum = dd + 128;

    const int z = blockIdx.x;
    const int b = z >> 3, h = z & 7;
    const int tid = threadIdx.x, wid = tid >> 5, lane = tid & 31;
    const float* whbase = g_Wh + ((size_t)b * Nn) * HD + h * NHID;

    if (tid < 128) rsum[tid] = 0.f;

    // scores
    const float* a1 = a_heads + h * (2 * NHID);
    const float* a2v = a1 + NHID;
    for (int j = wid; j < 128; j += 8) {
        const float w0 = whbase[(size_t)j * HD + lane];
        const float w1 = whbase[(size_t)j * HD + lane + 32];
        float s1 = fmaf(w0, a1[lane], w1 * a1[lane + 32]);
        float s2 = fmaf(w0, a2v[lane], w1 * a2v[lane + 32]);
        s1 = warp_sum(s1); s2 = warp_sum(s2);
        if (lane == 0) { ss[j] = s1; dd[j] = s2; }
    }
    // V^T split
    for (int t = tid; t < 64 * 128; t += 256) {
        const int j = t >> 6, d = t & 63;
        float x = whbase[(size_t)j * HD + d];
        __nv_bfloat16 hi = __float2bfloat16(x);
        Vh[d * PS + j] = hi;
        Vl[d * PS + j] = __float2bfloat16(x - __bfloat162float(hi));
    }
    __syncthreads();

    // gen mapping: i = tid>>1, jg = (tid&1)*8
    const int gi = tid >> 1;
    const int gjg = (tid & 1) << 3;
    const float ssi = ss[gi];
    const int* adjr = adj + ((size_t)b * Nn + gi) * Nn;
    int madj[8];
    float rs = 0.f;

    auto loadM = [&](int s) {
        const int j0 = (s << 4) + gjg;
        *reinterpret_cast<int4*>(madj)     = *reinterpret_cast<const int4*>(adjr + j0);
        *reinterpret_cast<int4*>(madj + 4) = *reinterpret_cast<const int4*>(adjr + j0 + 4);
    };
    auto genP = [&](int s, int buf) {
        const int j0 = (s << 4) + gjg;
        unsigned hp[4], lp[4];
        #pragma unroll
        for (int q = 0; q < 4; q++) {
            float p0, p1;
            {
                float e = ssi + dd[j0 + 2 * q];
                e = (e > 0.f) ? e : ALPHA * e;
                p0 = (madj[2 * q] > 0) ? __expf(e) : 0.f;
            }
            {
                float e = ssi + dd[j0 + 2 * q + 1];
                e = (e > 0.f) ? e : ALPHA * e;
                p1 = (madj[2 * q + 1] > 0) ? __expf(e) : 0.f;
            }
            rs += p0 + p1;
            __nv_bfloat16 h0 = __float2bfloat16(p0), h1 = __float2bfloat16(p1);
            hp[q] = bfus(h0) | (bfus(h1) << 16);
            lp[q] = bfus(__float2bfloat16(p0 - __bfloat162float(h0)))
                  | (bfus(__float2bfloat16(p1 - __bfloat162float(h1))) << 16);
        }
        *reinterpret_cast<uint4*>(Ph + buf * 128 * AS2 + gi * AS2 + gjg) =
            make_uint4(hp[0], hp[1], hp[2], hp[3]);
        *reinterpret_cast<uint4*>(Pl + buf * 128 * AS2 + gi * AS2 + gjg) =
            make_uint4(lp[0], lp[1], lp[2], lp[3]);
    };

    const int wy = wid & 3, wx = wid >> 2;
    const int lq = lane & 7, lg8 = (lane >> 3) & 1, lg16 = lane >> 4;
    const int fgid = lane >> 2, ftig = lane & 3;

    float acc[2][4][4];
    #pragma unroll
    for (int mt = 0; mt < 2; mt++)
        #pragma unroll
        for (int nt = 0; nt < 4; nt++)
            #pragma unroll
            for (int q = 0; q < 4; q++) acc[mt][nt][q] = 0.f;

    loadM(0);
    genP(0, 0);
    __syncthreads();

    for (int s = 0; s < 8; s++) {
        const int cur = s & 1;
        if (s < 7) loadM(s + 1);

        const __nv_bfloat16* Pc = Ph + cur * 128 * AS2;
        const __nv_bfloat16* Qc = Pl + cur * 128 * AS2;
        unsigned aH[2][4], aL[2][4], bH[4][2], bL[4][2];
        #pragma unroll
        for (int mt = 0; mt < 2; mt++) {
            const int r = wy * 32 + mt * 16 + lq + 8 * lg8;
            ldsm4(Pc + r * AS2 + 8 * lg16, aH[mt][0], aH[mt][1], aH[mt][2], aH[mt][3]);
            ldsm4(Qc + r * AS2 + 8 * lg16, aL[mt][0], aL[mt][1], aL[mt][2], aL[mt][3]);
        }
        #pragma unroll
        for (int p = 0; p < 2; p++) {
            const int rn = wx * 32 + p * 16 + lq + 8 * lg8;
            unsigned r0, r1, r2, r3;
            ldsm4(Vh + rn * PS + s * 16 + 8 * lg16, r0, r1, r2, r3);
            bH[2 * p][0] = r0; bH[2 * p + 1][0] = r1;
            bH[2 * p][1] = r2; bH[2 * p + 1][1] = r3;
            ldsm4(Vl + rn * PS + s * 16 + 8 * lg16, r0, r1, r2, r3);
            bL[2 * p][0] = r0; bL[2 * p + 1][0] = r1;
            bL[2 * p][1] = r2; bL[2 * p + 1][1] = r3;
        }
        #pragma unroll
        for (int mt = 0; mt < 2; mt++)
            #pragma unroll
            for (int nt = 0; nt < 4; nt++) {
                MMA16816(acc[mt][nt], aH[mt][0], aH[mt][1], aH[mt][2], aH[mt][3],
                         bH[nt][0], bH[nt][1]);
                MMA16816(acc[mt][nt], aH[mt][0], aH[mt][1], aH[mt][2], aH[mt][3],
                         bL[nt][0], bL[nt][1]);
                MMA16816(acc[mt][nt], aL[mt][0], aL[mt][1], aL[mt][2], aL[mt][3],
                         bH[nt][0], bH[nt][1]);
            }

        if (s < 7) genP(s + 1, cur ^ 1);
        __syncthreads();
    }

    atomicAdd(&rsum[gi], rs);
    __syncthreads();

    // epilogue: scale, elu, split-pack into g_hpk
    #pragma unroll
    for (int mt = 0; mt < 2; mt++) {
        const int r = wy * 32 + mt * 16 + fgid;
        const float inv0 = 1.f / rsum[r];
        const float inv8 = 1.f / rsum[r + 8];
        __nv_bfloat16* rp0 = g_hpk + (size_t)(b * Nn + r) * K3T + h * NHID;
        __nv_bfloat16* rp8 = g_hpk + (size_t)(b * Nn + r + 8) * K3T + h * NHID;
        #pragma unroll
        for (int nt = 0; nt < 4; nt++) {
            const int c = wx * 32 + nt * 8 + 2 * ftig;
            float v0 = acc[mt][nt][0] * inv0, v1 = acc[mt][nt][1] * inv0;
            float v2 = acc[mt][nt][2] * inv8, v3 = acc[mt][nt][3] * inv8;
            v0 = (v0 > 0.f) ? v0 : expm1f(v0);
            v1 = (v1 > 0.f) ? v1 : expm1f(v1);
            v2 = (v2 > 0.f) ? v2 : expm1f(v2);
            v3 = (v3 > 0.f) ? v3 : expm1f(v3);
            __nv_bfloat16 h0 = __float2bfloat16(v0), h1 = __float2bfloat16(v1);
            __nv_bfloat16 h2 = __float2bfloat16(v2), h3 = __float2bfloat16(v3);
            unsigned hp0 = bfus(h0) | (bfus(h1) << 16);
            unsigned lp0 = bfus(__float2bfloat16(v0 - __bfloat162float(h0)))
                         | (bfus(__float2bfloat16(v1 - __bfloat162float(h1))) << 16);
            unsigned hp8 = bfus(h2) | (bfus(h3) << 16);
            unsigned lp8 = bfus(__float2bfloat16(v2 - __bfloat162float(h2)))
                         | (bfus(__float2bfloat16(v3 - __bfloat162float(h3))) << 16);
            *reinterpret_cast<unsigned*>(rp0 + c)          = hp0;
            *reinterpret_cast<unsigned*>(rp0 + HD + c)     = hp0;
            *reinterpret_cast<unsigned*>(rp0 + 2 * HD + c) = lp0;
            *reinterpret_cast<unsigned*>(rp8 + c)          = hp8;
            *reinterpret_cast<unsigned*>(rp8 + HD + c)     = hp8;
            *reinterpret_cast<unsigned*>(rp8 + 2 * HD + c) = lp8;
        }
    }
}

// ---------------- score2 ----------------------------------------------------------
__global__ __launch_bounds__(256) void score2_kernel(const float* __restrict__ a_out)
{
    const int b = blockIdx.x;
    const int tid = threadIdx.x, warp = tid >> 5, lane = tid & 31;
    const float* W = g_Wh2 + (size_t)b * Nn * HID;
    for (int j = warp; j < 128; j += 8) {
        float s1 = 0.f, s2 = 0.f;
        #pragma unroll
        for (int t = 0; t < 10; t++) {
            int d = lane + 32 * t;
            if (d < HID) {
                float w = W[(size_t)j * HID + d];
                s1 = fmaf(w, a_out[d], s1);
                s2 = fmaf(w, a_out[HID + d], s2);
            }
        }
        s1 = warp_sum(s1); s2 = warp_sum(s2);
        if (lane == 0) { g_ss2[b * Nn + j] = s1; g_dd2[b * Nn + j] = s2; }
    }
}

// ---------------- av2_hmma: per (b, 64-col slice), grid (5,1,Bsz) ----------------
__global__ __launch_bounds__(256) void av2_hmma(const int* __restrict__ adj)
{
    extern __shared__ __align__(16) char smraw[];
    __nv_bfloat16* Vh = reinterpret_cast<__nv_bfloat16*>(smraw);
    __nv_bfloat16* Vl = Vh + 64 * PS;
    __nv_bfloat16* Ph = Vl + 64 * PS;
    __nv_bfloat16* Pl = Ph + 2 * 128 * AS2;
    float* ss   = reinterpret_cast<float*>(Pl + 2 * 128 * AS2);
    float* dd   = ss + 128;
    float* rsum = dd + 128;

    const int b = blockIdx.z;
    const int col0 = blockIdx.x * 64;
    const int tid = threadIdx.x, wid = tid >> 5, lane = tid & 31;
    const float* Wb = g_Wh2 + (size_t)b * Nn * HID;

    if (tid < 128) {
        ss[tid] = g_ss2[b * Nn + tid];
        dd[tid] = g_dd2[b * Nn + tid];
        rsum[tid] = 0.f;
    }
    for (int t = tid; t < 64 * 128; t += 256) {
        const int j = t >> 6, d = t & 63;
        const int gc = col0 + d;
        float x = (gc < HID) ? Wb[(size_t)j * HID + gc] : 0.f;
        __nv_bfloat16 hi = __float2bfloat16(x);
        Vh[d * PS + j] = hi;
        Vl[d * PS + j] = __float2bfloat16(x - __bfloat162float(hi));
    }
    __syncthreads();

    const int gi = tid >> 1;
    const int gjg = (tid & 1) << 3;
    const float ssi = ss[gi];
    const int* adjr = adj + ((size_t)b * Nn + gi) * Nn;
    int madj[8];
    float rs = 0.f;

    auto loadM = [&](int s) {
        const int j0 = (s << 4) + gjg;
        *reinterpret_cast<int4*>(madj)     = *reinterpret_cast<const int4*>(adjr + j0);
        *reinterpret_cast<int4*>(madj + 4) = *reinterpret_cast<const int4*>(adjr + j0 + 4);
    };
    auto genP = [&](int s, int buf) {
        const int j0 = (s << 4) + gjg;
        unsigned hp[4], lp[4];
        #pragma unroll
        for (int q = 0; q < 4; q++) {
            float p0, p1;
            {
                float e = ssi + dd[j0 + 2 * q];
                e = (e > 0.f) ? e : ALPHA * e;
                p0 = (madj[2 * q] > 0) ? __expf(e) : 0.f;
            }
            {
                float e = ssi + dd[j0 + 2 * q + 1];
                e = (e > 0.f) ? e : ALPHA * e;
                p1 = (madj[2 * q + 1] > 0) ? __expf(e) : 0.f;
            }
            rs += p0 + p1;
            __nv_bfloat16 h0 = __float2bfloat16(p0), h1 = __float2bfloat16(p1);
            hp[q] = bfus(h0) | (bfus(h1) << 16);
            lp[q] = bfus(__float2bfloat16(p0 - __bfloat162float(h0)))
                  | (bfus(__float2bfloat16(p1 - __bfloat162float(h1))) << 16);
        }
        *reinterpret_cast<uint4*>(Ph + buf * 128 * AS2 + gi * AS2 + gjg) =
            make_uint4(hp[0], hp[1], hp[2], hp[3]);
        *reinterpret_cast<uint4*>(Pl + buf * 128 * AS2 + gi * AS2 + gjg) =
            make_uint4(lp[0], lp[1], lp[2], lp[3]);
    };

    const int wy = wid & 3, wx = wid >> 2;
    const int lq = lane & 7, lg8 = (lane >> 3) & 1, lg16 = lane >> 4;
    const int fgid = lane >> 2, ftig = lane & 3;

    float acc[2][4][4];
    #pragma unroll
    for (int mt = 0; mt < 2; mt++)
        #pragma unroll
        for (int nt = 0; nt < 4; nt++)
            #pragma unroll
            for (int q = 0; q < 4; q++) acc[mt][nt][q] = 0.f;

    loadM(0);
    genP(0, 0);
    __syncthreads();

    for (int s = 0; s < 8; s++) {
        const int cur = s & 1;
        if (s < 7) loadM(s + 1);

        const __nv_bfloat16* Pc = Ph + cur * 128 * AS2;
        const __nv_bfloat16* Qc = Pl + cur * 128 * AS2;
        unsigned aH[2][4], aL[2][4], bH[4][2], bL[4][2];
        #pragma unroll
        for (int mt = 0; mt < 2; mt++) {
            const int r = wy * 32 + mt * 16 + lq + 8 * lg8;
            ldsm4(Pc + r * AS2 + 8 * lg16, aH[mt][0], aH[mt][1], aH[mt][2], aH[mt][3]);
            ldsm4(Qc + r * AS2 + 8 * lg16, aL[mt][0], aL[mt][1], aL[mt][2], aL[mt][3]);
        }
        #pragma unroll
        for (int p = 0; p < 2; p++) {
            const int rn = wx * 32 + p * 16 + lq + 8 * lg8;
            unsigned r0, r1, r2, r3;
            ldsm4(Vh + rn * PS + s * 16 + 8 * lg16, r0, r1, r2, r3);
            bH[2 * p][0] = r0; bH[2 * p + 1][0] = r1;
            bH[2 * p][1] = r2; bH[2 * p + 1][1] = r3;
            ldsm4(Vl + rn * PS + s * 16 + 8 * lg16, r0, r1, r2, r3);
            bL[2 * p][0] = r0; bL[2 * p + 1][0] = r1;
            bL[2 * p][1] = r2; bL[2 * p + 1][1] = r3;
        }
        #pragma unroll
        for (int mt = 0; mt < 2; mt++)
            #pragma unroll
            for (int nt = 0; nt < 4; nt++) {
                MMA16816(acc[mt][nt], aH[mt][0], aH[mt][1], aH[mt][2], aH[mt][3],
                         bH[nt][0], bH[nt][1]);
                MMA16816(acc[mt][nt], aH[mt][0], aH[mt][1], aH[mt][2], aH[mt][3],
                         bL[nt][0], bL[nt][1]);
                MMA16816(acc[mt][nt], aL[mt][0], aL[mt][1], aL[mt][2], aL[mt][3],
                         bH[nt][0], bH[nt][1]);
            }

        if (s < 7) genP(s + 1, cur ^ 1);
        __syncthreads();
    }

    atomicAdd(&rsum[gi], rs);
    __syncthreads();

    float* Cb = g_O + (size_t)b * Nn * HID;
    #pragma unroll
    for (int mt = 0; mt < 2; mt++) {
        const int r = wy * 32 + mt * 16 + fgid;
        const float inv0 = 1.f / rsum[r];
        const float inv8 = 1.f / rsum[r + 8];
        #pragma unroll
        for (int nt = 0; nt < 4; nt++) {
            const int c = col0 + wx * 32 + nt * 8 + 2 * ftig;
            if (c < HID) {
                float v0 = acc[mt][nt][0] * inv0, v1 = acc[mt][nt][1] * inv0;
                float v2 = acc[mt][nt][2] * inv8, v3 = acc[mt][nt][3] * inv8;
                v0 = (v0 > 0.f) ? v0 : expm1f(v0);
                v1 = (v1 > 0.f) ? v1 : expm1f(v1);
                v2 = (v2 > 0.f) ? v2 : expm1f(v2);
                v3 = (v3 > 0.f) ? v3 : expm1f(v3);
                *reinterpret_cast<float2*>(Cb + (size_t)r * HID + c)       = make_float2(v0, v1);
                *reinterpret_cast<float2*>(Cb + (size_t)(r + 8) * HID + c) = make_float2(v2, v3);
            }
        }
    }
}

// ---------------- ls2 -------------------------------------------------------------
__global__ __launch_bounds__(256) void ls2_kernel()
{
    __shared__ float acc[8 * HID];
    const int b = blockIdx.x;
    const int tid = threadIdx.x, warp = tid >> 5, lane = tid & 31;
    for (int t = tid; t < 8 * HID; t += 256) acc[t] = 0.f;
    __syncthreads();

    const float* O = g_O + (size_t)b * Nn * HID;
    float* accw = acc + warp * HID;
    for (int i = warp; i < 128; i += 8) {
        float o[10];
        #pragma unroll
        for (int t = 0; t < 10; t++) {
            int d = lane + 32 * t;
            o[t] = (d < HID) ? O[(size_t)i * HID + d] : -1e30f;
        }
        float m = o[0];
        #pragma unroll
        for (int t = 1; t < 10; t++) m = fmaxf(m, o[t]);
        m = warp_max(m);
        m = __shfl_sync(0xffffffffu, m, 0);
        float se = 0.f;
        #pragma unroll
        for (int t = 0; t < 10; t++) se += __expf(o[t] - m);
        se = warp_sum(se);
        se = __shfl_sync(0xffffffffu, se, 0);
        const float lse = m + logf(se);
        #pragma unroll
        for (int t = 0; t < 10; t++) {
            int d = lane + 32 * t;
            if (d < HID) accw[d] += o[t] - lse;
        }
    }
    __syncthreads();
    for (int d = tid; d < HID; d += 256) {
        float s = 0.f;
        #pragma unroll
        for (int w = 0; w < 8; w++) s += acc[w * HID + d];
        g_gat[b * HID + d] = s * (1.f / 128.f);
    }
}

// ---------------- head ------------------------------------------------------------
#define HB 4
__global__ __launch_bounds__(256) void head_fused(
    const float* __restrict__ fc2_w, const float* __restrict__ fc2_b,
    const float* __restrict__ Wg,    const float* __restrict__ bg,
    const float* __restrict__ Wf,    const float* __restrict__ bf,
    const float* __restrict__ W1,    const float* __restrict__ b1,
    const float* __restrict__ w2,    const float* __restrict__ b2,
    float* __restrict__ out)
{
    __shared__ float t1s [HB][512];
    __shared__ float gats[HB][HID];
    __shared__ float fpns[HB][HID];
    __shared__ float us  [HB][HID];
    __shared__ float vs  [HB][HID];
    __shared__ float ys  [HB][HID];

    const int b0 = blockIdx.x * HB;
    const int tid = threadIdx.x;

    for (int t = tid; t < HB * 512; t += 256) {
        int r = t >> 9;
        t1s[r][t & 511] = g_t1[(size_t)(b0 + r) * FP2 + (t & 511)];
    }
    for (int t = tid; t < HB * HID; t += 256) {
        int r = t / HID, c = t - r * HID;
        gats[r][c] = g_gat[(size_t)(b0 + r) * HID + c];
    }
    __syncthreads();

    for (int c = tid; c < HID; c += 256) {
        float a[HB] = {};
        #pragma unroll 4
        for (int k = 0; k < 512; k++) {
            float w = fc2_w[(size_t)k * HID + c];
            #pragma unroll
            for (int r = 0; r < HB; r++) a[r] = fmaf(t1s[r][k], w, a[r]);
        }
        float bb = fc2_b[c];
        #pragma unroll
        for (int r = 0; r < HB; r++) fpns[r][c] = a[r] + bb;
    }
    __syncthreads();

    for (int c = tid; c < HID; c += 256) {
        float a[HB] = {}, e[HB] = {};
        #pragma unroll 4
        for (int k = 0; k < HID; k++) {
            float wg = Wg[(size_t)k * HID + c];
            float wf = Wf[(size_t)k * HID + c];
            #pragma unroll
            for (int r = 0; r < HB; r++) {
                a[r] = fmaf(gats[r][k], wg, a[r]);
                e[r] = fmaf(fpns[r][k], wf, e[r]);
            }
        }
        float bbg = bg[c], bbf = bf[c];
        #pragma unroll
        for (int r = 0; r < HB; r++) {
            us[r][c] = fmaxf(a[r] + bbg, 0.f);
            vs[r][c] = fmaxf(e[r] + bbf, 0.f);
        }
    }
    __syncthreads();

    for (int c = tid; c < HID; c += 256) {
        float a[HB] = {};
        #pragma unroll 4
        for (int k = 0; k < HID; k++) {
            float w = W1[(size_t)k * HID + c];
            #pragma unroll
            for (int r = 0; r < HB; r++) a[r] = fmaf(us[r][k], w, a[r]);
        }
        #pragma unroll 4
        for (int k = 0; k < HID; k++) {
            float w = W1[(size_t)(k + HID) * HID + c];
            #pragma unroll
            for (int r = 0; r < HB; r++) a[r] = fmaf(vs[r][k], w, a[r]);
        }
        float bb = b1[c];
        #pragma unroll
        for (int r = 0; r < HB; r++) ys[r][c] = fmaxf(a[r] + bb, 0.f);
    }
    __syncthreads();

    const int warp = tid >> 5, lane = tid & 31;
    if (warp < HB) {
        float s = 0.f;
        for (int k = lane; k < HID; k += 32) s = fmaf(ys[warp][k], w2[k], s);
        s = warp_sum(s);
        if (lane == 0) out[b0 + warp] = 1.f / (1.f + expf(-(s + b2[0])));
    }
}

// ---------------- launch ----------------
extern "C" void kernel_launch(void* const* d_in, const int* in_sizes, int n_in,
                              void* d_out, int out_size)
{
    const float* atom_feats = (const float*)d_in[0];
    const float* fp         = (const float*)d_in[1];
    const float* W_heads    = (const float*)d_in[2];
    const float* a_heads    = (const float*)d_in[3];
    const float* W_out      = (const float*)d_in[4];
    const float* a_out      = (const float*)d_in[5];
    const float* fc1_w      = (const float*)d_in[6];
    const float* fc1_b      = (const float*)d_in[7];
    const float* fc2_w      = (const float*)d_in[8];
    const float* fc2_b      = (const float*)d_in[9];
    const float* fc_gat_w   = (const float*)d_in[10];
    const float* fc_gat_b   = (const float*)d_in[11];
    const float* fc_fpn_w   = (const float*)d_in[12];
    const float* fc_fpn_b   = (const float*)d_in[13];
    const float* ffn_w1     = (const float*)d_in[14];
    const float* ffn_b1     = (const float*)d_in[15];
    const float* ffn_w2     = (const float*)d_in[16];
    const float* ffn_b2     = (const float*)d_in[17];
    const int*   adj        = (const int*)  d_in[18];
    float* out = (float*)d_out;

    __nv_bfloat16 *pApk, *pBpk1, *pHpk, *pBpk3, *pFpk, *pW1k;
    float *pWh, *pWh2, *pPart;
    cudaGetSymbolAddress((void**)&pApk,  g_Apk);
    cudaGetSymbolAddress((void**)&pBpk1, g_Bpk1);
    cudaGetSymbolAddress((void**)&pWh,   g_Wh);
    cudaGetSymbolAddress((void**)&pHpk,  g_hpk);
    cudaGetSymbolAddress((void**)&pBpk3, g_Bpk3);
    cudaGetSymbolAddress((void**)&pWh2,  g_Wh2);
    cudaGetSymbolAddress((void**)&pFpk,  g_fpk);
    cudaGetSymbolAddress((void**)&pW1k,  g_w1k);
    cudaGetSymbolAddress((void**)&pPart, g_part);

    cudaFuncSetAttribute(gat1_hmma, cudaFuncAttributeMaxDynamicSharedMemorySize, ATT_SM);
    cudaFuncSetAttribute(av2_hmma,  cudaFuncAttributeMaxDynamicSharedMemorySize, ATT_SM);

    // 1,2: packing for K1
    pack_atoms<<<(Bsz * Nn * K1P + 255) / 256, 256>>>(atom_feats);
    pack_B1<<<(HD * K1P + 255) / 256, 256>>>(W_heads);
    // 3: K1 on HMMA
    mma_gemm<<<dim3(HD / 128, (Bsz * Nn) / 128, 1), 256>>>(
        pApk, pBpk1, pWh, K1T, K1T, K1T, HD, HD, 0, 0, 0);
    // 4: gat1 HMMA fused attention   <-- ncu capture target
    gat1_hmma<<<Bsz * Hh, 256, ATT_SM>>>(a_heads, adj);
    // 5,6: fc1 packing
    pack_fp<<<(Bsz * KF + 255) / 256, 256>>>(fp);
    pack_w1k<<<(FP2 * KF + 255) / 256, 256>>>(fc1_w);
    // 7,8: fc1 on HMMA split-K + reduce
    mma_gemm<<<dim3(FP2 / 128, Bsz / 128, FS1), 256>>>(
        pFpk, pW1k, pPart, KC1, KFT, KFT, FP2, FP2,
        (long long)KC1, (long long)KC1, (long long)Bsz * FP2);
    fc1_reduce<<<(Bsz * FP2 + 255) / 256, 256>>>(fc1_b);
    // 9: K3 packing (B side)
    pack_B3<<<(N3P * HD + 255) / 256, 256>>>(W_out);
    // 10: K3 on HMMA
    mma_gemm<<<dim3(N3P / 128, (Bsz * Nn) / 128, 1), 256>>>(
        pHpk, pBpk3, pWh2, K3T, K3T, K3T, HID, HID, 0, 0, 0);
    // 11: gat2 scores
    score2_kernel<<<Bsz, 256>>>(a_out);
    // 12: gat2 HMMA fused attention
    av2_hmma<<<dim3(5, 1, Bsz), 256, ATT_SM>>>(adj);
    // 13: gat2 log_softmax + mean
    ls2_kernel<<<Bsz, 256>>>();
    // 14: fused head
    head_fused<<<Bsz / HB, 256>>>(
        fc2_w, fc2_b, fc_gat_w, fc_gat_b, fc_fpn_w, fc_fpn_b,
        ffn_w1, ffn_b1, ffn_w2, ffn_b2, out);
}

// round 15
// speedup vs baseline: 1.3268x; 1.0200x over previous
#include <cuda_runtime.h>
#include <cuda_bf16.h>
#include <math.h>

// Problem constants
#define Bsz 256
#define Nn  128
#define Ff  133
#define Hh  8
#define NHID 64
#define HID 300
#define FP_DIM 1489
#define FP2 512
#define HD (Hh*NHID)     // 512
#define ALPHA 0.2f

#define K1P   160
#define K1T   (3*K1P)    // 480
#define K3T   (3*HD)     // 1536
#define N3P   384
#define KF    1536
#define KFT   (3*KF)     // 4608
#define FS1   12
#define KC1   (KFT/FS1)  // 384

// ---------------- scratch (device globals) ----------------------------------------
__device__ __nv_bfloat16 g_Apk [(size_t)Bsz*Nn * K1T];
__device__ __nv_bfloat16 g_Bpk1[(size_t)HD * K1T];
__device__ float         g_Wh  [(size_t)Bsz*Nn * HD];
__device__ __nv_bfloat16 g_hpk [(size_t)Bsz*Nn * K3T];
__device__ __nv_bfloat16 g_Bpk3[(size_t)N3P * K3T];
__device__ float g_Wh2 [(size_t)Bsz*Nn * HID];
__device__ float g_ss2 [Bsz * Nn];
__device__ float g_dd2 [Bsz * Nn];
__device__ float g_O   [(size_t)Bsz*Nn * HID];
__device__ float g_gat [Bsz * HID];
__device__ __nv_bfloat16 g_fpk [(size_t)Bsz * KFT];
__device__ __nv_bfloat16 g_w1k [(size_t)FP2 * KFT];
__device__ float g_part[(size_t)FS1 * Bsz * FP2];
__device__ float g_t1  [Bsz * FP2];

// ---------------- helpers ----------------
#define FMA2(acc, a, b) \
    asm("fma.rn.f32x2 %0, %1, %2, %0;" : "+l"(acc) : "l"(a), "l"(b))

__device__ __forceinline__ unsigned long long ld2(const float* p) {
    return *reinterpret_cast<const unsigned long long*>(p);
}
__device__ __forceinline__ unsigned long long dup2(float x) {
    unsigned long long r;
    asm("mov.b64 %0, {%1, %1};" : "=l"(r) : "r"(__float_as_uint(x)));
    return r;
}
__device__ __forceinline__ float lo32(unsigned long long v) {
    return __uint_as_float((unsigned)v);
}
__device__ __forceinline__ float hi32(unsigned long long v) {
    return __uint_as_float((unsigned)(v >> 32));
}
__device__ __forceinline__ float warp_sum(float v) {
    #pragma unroll
    for (int o = 16; o; o >>= 1) v += __shfl_down_sync(0xffffffffu, v, o);
    return v;
}
__device__ __forceinline__ float warp_max(float v) {
    #pragma unroll
    for (int o = 16; o; o >>= 1) v = fmaxf(v, __shfl_down_sync(0xffffffffu, v, o));
    return v;
}
__device__ __forceinline__ unsigned smem_u32(const void* p) {
    unsigned a;
    asm("{ .reg .u64 t; cvta.to.shared.u64 t, %1; cvt.u32.u64 %0, t; }" : "=r"(a) : "l"(p));
    return a;
}
__device__ __forceinline__ void ldsm4(const __nv_bfloat16* p,
                                      unsigned& r0, unsigned& r1, unsigned& r2, unsigned& r3) {
    unsigned a = smem_u32(p);
    asm volatile("ldmatrix.sync.aligned.m8n8.x4.shared.b16 {%0,%1,%2,%3}, [%4];"
                 : "=r"(r0), "=r"(r1), "=r"(r2), "=r"(r3) : "r"(a));
}
#define MMA16816(acc, a0, a1, a2, a3, b0, b1) \
    asm volatile("mma.sync.aligned.m16n8k16.row.col.f32.bf16.bf16.f32 " \
                 "{%0,%1,%2,%3}, {%4,%5,%6,%7}, {%8,%9}, {%0,%1,%2,%3};" \
                 : "+f"((acc)[0]), "+f"((acc)[1]), "+f"((acc)[2]), "+f"((acc)[3]) \
                 : "r"(a0), "r"(a1), "r"(a2), "r"(a3), "r"(b0), "r"(b1))
__device__ __forceinline__ unsigned bfus(__nv_bfloat16 x) {
    return (unsigned)__bfloat16_as_ushort(x);
}

// ================= mma_gemm: bf16 HMMA GEMM, 128x128 tile, KC=32, ldmatrix ======
#define MSTR 40
__global__ __launch_bounds__(256) void mma_gemm(
    const __nv_bfloat16* __restrict__ A, const __nv_bfloat16* __restrict__ B,
    float* __restrict__ C, int Ktot, int lda, int ldb, int Nreal, int ldc,
    long long bA, long long bB, long long bC)
{
    __shared__ __align__(16) __nv_bfloat16 As[2][128][MSTR];
    __shared__ __align__(16) __nv_bfloat16 Bs[2][128][MSTR];

    A += (long long)blockIdx.z * bA;
    B += (long long)blockIdx.z * bB;
    C += (long long)blockIdx.z * bC;

    const int tid = threadIdx.x;
    const int wid = tid >> 5, lane = tid & 31;
    const int wy = wid & 3, wx = wid >> 2;
    const int lq = lane & 7, lg8 = (lane >> 3) & 1, lg16 = lane >> 4;
    const int fgid = lane >> 2, ftig = lane & 3;
    const int row0 = blockIdx.y * 128, col0 = blockIdx.x * 128;

    const int lr0 = tid >> 2;
    const int lcq = (tid & 3) << 3;

    uint4 va0, va1, vb0, vb1;
    auto load_g = [&](int k0) {
        va0 = *reinterpret_cast<const uint4*>(A + (size_t)(row0 + lr0) * lda + k0 + lcq);
        va1 = *reinterpret_cast<const uint4*>(A + (size_t)(row0 + lr0 + 64) * lda + k0 + lcq);
        vb0 = *reinterpret_cast<const uint4*>(B + (size_t)(col0 + lr0) * ldb + k0 + lcq);
        vb1 = *reinterpret_cast<const uint4*>(B + (size_t)(col0 + lr0 + 64) * ldb + k0 + lcq);
    };
    auto store_s = [&](int buf) {
        *reinterpret_cast<uint4*>(&As[buf][lr0][lcq])      = va0;
        *reinterpret_cast<uint4*>(&As[buf][lr0 + 64][lcq]) = va1;
        *reinterpret_cast<uint4*>(&Bs[buf][lr0][lcq])      = vb0;
        *reinterpret_cast<uint4*>(&Bs[buf][lr0 + 64][lcq]) = vb1;
    };

    float acc[2][8][4];
    #pragma unroll
    for (int mt = 0; mt < 2; mt++)
        #pragma unroll
        for (int nt = 0; nt < 8; nt++)
            #pragma unroll
            for (int q = 0; q < 4; q++) acc[mt][nt][q] = 0.f;

    const int nsteps = Ktot >> 5;
    load_g(0);
    store_s(0);
    __syncthreads();

    for (int s = 0; s < nsteps; s++) {
        const int cur = s & 1;
        if (s + 1 < nsteps) load_g((s + 1) << 5);

        #pragma unroll
        for (int kk = 0; kk < 32; kk += 16) {
            unsigned af[2][4], bfr[8][2];
            #pragma unroll
            for (int mt = 0; mt < 2; mt++) {
                const int r = wy * 32 + mt * 16 + lq + 8 * lg8;
                ldsm4(&As[cur][r][kk + 8 * lg16],
                      af[mt][0], af[mt][1], af[mt][2], af[mt][3]);
            }
            #pragma unroll
            for (int p = 0; p < 4; p++) {
                const int r = wx * 64 + p * 16 + lq + 8 * lg8;
                unsigned r0, r1, r2, r3;
                ldsm4(&Bs[cur][r][kk + 8 * lg16], r0, r1, r2, r3);
                bfr[2 * p][0] = r0; bfr[2 * p + 1][0] = r1;
                bfr[2 * p][1] = r2; bfr[2 * p + 1][1] = r3;
            }
            #pragma unroll
            for (int mt = 0; mt < 2; mt++)
                #pragma unroll
                for (int nt = 0; nt < 8; nt++)
                    MMA16816(acc[mt][nt], af[mt][0], af[mt][1], af[mt][2], af[mt][3],
                             bfr[nt][0], bfr[nt][1]);
        }

        if (s + 1 < nsteps) store_s(cur ^ 1);
        __syncthreads();
    }

    #pragma unroll
    for (int mt = 0; mt < 2; mt++) {
        const int r0 = row0 + wy * 32 + mt * 16 + fgid;
        #pragma unroll
        for (int nt = 0; nt < 8; nt++) {
            const int c = col0 + wx * 64 + nt * 8 + 2 * ftig;
            if (c < Nreal) {
                *reinterpret_cast<float2*>(C + (size_t)r0 * ldc + c) =
                    make_float2(acc[mt][nt][0], acc[mt][nt][1]);
                *reinterpret_cast<float2*>(C + (size_t)(r0 + 8) * ldc + c) =
                    make_float2(acc[mt][nt][2], acc[mt][nt][3]);
            }
        }
    }
}

// ---------------- packing kernels ------------------------------------------------
__global__ void pack_atoms(const float* __restrict__ src) {
    int t = blockIdx.x * blockDim.x + threadIdx.x;
    if (t >= Bsz * Nn * K1P) return;
    int k = t % K1P, r = t / K1P;
    float x = (k < Ff) ? src[(size_t)r * Ff + k] : 0.f;
    __nv_bfloat16 hi = __float2bfloat16(x);
    __nv_bfloat16 lo = __float2bfloat16(x - __bfloat162float(hi));
    __nv_bfloat16* row = g_Apk + (size_t)r * K1T;
    row[k] = hi; row[K1P + k] = hi; row[2 * K1P + k] = lo;
}
__global__ void pack_B1(const float* __restrict__ W_heads) {
    int t = blockIdx.x * blockDim.x + threadIdx.x;
    if (t >= HD * K1P) return;
    int k = t % K1P, n = t / K1P;
    int h = n >> 6, d = n & 63;
    float x = (k < Ff) ? W_heads[((size_t)h * Ff + k) * NHID + d] : 0.f;
    __nv_bfloat16 hi = __float2bfloat16(x);
    __nv_bfloat16 lo = __float2bfloat16(x - __bfloat162float(hi));
    __nv_bfloat16* row = g_Bpk1 + (size_t)n * K1T;
    row[k] = hi; row[K1P + k] = lo; row[2 * K1P + k] = hi;
}
__global__ void pack_B3(const float* __restrict__ W_out) {
    int t = blockIdx.x * blockDim.x + threadIdx.x;
    if (t >= N3P * HD) return;
    int k = t % HD, n = t / HD;
    float x = (n < HID) ? W_out[(size_t)k * HID + n] : 0.f;
    __nv_bfloat16 hi = __float2bfloat16(x);
    __nv_bfloat16 lo = __float2bfloat16(x - __bfloat162float(hi));
    __nv_bfloat16* row = g_Bpk3 + (size_t)n * K3T;
    row[k] = hi; row[HD + k] = lo; row[2 * HD + k] = hi;
}
__global__ void pack_fp(const float* __restrict__ fp) {
    int t = blockIdx.x * blockDim.x + threadIdx.x;
    if (t >= Bsz * KF) return;
    int k = t % KF, r = t / KF;
    float x = (k < FP_DIM) ? fp[(size_t)r * FP_DIM + k] : 0.f;
    __nv_bfloat16 hi = __float2bfloat16(x);
    __nv_bfloat16 lo = __float2bfloat16(x - __bfloat162float(hi));
    __nv_bfloat16* row = g_fpk + (size_t)r * KFT;
    row[k] = hi; row[KF + k] = hi; row[2 * KF + k] = lo;
}
__global__ void pack_w1k(const float* __restrict__ w) {
    int t = blockIdx.x * blockDim.x + threadIdx.x;
    if (t >= FP2 * KF) return;
    int k = t % KF, n = t / KF;
    float x = (k < FP_DIM) ? w[(size_t)k * FP2 + n] : 0.f;
    __nv_bfloat16 hi = __float2bfloat16(x);
    __nv_bfloat16 lo = __float2bfloat16(x - __bfloat162float(hi));
    __nv_bfloat16* row = g_w1k + (size_t)n * KFT;
    row[k] = hi; row[KF + k] = lo; row[2 * KF + k] = hi;
}

// ---------------- fc1 reduce ------------------------------------------------------
__global__ void fc1_reduce(const float* __restrict__ fc1_b) {
    int t = blockIdx.x * blockDim.x + threadIdx.x;
    if (t >= Bsz * FP2) return;
    float s = 0.f;
    #pragma unroll
    for (int z = 0; z < FS1; z++) s += g_part[(size_t)z * Bsz * FP2 + t];
    g_t1[t] = fmaxf(s + fc1_b[t & (FP2 - 1)], 0.f);
}

// ============ gat1_fused: scores + on-the-fly probs + FMA2 AV + elu ==============
__global__ __launch_bounds__(256) void gat1_fused(const float* __restrict__ a_heads,
                                                  const int* __restrict__ adj)
{
    __shared__ __align__(16) float Ws[128 * 68];
    __shared__ __align__(16) float As[2][16][132];
    __shared__ float ss[128], dd[128], rsum[128];

    const int z = blockIdx.x;
    const int b = z >> 3, h = z & 7;
    const int tid = threadIdx.x, warp = tid >> 5, lane = tid & 31;
    const float* whbase = g_Wh + ((size_t)b * Nn) * HD + h * NHID;

    for (int s = tid; s < 2048; s += 256) {
        int j = s >> 4, q = (s & 15) << 2;
        float4 v = *reinterpret_cast<const float4*>(whbase + (size_t)j * HD + q);
        *reinterpret_cast<float4*>(&Ws[j * 68 + q]) = v;
    }
    if (tid < 128) rsum[tid] = 0.f;
    __syncthreads();

    const float* a1 = a_heads + h * (2 * NHID);
    const float* a2v = a1 + NHID;
    for (int j = warp; j < 128; j += 8) {
        const float w0 = Ws[j * 68 + lane];
        const float w1 = Ws[j * 68 + lane + 32];
        float s1 = fmaf(w0, a1[lane], w1 * a1[lane + 32]);
        float s2 = fmaf(w0, a2v[lane], w1 * a2v[lane + 32]);
        s1 = warp_sum(s1); s2 = warp_sum(s2);
        if (lane == 0) { ss[j] = s1; dd[j] = s2; }
    }
    __syncthreads();

    const int* adjb = adj + (size_t)b * Nn * Nn;
    const int am = tid >> 2;
    const int aq = (tid & 3) << 2;
    const float sm0 = ss[am], sm1 = ss[am + 64];
    float rs0 = 0.f, rs1 = 0.f;
    int mm0[4], mm1[4];

    auto loadM = [&](int k0) {
        *reinterpret_cast<int4*>(mm0) = *reinterpret_cast<const int4*>(adjb + am * Nn + k0 + aq);
        *reinterpret_cast<int4*>(mm1) = *reinterpret_cast<const int4*>(adjb + (am + 64) * Nn + k0 + aq);
    };
    auto genStore = [&](int k0, int buf) {
        #pragma unroll
        for (int q = 0; q < 4; q++) {
            const float dv = dd[k0 + aq + q];
            float e0 = sm0 + dv; e0 = (e0 > 0.f) ? e0 : ALPHA * e0;
            float e1 = sm1 + dv; e1 = (e1 > 0.f) ? e1 : ALPHA * e1;
            float p0 = (mm0[q] > 0) ? __expf(e0) : 0.f;
            float p1 = (mm1[q] > 0) ? __expf(e1) : 0.f;
            rs0 += p0; rs1 += p1;
            As[buf][aq + q][am] = p0;
            As[buf][aq + q][am + 64] = p1;
        }
    };

    const int tx = tid & 15, ty = tid >> 4;
    unsigned long long acc[8][2];
    #pragma unroll
    for (int i = 0; i < 8; i++) { acc[i][0] = 0ull; acc[i][1] = 0ull; }

    loadM(0);
    genStore(0, 0);
    __syncthreads();

    for (int s = 0; s < 8; s++) {
        const int cur = s & 1;
        if (s < 7) loadM((s + 1) << 4);
        #pragma unroll
        for (int k = 0; k < 16; k++) {
            unsigned long long aL[8], b2[2];
            #pragma unroll
            for (int ii = 0; ii < 4; ii++) {
                const unsigned long long pr = ld2(&As[cur][k][2 * ty + 32 * ii]);
                aL[2 * ii]     = dup2(lo32(pr));
                aL[2 * ii + 1] = dup2(hi32(pr));
            }
            b2[0] = ld2(&Ws[(s * 16 + k) * 68 + 2 * tx]);
            b2[1] = ld2(&Ws[(s * 16 + k) * 68 + 2 * tx + 32]);
            #pragma unroll
            for (int i = 0; i < 8; i++) {
                FMA2(acc[i][0], aL[i], b2[0]);
                FMA2(acc[i][1], aL[i], b2[1]);
            }
        }
        if (s < 7) genStore((s + 1) << 4, cur ^ 1);
        __syncthreads();
    }

    atomicAdd(&rsum[am], rs0);
    atomicAdd(&rsum[am + 64], rs1);
    __syncthreads();

    #pragma unroll
    for (int i = 0; i < 8; i++) {
        const int r = 2 * ty + 32 * (i >> 1) + (i & 1);
        const float inv = 1.f / rsum[r];
        __nv_bfloat16* rowp = g_hpk + (size_t)(b * Nn + r) * K3T + h * NHID;
        #pragma unroll
        for (int jj = 0; jj < 2; jj++) {
            const int c = 2 * (tx + 16 * jj);
            float v0 = lo32(acc[i][jj]) * inv;
            float v1 = hi32(acc[i][jj]) * inv;
            v0 = (v0 > 0.f) ? v0 : expm1f(v0);
            v1 = (v1 > 0.f) ? v1 : expm1f(v1);
            __nv_bfloat16 h0 = __float2bfloat16(v0);
            __nv_bfloat16 h1 = __float2bfloat16(v1);
            __nv_bfloat16 l0 = __float2bfloat16(v0 - __bfloat162float(h0));
            __nv_bfloat16 l1 = __float2bfloat16(v1 - __bfloat162float(h1));
            unsigned hp = bfus(h0) | (bfus(h1) << 16);
            unsigned lp = bfus(l0) | (bfus(l1) << 16);
            *reinterpret_cast<unsigned*>(rowp + c)           = hp;
            *reinterpret_cast<unsigned*>(rowp + HD + c)      = hp;
            *reinterpret_cast<unsigned*>(rowp + 2 * HD + c)  = lp;
        }
    }
}

// ---------------- score2 ----------------------------------------------------------
__global__ __launch_bounds__(256) void score2_kernel(const float* __restrict__ a_out)
{
    const int b = blockIdx.x;
    const int tid = threadIdx.x, warp = tid >> 5, lane = tid & 31;
    const float* W = g_Wh2 + (size_t)b * Nn * HID;
    for (int j = warp; j < 128; j += 8) {
        float s1 = 0.f, s2 = 0.f;
        #pragma unroll
        for (int t = 0; t < 10; t++) {
            int d = lane + 32 * t;
            if (d < HID) {
                float w = W[(size_t)j * HID + d];
                s1 = fmaf(w, a_out[d], s1);
                s2 = fmaf(w, a_out[HID + d], s2);
            }
        }
        s1 = warp_sum(s1); s2 = warp_sum(s2);
        if (lane == 0) { g_ss2[b * Nn + j] = s1; g_dd2[b * Nn + j] = s2; }
    }
}

// ============ av2_hmma: per (b, 64-col slice), grid (5,1,Bsz) ====================
#define PS   136
#define AS2  24
#define ATT_SM (64*PS*2*2 + 2*128*AS2*2*2 + 3*128*4)   // 60,928 B
__global__ __launch_bounds__(256) void av2_hmma(const int* __restrict__ adj)
{
    extern __shared__ __align__(16) char smraw[];
    __nv_bfloat16* Vh = reinterpret_cast<__nv_bfloat16*>(smraw);
    __nv_bfloat16* Vl = Vh + 64 * PS;
    __nv_bfloat16* Ph = Vl + 64 * PS;
    __nv_bfloat16* Pl = Ph + 2 * 128 * AS2;
    float* ss   = reinterpret_cast<float*>(Pl + 2 * 128 * AS2);
    float* dd   = ss + 128;
    float* rsum = dd + 128;

    const int b = blockIdx.z;
    const int col0 = blockIdx.x * 64;
    const int tid = threadIdx.x, wid = tid >> 5, lane = tid & 31;
    const float* Wb = g_Wh2 + (size_t)b * Nn * HID;

    if (tid < 128) {
        ss[tid] = g_ss2[b * Nn + tid];
        dd[tid] = g_dd2[b * Nn + tid];
        rsum[tid] = 0.f;
    }
    for (int t = tid; t < 64 * 128; t += 256) {
        const int j = t >> 6, d = t & 63;
        const int gc = col0 + d;
        float x = (gc < HID) ? Wb[(size_t)j * HID + gc] : 0.f;
        __nv_bfloat16 hi = __float2bfloat16(x);
        Vh[d * PS + j] = hi;
        Vl[d * PS + j] = __float2bfloat16(x - __bfloat162float(hi));
    }
    __syncthreads();

    const int gi = tid >> 1;
    const int gjg = (tid & 1) << 3;
    const float ssi = ss[gi];
    const int* adjr = adj + ((size_t)b * Nn + gi) * Nn;
    int madj[8];
    float rs = 0.f;

    auto loadM = [&](int s) {
        const int j0 = (s << 4) + gjg;
        *reinterpret_cast<int4*>(madj)     = *reinterpret_cast<const int4*>(adjr + j0);
        *reinterpret_cast<int4*>(madj + 4) = *reinterpret_cast<const int4*>(adjr + j0 + 4);
    };
    auto genP = [&](int s, int buf) {
        const int j0 = (s << 4) + gjg;
        unsigned hp[4], lp[4];
        #pragma unroll
        for (int q = 0; q < 4; q++) {
            float p0, p1;
            {
                float e = ssi + dd[j0 + 2 * q];
                e = (e > 0.f) ? e : ALPHA * e;
                p0 = (madj[2 * q] > 0) ? __expf(e) : 0.f;
            }
            {
                float e = ssi + dd[j0 + 2 * q + 1];
                e = (e > 0.f) ? e : ALPHA * e;
                p1 = (madj[2 * q + 1] > 0) ? __expf(e) : 0.f;
            }
            rs += p0 + p1;
            __nv_bfloat16 h0 = __float2bfloat16(p0), h1 = __float2bfloat16(p1);
            hp[q] = bfus(h0) | (bfus(h1) << 16);
            lp[q] = bfus(__float2bfloat16(p0 - __bfloat162float(h0)))
                  | (bfus(__float2bfloat16(p1 - __bfloat162float(h1))) << 16);
        }
        *reinterpret_cast<uint4*>(Ph + buf * 128 * AS2 + gi * AS2 + gjg) =
            make_uint4(hp[0], hp[1], hp[2], hp[3]);
        *reinterpret_cast<uint4*>(Pl + buf * 128 * AS2 + gi * AS2 + gjg) =
            make_uint4(lp[0], lp[1], lp[2], lp[3]);
    };

    const int wy = wid & 3, wx = wid >> 2;
    const int lq = lane & 7, lg8 = (lane >> 3) & 1, lg16 = lane >> 4;
    const int fgid = lane >> 2, ftig = lane & 3;

    float acc[2][4][4];
    #pragma unroll
    for (int mt = 0; mt < 2; mt++)
        #pragma unroll
        for (int nt = 0; nt < 4; nt++)
            #pragma unroll
            for (int q = 0; q < 4; q++) acc[mt][nt][q] = 0.f;

    loadM(0);
    genP(0, 0);
    __syncthreads();

    for (int s = 0; s < 8; s++) {
        const int cur = s & 1;
        if (s < 7) loadM(s + 1);

        const __nv_bfloat16* Pc = Ph + cur * 128 * AS2;
        const __nv_bfloat16* Qc = Pl + cur * 128 * AS2;
        unsigned aH[2][4], aL[2][4], bH[4][2], bL[4][2];
        #pragma unroll
        for (int mt = 0; mt < 2; mt++) {
            const int r = wy * 32 + mt * 16 + lq + 8 * lg8;
            ldsm4(Pc + r * AS2 + 8 * lg16, aH[mt][0], aH[mt][1], aH[mt][2], aH[mt][3]);
            ldsm4(Qc + r * AS2 + 8 * lg16, aL[mt][0], aL[mt][1], aL[mt][2], aL[mt][3]);
        }
        #pragma unroll
        for (int p = 0; p < 2; p++) {
            const int rn = wx * 32 + p * 16 + lq + 8 * lg8;
            unsigned r0, r1, r2, r3;
            ldsm4(Vh + rn * PS + s * 16 + 8 * lg16, r0, r1, r2, r3);
            bH[2 * p][0] = r0; bH[2 * p + 1][0] = r1;
            bH[2 * p][1] = r2; bH[2 * p + 1][1] = r3;
            ldsm4(Vl + rn * PS + s * 16 + 8 * lg16, r0, r1, r2, r3);
            bL[2 * p][0] = r0; bL[2 * p + 1][0] = r1;
            bL[2 * p][1] = r2; bL[2 * p + 1][1] = r3;
        }
        #pragma unroll
        for (int mt = 0; mt < 2; mt++)
            #pragma unroll
            for (int nt = 0; nt < 4; nt++) {
                MMA16816(acc[mt][nt], aH[mt][0], aH[mt][1], aH[mt][2], aH[mt][3],
                         bH[nt][0], bH[nt][1]);
                MMA16816(acc[mt][nt], aH[mt][0], aH[mt][1], aH[mt][2], aH[mt][3],
                         bL[nt][0], bL[nt][1]);
                MMA16816(acc[mt][nt], aL[mt][0], aL[mt][1], aL[mt][2], aL[mt][3],
                         bH[nt][0], bH[nt][1]);
            }

        if (s < 7) genP(s + 1, cur ^ 1);
        __syncthreads();
    }

    atomicAdd(&rsum[gi], rs);
    __syncthreads();

    float* Cb = g_O + (size_t)b * Nn * HID;
    #pragma unroll
    for (int mt = 0; mt < 2; mt++) {
        const int r = wy * 32 + mt * 16 + fgid;
        const float inv0 = 1.f / rsum[r];
        const float inv8 = 1.f / rsum[r + 8];
        #pragma unroll
        for (int nt = 0; nt < 4; nt++) {
            const int c = col0 + wx * 32 + nt * 8 + 2 * ftig;
            if (c < HID) {
                float v0 = acc[mt][nt][0] * inv0, v1 = acc[mt][nt][1] * inv0;
                float v2 = acc[mt][nt][2] * inv8, v3 = acc[mt][nt][3] * inv8;
                v0 = (v0 > 0.f) ? v0 : expm1f(v0);
                v1 = (v1 > 0.f) ? v1 : expm1f(v1);
                v2 = (v2 > 0.f) ? v2 : expm1f(v2);
                v3 = (v3 > 0.f) ? v3 : expm1f(v3);
                *reinterpret_cast<float2*>(Cb + (size_t)r * HID + c)       = make_float2(v0, v1);
                *reinterpret_cast<float2*>(Cb + (size_t)(r + 8) * HID + c) = make_float2(v2, v3);
            }
        }
    }
}

// ---------------- ls2 -------------------------------------------------------------
__global__ __launch_bounds__(256) void ls2_kernel()
{
    __shared__ float acc[8 * HID];
    const int b = blockIdx.x;
    const int tid = threadIdx.x, warp = tid >> 5, lane = tid & 31;
    for (int t = tid; t < 8 * HID; t += 256) acc[t] = 0.f;
    __syncthreads();

    const float* O = g_O + (size_t)b * Nn * HID;
    float* accw = acc + warp * HID;
    for (int i = warp; i < 128; i += 8) {
        float o[10];
        #pragma unroll
        for (int t = 0; t < 10; t++) {
            int d = lane + 32 * t;
            o[t] = (d < HID) ? O[(size_t)i * HID + d] : -1e30f;
        }
        float m = o[0];
        #pragma unroll
        for (int t = 1; t < 10; t++) m = fmaxf(m, o[t]);
        m = warp_max(m);
        m = __shfl_sync(0xffffffffu, m, 0);
        float se = 0.f;
        #pragma unroll
        for (int t = 0; t < 10; t++) se += __expf(o[t] - m);
        se = warp_sum(se);
        se = __shfl_sync(0xffffffffu, se, 0);
        const float lse = m + logf(se);
        #pragma unroll
        for (int t = 0; t < 10; t++) {
            int d = lane + 32 * t;
            if (d < HID) accw[d] += o[t] - lse;
        }
    }
    __syncthreads();
    for (int d = tid; d < HID; d += 256) {
        float s = 0.f;
        #pragma unroll
        for (int w = 0; w < 8; w++) s += acc[w * HID + d];
        g_gat[b * HID + d] = s * (1.f / 128.f);
    }
}

// ---------------- head ------------------------------------------------------------
#define HB 4
__global__ __launch_bounds__(256) void head_fused(
    const float* __restrict__ fc2_w, const float* __restrict__ fc2_b,
    const float* __restrict__ Wg,    const float* __restrict__ bg,
    const float* __restrict__ Wf,    const float* __restrict__ bf,
    const float* __restrict__ W1,    const float* __restrict__ b1,
    const float* __restrict__ w2,    const float* __restrict__ b2,
    float* __restrict__ out)
{
    __shared__ float t1s [HB][512];
    __shared__ float gats[HB][HID];
    __shared__ float fpns[HB][HID];
    __shared__ float us  [HB][HID];
    __shared__ float vs  [HB][HID];
    __shared__ float ys  [HB][HID];

    const int b0 = blockIdx.x * HB;
    const int tid = threadIdx.x;

    for (int t = tid; t < HB * 512; t += 256) {
        int r = t >> 9;
        t1s[r][t & 511] = g_t1[(size_t)(b0 + r) * FP2 + (t & 511)];
    }
    for (int t = tid; t < HB * HID; t += 256) {
        int r = t / HID, c = t - r * HID;
        gats[r][c] = g_gat[(size_t)(b0 + r) * HID + c];
    }
    __syncthreads();

    for (int c = tid; c < HID; c += 256) {
        float a[HB] = {};
        #pragma unroll 4
        for (int k = 0; k < 512; k++) {
            float w = fc2_w[(size_t)k * HID + c];
            #pragma unroll
            for (int r = 0; r < HB; r++) a[r] = fmaf(t1s[r][k], w, a[r]);
        }
        float bb = fc2_b[c];
        #pragma unroll
        for (int r = 0; r < HB; r++) fpns[r][c] = a[r] + bb;
    }
    __syncthreads();

    for (int c = tid; c < HID; c += 256) {
        float a[HB] = {}, e[HB] = {};
        #pragma unroll 4
        for (int k = 0; k < HID; k++) {
            float wg = Wg[(size_t)k * HID + c];
            float wf = Wf[(size_t)k * HID + c];
            #pragma unroll
            for (int r = 0; r < HB; r++) {
                a[r] = fmaf(gats[r][k], wg, a[r]);
                e[r] = fmaf(fpns[r][k], wf, e[r]);
            }
        }
        float bbg = bg[c], bbf = bf[c];
        #pragma unroll
        for (int r = 0; r < HB; r++) {
            us[r][c] = fmaxf(a[r] + bbg, 0.f);
            vs[r][c] = fmaxf(e[r] + bbf, 0.f);
        }
    }
    __syncthreads();

    for (int c = tid; c < HID; c += 256) {
        float a[HB] = {};
        #pragma unroll 4
        for (int k = 0; k < HID; k++) {
            float w = W1[(size_t)k * HID + c];
            #pragma unroll
            for (int r = 0; r < HB; r++) a[r] = fmaf(us[r][k], w, a[r]);
        }
        #pragma unroll 4
        for (int k = 0; k < HID; k++) {
            float w = W1[(size_t)(k + HID) * HID + c];
            #pragma unroll
            for (int r = 0; r < HB; r++) a[r] = fmaf(vs[r][k], w, a[r]);
        }
        float bb = b1[c];
        #pragma unroll
        for (int r = 0; r < HB; r++) ys[r][c] = fmaxf(a[r] + bb, 0.f);
    }
    __syncthreads();

    const int warp = tid >> 5, lane = tid & 31;
    if (warp < HB) {
        float s = 0.f;
        for (int k = lane; k < HID; k += 32) s = fmaf(ys[warp][k], w2[k], s);
        s = warp_sum(s);
        if (lane == 0) out[b0 + warp] = 1.f / (1.f + expf(-(s + b2[0])));
    }
}

// ---------------- launch ----------------
extern "C" void kernel_launch(void* const* d_in, const int* in_sizes, int n_in,
                              void* d_out, int out_size)
{
    const float* atom_feats = (const float*)d_in[0];
    const float* fp         = (const float*)d_in[1];
    const float* W_heads    = (const float*)d_in[2];
    const float* a_heads    = (const float*)d_in[3];
    const float* W_out      = (const float*)d_in[4];
    const float* a_out      = (const float*)d_in[5];
    const float* fc1_w      = (const float*)d_in[6];
    const float* fc1_b      = (const float*)d_in[7];
    const float* fc2_w      = (const float*)d_in[8];
    const float* fc2_b      = (const float*)d_in[9];
    const float* fc_gat_w   = (const float*)d_in[10];
    const float* fc_gat_b   = (const float*)d_in[11];
    const float* fc_fpn_w   = (const float*)d_in[12];
    const float* fc_fpn_b   = (const float*)d_in[13];
    const float* ffn_w1     = (const float*)d_in[14];
    const float* ffn_b1     = (const float*)d_in[15];
    const float* ffn_w2     = (const float*)d_in[16];
    const float* ffn_b2     = (const float*)d_in[17];
    const int*   adj        = (const int*)  d_in[18];
    float* out = (float*)d_out;

    __nv_bfloat16 *pApk, *pBpk1, *pHpk, *pBpk3, *pFpk, *pW1k;
    float *pWh, *pWh2, *pPart;
    cudaGetSymbolAddress((void**)&pApk,  g_Apk);
    cudaGetSymbolAddress((void**)&pBpk1, g_Bpk1);
    cudaGetSymbolAddress((void**)&pWh,   g_Wh);
    cudaGetSymbolAddress((void**)&pHpk,  g_hpk);
    cudaGetSymbolAddress((void**)&pBpk3, g_Bpk3);
    cudaGetSymbolAddress((void**)&pWh2,  g_Wh2);
    cudaGetSymbolAddress((void**)&pFpk,  g_fpk);
    cudaGetSymbolAddress((void**)&pW1k,  g_w1k);
    cudaGetSymbolAddress((void**)&pPart, g_part);

    cudaFuncSetAttribute(av2_hmma, cudaFuncAttributeMaxDynamicSharedMemorySize, ATT_SM);

    // 1,2: packing for K1
    pack_atoms<<<(Bsz * Nn * K1P + 255) / 256, 256>>>(atom_feats);
    pack_B1<<<(HD * K1P + 255) / 256, 256>>>(W_heads);
    // 3: K1 on HMMA
    mma_gemm<<<dim3(HD / 128, (Bsz * Nn) / 128, 1), 256>>>(
        pApk, pBpk1, pWh, K1T, K1T, K1T, HD, HD, 0, 0, 0);
    // 4: gat1 fused (FMA2, writes packed h)   <-- ncu capture target
    gat1_fused<<<Bsz * Hh, 256>>>(a_heads, adj);
    // 5,6: fc1 packing
    pack_fp<<<(Bsz * KF + 255) / 256, 256>>>(fp);
    pack_w1k<<<(FP2 * KF + 255) / 256, 256>>>(fc1_w);
    // 7,8: fc1 on HMMA split-K + reduce
    mma_gemm<<<dim3(FP2 / 128, Bsz / 128, FS1), 256>>>(
        pFpk, pW1k, pPart, KC1, KFT, KFT, FP2, FP2,
        (long long)KC1, (long long)KC1, (long long)Bsz * FP2);
    fc1_reduce<<<(Bsz * FP2 + 255) / 256, 256>>>(fc1_b);
    // 9: K3 packing (B side)
    pack_B3<<<(N3P * HD + 255) / 256, 256>>>(W_out);
    // 10: K3 on HMMA
    mma_gemm<<<dim3(N3P / 128, (Bsz * Nn) / 128, 1), 256>>>(
        pHpk, pBpk3, pWh2, K3T, K3T, K3T, HID, HID, 0, 0, 0);
    // 11: gat2 scores
    score2_kernel<<<Bsz, 256>>>(a_out);
    // 12: gat2 HMMA fused attention
    av2_hmma<<<dim3(5, 1, Bsz), 256, ATT_SM>>>(adj);
    // 13: gat2 log_softmax + mean
    ls2_kernel<<<Bsz, 256>>>();
    // 14: fused head
    head_fused<<<Bsz / HB, 256>>>(
        fc2_w, fc2_b, fc_gat_w, fc_gat_b, fc_fpn_w, fc_fpn_b,
        ffn_w1, ffn_b1, ffn_w2, ffn_b2, out);
}

// round 16
// speedup vs baseline: 1.4331x; 1.0801x over previous
#include <cuda_runtime.h>
#include <cuda_bf16.h>
#include <math.h>

// Problem constants
#define Bsz 256
#define Nn  128
#define Ff  133
#define Hh  8
#define NHID 64
#define HID 300
#define FP_DIM 1489
#define FP2 512
#define HD (Hh*NHID)     // 512
#define ALPHA 0.2f

#define K1P   160
#define K1T   (3*K1P)    // 480
#define K3T   (3*HD)     // 1536
#define N3P   384
#define KF    1536
#define KFT   (3*KF)     // 4608
#define FS1   12
#define KC1   (KFT/FS1)  // 384

// ---------------- scratch (device globals) ----------------------------------------
__device__ __nv_bfloat16 g_Apk [(size_t)Bsz*Nn * K1T];
__device__ __nv_bfloat16 g_Bpk1[(size_t)HD * K1T];
__device__ float         g_Wh  [(size_t)Bsz*Nn * HD];
__device__ __nv_bfloat16 g_hpk [(size_t)Bsz*Nn * K3T];
__device__ __nv_bfloat16 g_Bpk3[(size_t)N3P * K3T];
__device__ float g_Wh2 [(size_t)Bsz*Nn * HID];
__device__ float g_ss2 [Bsz * Nn];
__device__ float g_dd2 [Bsz * Nn];
__device__ float g_O   [(size_t)Bsz*Nn * HID];
__device__ float g_gat [Bsz * HID];
__device__ __nv_bfloat16 g_fpk [(size_t)Bsz * KFT];
__device__ __nv_bfloat16 g_w1k [(size_t)FP2 * KFT];
__device__ float g_part[(size_t)FS1 * Bsz * FP2];
__device__ float g_t1  [Bsz * FP2];

// ---------------- helpers ----------------
#define FMA2(acc, a, b) \
    asm("fma.rn.f32x2 %0, %1, %2, %0;" : "+l"(acc) : "l"(a), "l"(b))

__device__ __forceinline__ unsigned long long ld2(const float* p) {
    return *reinterpret_cast<const unsigned long long*>(p);
}
__device__ __forceinline__ unsigned long long dup2(float x) {
    unsigned long long r;
    asm("mov.b64 %0, {%1, %1};" : "=l"(r) : "r"(__float_as_uint(x)));
    return r;
}
__device__ __forceinline__ float lo32(unsigned long long v) {
    return __uint_as_float((unsigned)v);
}
__device__ __forceinline__ float hi32(unsigned long long v) {
    return __uint_as_float((unsigned)(v >> 32));
}
__device__ __forceinline__ float warp_sum(float v) {
    #pragma unroll
    for (int o = 16; o; o >>= 1) v += __shfl_down_sync(0xffffffffu, v, o);
    return v;
}
__device__ __forceinline__ float warp_max(float v) {
    #pragma unroll
    for (int o = 16; o; o >>= 1) v = fmaxf(v, __shfl_down_sync(0xffffffffu, v, o));
    return v;
}
__device__ __forceinline__ unsigned smem_u32(const void* p) {
    unsigned a;
    asm("{ .reg .u64 t; cvta.to.shared.u64 t, %1; cvt.u32.u64 %0, t; }" : "=r"(a) : "l"(p));
    return a;
}
__device__ __forceinline__ void ldsm4(const __nv_bfloat16* p,
                                      unsigned& r0, unsigned& r1, unsigned& r2, unsigned& r3) {
    unsigned a = smem_u32(p);
    asm volatile("ldmatrix.sync.aligned.m8n8.x4.shared.b16 {%0,%1,%2,%3}, [%4];"
                 : "=r"(r0), "=r"(r1), "=r"(r2), "=r"(r3) : "r"(a));
}
#define MMA16816(acc, a0, a1, a2, a3, b0, b1) \
    asm volatile("mma.sync.aligned.m16n8k16.row.col.f32.bf16.bf16.f32 " \
                 "{%0,%1,%2,%3}, {%4,%5,%6,%7}, {%8,%9}, {%0,%1,%2,%3};" \
                 : "+f"((acc)[0]), "+f"((acc)[1]), "+f"((acc)[2]), "+f"((acc)[3]) \
                 : "r"(a0), "r"(a1), "r"(a2), "r"(a3), "r"(b0), "r"(b1))
__device__ __forceinline__ unsigned bfus(__nv_bfloat16 x) {
    return (unsigned)__bfloat16_as_ushort(x);
}

// ================= mma_gemm: bf16 HMMA GEMM, 128x128 tile, KC=32, ldmatrix ======
#define MSTR 40
__global__ __launch_bounds__(256) void mma_gemm(
    const __nv_bfloat16* __restrict__ A, const __nv_bfloat16* __restrict__ B,
    float* __restrict__ C, int Ktot, int lda, int ldb, int Nreal, int ldc,
    long long bA, long long bB, long long bC)
{
    __shared__ __align__(16) __nv_bfloat16 As[2][128][MSTR];
    __shared__ __align__(16) __nv_bfloat16 Bs[2][128][MSTR];

    A += (long long)blockIdx.z * bA;
    B += (long long)blockIdx.z * bB;
    C += (long long)blockIdx.z * bC;

    const int tid = threadIdx.x;
    const int wid = tid >> 5, lane = tid & 31;
    const int wy = wid & 3, wx = wid >> 2;
    const int lq = lane & 7, lg8 = (lane >> 3) & 1, lg16 = lane >> 4;
    const int fgid = lane >> 2, ftig = lane & 3;
    const int row0 = blockIdx.y * 128, col0 = blockIdx.x * 128;

    const int lr0 = tid >> 2;
    const int lcq = (tid & 3) << 3;

    uint4 va0, va1, vb0, vb1;
    auto load_g = [&](int k0) {
        va0 = *reinterpret_cast<const uint4*>(A + (size_t)(row0 + lr0) * lda + k0 + lcq);
        va1 = *reinterpret_cast<const uint4*>(A + (size_t)(row0 + lr0 + 64) * lda + k0 + lcq);
        vb0 = *reinterpret_cast<const uint4*>(B + (size_t)(col0 + lr0) * ldb + k0 + lcq);
        vb1 = *reinterpret_cast<const uint4*>(B + (size_t)(col0 + lr0 + 64) * ldb + k0 + lcq);
    };
    auto store_s = [&](int buf) {
        *reinterpret_cast<uint4*>(&As[buf][lr0][lcq])      = va0;
        *reinterpret_cast<uint4*>(&As[buf][lr0 + 64][lcq]) = va1;
        *reinterpret_cast<uint4*>(&Bs[buf][lr0][lcq])      = vb0;
        *reinterpret_cast<uint4*>(&Bs[buf][lr0 + 64][lcq]) = vb1;
    };

    float acc[2][8][4];
    #pragma unroll
    for (int mt = 0; mt < 2; mt++)
        #pragma unroll
        for (int nt = 0; nt < 8; nt++)
            #pragma unroll
            for (int q = 0; q < 4; q++) acc[mt][nt][q] = 0.f;

    const int nsteps = Ktot >> 5;
    load_g(0);
    store_s(0);
    __syncthreads();

    for (int s = 0; s < nsteps; s++) {
        const int cur = s & 1;
        if (s + 1 < nsteps) load_g((s + 1) << 5);

        #pragma unroll
        for (int kk = 0; kk < 32; kk += 16) {
            unsigned af[2][4], bfr[8][2];
            #pragma unroll
            for (int mt = 0; mt < 2; mt++) {
                const int r = wy * 32 + mt * 16 + lq + 8 * lg8;
                ldsm4(&As[cur][r][kk + 8 * lg16],
                      af[mt][0], af[mt][1], af[mt][2], af[mt][3]);
            }
            #pragma unroll
            for (int p = 0; p < 4; p++) {
                const int r = wx * 64 + p * 16 + lq + 8 * lg8;
                unsigned r0, r1, r2, r3;
                ldsm4(&Bs[cur][r][kk + 8 * lg16], r0, r1, r2, r3);
                bfr[2 * p][0] = r0; bfr[2 * p + 1][0] = r1;
                bfr[2 * p][1] = r2; bfr[2 * p + 1][1] = r3;
            }
            #pragma unroll
            for (int mt = 0; mt < 2; mt++)
                #pragma unroll
                for (int nt = 0; nt < 8; nt++)
                    MMA16816(acc[mt][nt], af[mt][0], af[mt][1], af[mt][2], af[mt][3],
                             bfr[nt][0], bfr[nt][1]);
        }

        if (s + 1 < nsteps) store_s(cur ^ 1);
        __syncthreads();
    }

    #pragma unroll
    for (int mt = 0; mt < 2; mt++) {
        const int r0 = row0 + wy * 32 + mt * 16 + fgid;
        #pragma unroll
        for (int nt = 0; nt < 8; nt++) {
            const int c = col0 + wx * 64 + nt * 8 + 2 * ftig;
            if (c < Nreal) {
                *reinterpret_cast<float2*>(C + (size_t)r0 * ldc + c) =
                    make_float2(acc[mt][nt][0], acc[mt][nt][1]);
                *reinterpret_cast<float2*>(C + (size_t)(r0 + 8) * ldc + c) =
                    make_float2(acc[mt][nt][2], acc[mt][nt][3]);
            }
        }
    }
}

// ---------------- packing kernels ------------------------------------------------
__global__ void pack_atoms(const float* __restrict__ src) {
    int t = blockIdx.x * blockDim.x + threadIdx.x;
    if (t >= Bsz * Nn * K1P) return;
    int k = t % K1P, r = t / K1P;
    float x = (k < Ff) ? src[(size_t)r * Ff + k] : 0.f;
    __nv_bfloat16 hi = __float2bfloat16(x);
    __nv_bfloat16 lo = __float2bfloat16(x - __bfloat162float(hi));
    __nv_bfloat16* row = g_Apk + (size_t)r * K1T;
    row[k] = hi; row[K1P + k] = hi; row[2 * K1P + k] = lo;
}
__global__ void pack_B1(const float* __restrict__ W_heads) {
    int t = blockIdx.x * blockDim.x + threadIdx.x;
    if (t >= HD * K1P) return;
    int k = t % K1P, n = t / K1P;
    int h = n >> 6, d = n & 63;
    float x = (k < Ff) ? W_heads[((size_t)h * Ff + k) * NHID + d] : 0.f;
    __nv_bfloat16 hi = __float2bfloat16(x);
    __nv_bfloat16 lo = __float2bfloat16(x - __bfloat162float(hi));
    __nv_bfloat16* row = g_Bpk1 + (size_t)n * K1T;
    row[k] = hi; row[K1P + k] = lo; row[2 * K1P + k] = hi;
}
__global__ void pack_B3(const float* __restrict__ W_out) {
    int t = blockIdx.x * blockDim.x + threadIdx.x;
    if (t >= N3P * HD) return;
    int k = t % HD, n = t / HD;
    float x = (n < HID) ? W_out[(size_t)k * HID + n] : 0.f;
    __nv_bfloat16 hi = __float2bfloat16(x);
    __nv_bfloat16 lo = __float2bfloat16(x - __bfloat162float(hi));
    __nv_bfloat16* row = g_Bpk3 + (size_t)n * K3T;
    row[k] = hi; row[HD + k] = lo; row[2 * HD + k] = hi;
}
__global__ void pack_fp(const float* __restrict__ fp) {
    int t = blockIdx.x * blockDim.x + threadIdx.x;
    if (t >= Bsz * KF) return;
    int k = t % KF, r = t / KF;
    float x = (k < FP_DIM) ? fp[(size_t)r * FP_DIM + k] : 0.f;
    __nv_bfloat16 hi = __float2bfloat16(x);
    __nv_bfloat16 lo = __float2bfloat16(x - __bfloat162float(hi));
    __nv_bfloat16* row = g_fpk + (size_t)r * KFT;
    row[k] = hi; row[KF + k] = hi; row[2 * KF + k] = lo;
}
__global__ void pack_w1k(const float* __restrict__ w) {
    int t = blockIdx.x * blockDim.x + threadIdx.x;
    if (t >= FP2 * KF) return;
    int k = t % KF, n = t / KF;
    float x = (k < FP_DIM) ? w[(size_t)k * FP2 + n] : 0.f;
    __nv_bfloat16 hi = __float2bfloat16(x);
    __nv_bfloat16 lo = __float2bfloat16(x - __bfloat162float(hi));
    __nv_bfloat16* row = g_w1k + (size_t)n * KFT;
    row[k] = hi; row[KF + k] = lo; row[2 * KF + k] = hi;
}

// ---------------- fc1 reduce ------------------------------------------------------
__global__ void fc1_reduce(const float* __restrict__ fc1_b) {
    int t = blockIdx.x * blockDim.x + threadIdx.x;
    if (t >= Bsz * FP2) return;
    float s = 0.f;
    #pragma unroll
    for (int z = 0; z < FS1; z++) s += g_part[(size_t)z * Bsz * FP2 + t];
    g_t1[t] = fmaxf(s + fc1_b[t & (FP2 - 1)], 0.f);
}

// ============ gat1_fused: separable-exp probs + FMA2 AV + elu ====================
// exp(leaky(s+d)) = (s+d>0) ? exp(s)exp(d) : exp(.2s)exp(.2d) — 512 exps, not 16K.
__global__ __launch_bounds__(256) void gat1_fused(const float* __restrict__ a_heads,
                                                  const int* __restrict__ adj)
{
    __shared__ __align__(16) float Ws[128 * 68];
    __shared__ __align__(16) float As[2][16][132];
    __shared__ float ss[128], dd[128], rsum[128];
    __shared__ float E1[128], E5[128], F1[128], F5[128];

    const int z = blockIdx.x;
    const int b = z >> 3, h = z & 7;
    const int tid = threadIdx.x, warp = tid >> 5, lane = tid & 31;
    const float* whbase = g_Wh + ((size_t)b * Nn) * HD + h * NHID;

    for (int s = tid; s < 2048; s += 256) {
        int j = s >> 4, q = (s & 15) << 2;
        float4 v = *reinterpret_cast<const float4*>(whbase + (size_t)j * HD + q);
        *reinterpret_cast<float4*>(&Ws[j * 68 + q]) = v;
    }
    if (tid < 128) rsum[tid] = 0.f;
    __syncthreads();

    const float* a1 = a_heads + h * (2 * NHID);
    const float* a2v = a1 + NHID;
    for (int j = warp; j < 128; j += 8) {
        const float w0 = Ws[j * 68 + lane];
        const float w1 = Ws[j * 68 + lane + 32];
        float s1 = fmaf(w0, a1[lane], w1 * a1[lane + 32]);
        float s2 = fmaf(w0, a2v[lane], w1 * a2v[lane + 32]);
        s1 = warp_sum(s1); s2 = warp_sum(s2);
        if (lane == 0) { ss[j] = s1; dd[j] = s2; }
    }
    __syncthreads();

    if (tid < 128) {
        const float sv = ss[tid], dv = dd[tid];
        E1[tid] = __expf(sv); E5[tid] = __expf(ALPHA * sv);
        F1[tid] = __expf(dv); F5[tid] = __expf(ALPHA * dv);
    }
    __syncthreads();

    const int* adjb = adj + (size_t)b * Nn * Nn;
    const int am = tid >> 2;
    const int aq = (tid & 3) << 2;
    const float sm0 = ss[am], sm1 = ss[am + 64];
    const float e1_0 = E1[am], e5_0 = E5[am];
    const float e1_1 = E1[am + 64], e5_1 = E5[am + 64];
    float rs0 = 0.f, rs1 = 0.f;
    int mm0[4], mm1[4];

    auto loadM = [&](int k0) {
        *reinterpret_cast<int4*>(mm0) = *reinterpret_cast<const int4*>(adjb + am * Nn + k0 + aq);
        *reinterpret_cast<int4*>(mm1) = *reinterpret_cast<const int4*>(adjb + (am + 64) * Nn + k0 + aq);
    };
    auto genStore = [&](int k0, int buf) {
        #pragma unroll
        for (int q = 0; q < 4; q++) {
            const int j = k0 + aq + q;
            const float dv = dd[j];
            const float f1 = F1[j], f5 = F5[j];
            float p0 = (sm0 + dv > 0.f) ? e1_0 * f1 : e5_0 * f5;
            float p1 = (sm1 + dv > 0.f) ? e1_1 * f1 : e5_1 * f5;
            p0 = (mm0[q] > 0) ? p0 : 0.f;
            p1 = (mm1[q] > 0) ? p1 : 0.f;
            rs0 += p0; rs1 += p1;
            As[buf][aq + q][am] = p0;
            As[buf][aq + q][am + 64] = p1;
        }
    };

    const int tx = tid & 15, ty = tid >> 4;
    unsigned long long acc[8][2];
    #pragma unroll
    for (int i = 0; i < 8; i++) { acc[i][0] = 0ull; acc[i][1] = 0ull; }

    loadM(0);
    genStore(0, 0);
    __syncthreads();

    for (int s = 0; s < 8; s++) {
        const int cur = s & 1;
        if (s < 7) loadM((s + 1) << 4);
        #pragma unroll
        for (int k = 0; k < 16; k++) {
            unsigned long long aL[8], b2[2];
            #pragma unroll
            for (int ii = 0; ii < 4; ii++) {
                const unsigned long long pr = ld2(&As[cur][k][2 * ty + 32 * ii]);
                aL[2 * ii]     = dup2(lo32(pr));
                aL[2 * ii + 1] = dup2(hi32(pr));
            }
            b2[0] = ld2(&Ws[(s * 16 + k) * 68 + 2 * tx]);
            b2[1] = ld2(&Ws[(s * 16 + k) * 68 + 2 * tx + 32]);
            #pragma unroll
            for (int i = 0; i < 8; i++) {
                FMA2(acc[i][0], aL[i], b2[0]);
                FMA2(acc[i][1], aL[i], b2[1]);
            }
        }
        if (s < 7) genStore((s + 1) << 4, cur ^ 1);
        __syncthreads();
    }

    atomicAdd(&rsum[am], rs0);
    atomicAdd(&rsum[am + 64], rs1);
    __syncthreads();

    #pragma unroll
    for (int i = 0; i < 8; i++) {
        const int r = 2 * ty + 32 * (i >> 1) + (i & 1);
        const float inv = 1.f / rsum[r];
        __nv_bfloat16* rowp = g_hpk + (size_t)(b * Nn + r) * K3T + h * NHID;
        #pragma unroll
        for (int jj = 0; jj < 2; jj++) {
            const int c = 2 * (tx + 16 * jj);
            float v0 = lo32(acc[i][jj]) * inv;
            float v1 = hi32(acc[i][jj]) * inv;
            v0 = (v0 > 0.f) ? v0 : expm1f(v0);
            v1 = (v1 > 0.f) ? v1 : expm1f(v1);
            __nv_bfloat16 h0 = __float2bfloat16(v0);
            __nv_bfloat16 h1 = __float2bfloat16(v1);
            __nv_bfloat16 l0 = __float2bfloat16(v0 - __bfloat162float(h0));
            __nv_bfloat16 l1 = __float2bfloat16(v1 - __bfloat162float(h1));
            unsigned hp = bfus(h0) | (bfus(h1) << 16);
            unsigned lp = bfus(l0) | (bfus(l1) << 16);
            *reinterpret_cast<unsigned*>(rowp + c)           = hp;
            *reinterpret_cast<unsigned*>(rowp + HD + c)      = hp;
            *reinterpret_cast<unsigned*>(rowp + 2 * HD + c)  = lp;
        }
    }
}

// ---------------- score2 ----------------------------------------------------------
__global__ __launch_bounds__(256) void score2_kernel(const float* __restrict__ a_out)
{
    const int b = blockIdx.x;
    const int tid = threadIdx.x, warp = tid >> 5, lane = tid & 31;
    const float* W = g_Wh2 + (size_t)b * Nn * HID;
    for (int j = warp; j < 128; j += 8) {
        float s1 = 0.f, s2 = 0.f;
        #pragma unroll
        for (int t = 0; t < 10; t++) {
            int d = lane + 32 * t;
            if (d < HID) {
                float w = W[(size_t)j * HID + d];
                s1 = fmaf(w, a_out[d], s1);
                s2 = fmaf(w, a_out[HID + d], s2);
            }
        }
        s1 = warp_sum(s1); s2 = warp_sum(s2);
        if (lane == 0) { g_ss2[b * Nn + j] = s1; g_dd2[b * Nn + j] = s2; }
    }
}

// ============ av2_hmma: separable-exp probs + HMMA AV, grid (5,1,Bsz) ============
#define PS   136
#define AS2  24
#define ATT_SM (64*PS*2*2 + 2*128*AS2*2*2 + 3*128*4 + 4*128*4)
__global__ __launch_bounds__(256) void av2_hmma(const int* __restrict__ adj)
{
    extern __shared__ __align__(16) char smraw[];
    __nv_bfloat16* Vh = reinterpret_cast<__nv_bfloat16*>(smraw);
    __nv_bfloat16* Vl = Vh + 64 * PS;
    __nv_bfloat16* Ph = Vl + 64 * PS;
    __nv_bfloat16* Pl = Ph + 2 * 128 * AS2;
    float* ss   = reinterpret_cast<float*>(Pl + 2 * 128 * AS2);
    float* dd   = ss + 128;
    float* rsum = dd + 128;
    float* E1   = rsum + 128;
    float* E5   = E1 + 128;
    float* F1   = E5 + 128;
    float* F5   = F1 + 128;

    const int b = blockIdx.z;
    const int col0 = blockIdx.x * 64;
    const int tid = threadIdx.x, wid = tid >> 5, lane = tid & 31;
    const float* Wb = g_Wh2 + (size_t)b * Nn * HID;

    if (tid < 128) {
        const float sv = g_ss2[b * Nn + tid];
        const float dv = g_dd2[b * Nn + tid];
        ss[tid] = sv; dd[tid] = dv;
        rsum[tid] = 0.f;
        E1[tid] = __expf(sv); E5[tid] = __expf(ALPHA * sv);
        F1[tid] = __expf(dv); F5[tid] = __expf(ALPHA * dv);
    }
    for (int t = tid; t < 64 * 128; t += 256) {
        const int j = t >> 6, d = t & 63;
        const int gc = col0 + d;
        float x = (gc < HID) ? Wb[(size_t)j * HID + gc] : 0.f;
        __nv_bfloat16 hi = __float2bfloat16(x);
        Vh[d * PS + j] = hi;
        Vl[d * PS + j] = __float2bfloat16(x - __bfloat162float(hi));
    }
    __syncthreads();

    const int gi = tid >> 1;
    const int gjg = (tid & 1) << 3;
    const float ssi = ss[gi];
    const float e1i = E1[gi], e5i = E5[gi];
    const int* adjr = adj + ((size_t)b * Nn + gi) * Nn;
    int madj[8];
    float rs = 0.f;

    auto loadM = [&](int s) {
        const int j0 = (s << 4) + gjg;
        *reinterpret_cast<int4*>(madj)     = *reinterpret_cast<const int4*>(adjr + j0);
        *reinterpret_cast<int4*>(madj + 4) = *reinterpret_cast<const int4*>(adjr + j0 + 4);
    };
    auto genP = [&](int s, int buf) {
        const int j0 = (s << 4) + gjg;
        unsigned hp[4], lp[4];
        #pragma unroll
        for (int q = 0; q < 4; q++) {
            const int ja = j0 + 2 * q, jb = ja + 1;
            float p0 = (ssi + dd[ja] > 0.f) ? e1i * F1[ja] : e5i * F5[ja];
            float p1 = (ssi + dd[jb] > 0.f) ? e1i * F1[jb] : e5i * F5[jb];
            p0 = (madj[2 * q] > 0) ? p0 : 0.f;
            p1 = (madj[2 * q + 1] > 0) ? p1 : 0.f;
            rs += p0 + p1;
            __nv_bfloat16 h0 = __float2bfloat16(p0), h1 = __float2bfloat16(p1);
            hp[q] = bfus(h0) | (bfus(h1) << 16);
            lp[q] = bfus(__float2bfloat16(p0 - __bfloat162float(h0)))
                  | (bfus(__float2bfloat16(p1 - __bfloat162float(h1))) << 16);
        }
        *reinterpret_cast<uint4*>(Ph + buf * 128 * AS2 + gi * AS2 + gjg) =
            make_uint4(hp[0], hp[1], hp[2], hp[3]);
        *reinterpret_cast<uint4*>(Pl + buf * 128 * AS2 + gi * AS2 + gjg) =
            make_uint4(lp[0], lp[1], lp[2], lp[3]);
    };

    const int wy = wid & 3, wx = wid >> 2;
    const int lq = lane & 7, lg8 = (lane >> 3) & 1, lg16 = lane >> 4;
    const int fgid = lane >> 2, ftig = lane & 3;

    float acc[2][4][4];
    #pragma unroll
    for (int mt = 0; mt < 2; mt++)
        #pragma unroll
        for (int nt = 0; nt < 4; nt++)
            #pragma unroll
            for (int q = 0; q < 4; q++) acc[mt][nt][q] = 0.f;

    loadM(0);
    genP(0, 0);
    __syncthreads();

    for (int s = 0; s < 8; s++) {
        const int cur = s & 1;
        if (s < 7) loadM(s + 1);

        const __nv_bfloat16* Pc = Ph + cur * 128 * AS2;
        const __nv_bfloat16* Qc = Pl + cur * 128 * AS2;
        unsigned aH[2][4], aL[2][4], bH[4][2], bL[4][2];
        #pragma unroll
        for (int mt = 0; mt < 2; mt++) {
            const int r = wy * 32 + mt * 16 + lq + 8 * lg8;
            ldsm4(Pc + r * AS2 + 8 * lg16, aH[mt][0], aH[mt][1], aH[mt][2], aH[mt][3]);
            ldsm4(Qc + r * AS2 + 8 * lg16, aL[mt][0], aL[mt][1], aL[mt][2], aL[mt][3]);
        }
        #pragma unroll
        for (int p = 0; p < 2; p++) {
            const int rn = wx * 32 + p * 16 + lq + 8 * lg8;
            unsigned r0, r1, r2, r3;
            ldsm4(Vh + rn * PS + s * 16 + 8 * lg16, r0, r1, r2, r3);
            bH[2 * p][0] = r0; bH[2 * p + 1][0] = r1;
            bH[2 * p][1] = r2; bH[2 * p + 1][1] = r3;
            ldsm4(Vl + rn * PS + s * 16 + 8 * lg16, r0, r1, r2, r3);
            bL[2 * p][0] = r0; bL[2 * p + 1][0] = r1;
            bL[2 * p][1] = r2; bL[2 * p + 1][1] = r3;
        }
        #pragma unroll
        for (int mt = 0; mt < 2; mt++)
            #pragma unroll
            for (int nt = 0; nt < 4; nt++) {
                MMA16816(acc[mt][nt], aH[mt][0], aH[mt][1], aH[mt][2], aH[mt][3],
                         bH[nt][0], bH[nt][1]);
                MMA16816(acc[mt][nt], aH[mt][0], aH[mt][1], aH[mt][2], aH[mt][3],
                         bL[nt][0], bL[nt][1]);
                MMA16816(acc[mt][nt], aL[mt][0], aL[mt][1], aL[mt][2], aL[mt][3],
                         bH[nt][0], bH[nt][1]);
            }

        if (s < 7) genP(s + 1, cur ^ 1);
        __syncthreads();
    }

    atomicAdd(&rsum[gi], rs);
    __syncthreads();

    float* Cb = g_O + (size_t)b * Nn * HID;
    #pragma unroll
    for (int mt = 0; mt < 2; mt++) {
        const int r = wy * 32 + mt * 16 + fgid;
        const float inv0 = 1.f / rsum[r];
        const float inv8 = 1.f / rsum[r + 8];
        #pragma unroll
        for (int nt = 0; nt < 4; nt++) {
            const int c = col0 + wx * 32 + nt * 8 + 2 * ftig;
            if (c < HID) {
                float v0 = acc[mt][nt][0] * inv0, v1 = acc[mt][nt][1] * inv0;
                float v2 = acc[mt][nt][2] * inv8, v3 = acc[mt][nt][3] * inv8;
                v0 = (v0 > 0.f) ? v0 : expm1f(v0);
                v1 = (v1 > 0.f) ? v1 : expm1f(v1);
                v2 = (v2 > 0.f) ? v2 : expm1f(v2);
                v3 = (v3 > 0.f) ? v3 : expm1f(v3);
                *reinterpret_cast<float2*>(Cb + (size_t)r * HID + c)       = make_float2(v0, v1);
                *reinterpret_cast<float2*>(Cb + (size_t)(r + 8) * HID + c) = make_float2(v2, v3);
            }
        }
    }
}

// ---------------- ls2 -------------------------------------------------------------
__global__ __launch_bounds__(256) void ls2_kernel()
{
    __shared__ float acc[8 * HID];
    const int b = blockIdx.x;
    const int tid = threadIdx.x, warp = tid >> 5, lane = tid & 31;
    for (int t = tid; t < 8 * HID; t += 256) acc[t] = 0.f;
    __syncthreads();

    const float* O = g_O + (size_t)b * Nn * HID;
    float* accw = acc + warp * HID;
    for (int i = warp; i < 128; i += 8) {
        float o[10];
        #pragma unroll
        for (int t = 0; t < 10; t++) {
            int d = lane + 32 * t;
            o[t] = (d < HID) ? O[(size_t)i * HID + d] : -1e30f;
        }
        float m = o[0];
        #pragma unroll
        for (int t = 1; t < 10; t++) m = fmaxf(m, o[t]);
        m = warp_max(m);
        m = __shfl_sync(0xffffffffu, m, 0);
        float se = 0.f;
        #pragma unroll
        for (int t = 0; t < 10; t++) se += __expf(o[t] - m);
        se = warp_sum(se);
        se = __shfl_sync(0xffffffffu, se, 0);
        const float lse = m + logf(se);
        #pragma unroll
        for (int t = 0; t < 10; t++) {
            int d = lane + 32 * t;
            if (d < HID) accw[d] += o[t] - lse;
        }
    }
    __syncthreads();
    for (int d = tid; d < HID; d += 256) {
        float s = 0.f;
        #pragma unroll
        for (int w = 0; w < 8; w++) s += acc[w * HID + d];
        g_gat[b * HID + d] = s * (1.f / 128.f);
    }
}

// ---------------- head ------------------------------------------------------------
#define HB 2
__global__ __launch_bounds__(256) void head_fused(
    const float* __restrict__ fc2_w, const float* __restrict__ fc2_b,
    const float* __restrict__ Wg,    const float* __restrict__ bg,
    const float* __restrict__ Wf,    const float* __restrict__ bf,
    const float* __restrict__ W1,    const float* __restrict__ b1,
    const float* __restrict__ w2,    const float* __restrict__ b2,
    float* __restrict__ out)
{
    __shared__ float t1s [HB][512];
    __shared__ float gats[HB][HID];
    __shared__ float fpns[HB][HID];
    __shared__ float us  [HB][HID];
    __shared__ float vs  [HB][HID];
    __shared__ float ys  [HB][HID];

    const int b0 = blockIdx.x * HB;
    const int tid = threadIdx.x;

    for (int t = tid; t < HB * 512; t += 256) {
        int r = t >> 9;
        t1s[r][t & 511] = g_t1[(size_t)(b0 + r) * FP2 + (t & 511)];
    }
    for (int t = tid; t < HB * HID; t += 256) {
        int r = t / HID, c = t - r * HID;
        gats[r][c] = g_gat[(size_t)(b0 + r) * HID + c];
    }
    __syncthreads();

    for (int c = tid; c < HID; c += 256) {
        float a[HB] = {};
        #pragma unroll 4
        for (int k = 0; k < 512; k++) {
            float w = fc2_w[(size_t)k * HID + c];
            #pragma unroll
            for (int r = 0; r < HB; r++) a[r] = fmaf(t1s[r][k], w, a[r]);
        }
        float bb = fc2_b[c];
        #pragma unroll
        for (int r = 0; r < HB; r++) fpns[r][c] = a[r] + bb;
    }
    __syncthreads();

    for (int c = tid; c < HID; c += 256) {
        float a[HB] = {}, e[HB] = {};
        #pragma unroll 4
        for (int k = 0; k < HID; k++) {
            float wg = Wg[(size_t)k * HID + c];
            float wf = Wf[(size_t)k * HID + c];
            #pragma unroll
            for (int r = 0; r < HB; r++) {
                a[r] = fmaf(gats[r][k], wg, a[r]);
                e[r] = fmaf(fpns[r][k], wf, e[r]);
            }
        }
        float bbg = bg[c], bbf = bf[c];
        #pragma unroll
        for (int r = 0; r < HB; r++) {
            us[r][c] = fmaxf(a[r] + bbg, 0.f);
            vs[r][c] = fmaxf(e[r] + bbf, 0.f);
        }
    }
    __syncthreads();

    for (int c = tid; c < HID; c += 256) {
        float a[HB] = {};
        #pragma unroll 4
        for (int k = 0; k < HID; k++) {
            float w = W1[(size_t)k * HID + c];
            #pragma unroll
            for (int r = 0; r < HB; r++) a[r] = fmaf(us[r][k], w, a[r]);
        }
        #pragma unroll 4
        for (int k = 0; k < HID; k++) {
            float w = W1[(size_t)(k + HID) * HID + c];
            #pragma unroll
            for (int r = 0; r < HB; r++) a[r] = fmaf(vs[r][k], w, a[r]);
        }
        float bb = b1[c];
        #pragma unroll
        for (int r = 0; r < HB; r++) ys[r][c] = fmaxf(a[r] + bb, 0.f);
    }
    __syncthreads();

    const int warp = tid >> 5, lane = tid & 31;
    if (warp < HB) {
        float s = 0.f;
        for (int k = lane; k < HID; k += 32) s = fmaf(ys[warp][k], w2[k], s);
        s = warp_sum(s);
        if (lane == 0) out[b0 + warp] = 1.f / (1.f + expf(-(s + b2[0])));
    }
}

// ---------------- launch ----------------
extern "C" void kernel_launch(void* const* d_in, const int* in_sizes, int n_in,
                              void* d_out, int out_size)
{
    const float* atom_feats = (const float*)d_in[0];
    const float* fp         = (const float*)d_in[1];
    const float* W_heads    = (const float*)d_in[2];
    const float* a_heads    = (const float*)d_in[3];
    const float* W_out      = (const float*)d_in[4];
    const float* a_out      = (const float*)d_in[5];
    const float* fc1_w      = (const float*)d_in[6];
    const float* fc1_b      = (const float*)d_in[7];
    const float* fc2_w      = (const float*)d_in[8];
    const float* fc2_b      = (const float*)d_in[9];
    const float* fc_gat_w   = (const float*)d_in[10];
    const float* fc_gat_b   = (const float*)d_in[11];
    const float* fc_fpn_w   = (const float*)d_in[12];
    const float* fc_fpn_b   = (const float*)d_in[13];
    const float* ffn_w1     = (const float*)d_in[14];
    const float* ffn_b1     = (const float*)d_in[15];
    const float* ffn_w2     = (const float*)d_in[16];
    const float* ffn_b2     = (const float*)d_in[17];
    const int*   adj        = (const int*)  d_in[18];
    float* out = (float*)d_out;

    __nv_bfloat16 *pApk, *pBpk1, *pHpk, *pBpk3, *pFpk, *pW1k;
    float *pWh, *pWh2, *pPart;
    cudaGetSymbolAddress((void**)&pApk,  g_Apk);
    cudaGetSymbolAddress((void**)&pBpk1, g_Bpk1);
    cudaGetSymbolAddress((void**)&pWh,   g_Wh);
    cudaGetSymbolAddress((void**)&pHpk,  g_hpk);
    cudaGetSymbolAddress((void**)&pBpk3, g_Bpk3);
    cudaGetSymbolAddress((void**)&pWh2,  g_Wh2);
    cudaGetSymbolAddress((void**)&pFpk,  g_fpk);
    cudaGetSymbolAddress((void**)&pW1k,  g_w1k);
    cudaGetSymbolAddress((void**)&pPart, g_part);

    cudaFuncSetAttribute(av2_hmma, cudaFuncAttributeMaxDynamicSharedMemorySize, ATT_SM);

    // 1,2: packing for K1
    pack_atoms<<<(Bsz * Nn * K1P + 255) / 256, 256>>>(atom_feats);
    pack_B1<<<(HD * K1P + 255) / 256, 256>>>(W_heads);
    // 3: K1 on HMMA
    mma_gemm<<<dim3(HD / 128, (Bsz * Nn) / 128, 1), 256>>>(
        pApk, pBpk1, pWh, K1T, K1T, K1T, HD, HD, 0, 0, 0);
    // 4: gat1 fused (separable exp, FMA2 AV)   <-- ncu capture target
    gat1_fused<<<Bsz * Hh, 256>>>(a_heads, adj);
    // 5,6: fc1 packing
    pack_fp<<<(Bsz * KF + 255) / 256, 256>>>(fp);
    pack_w1k<<<(FP2 * KF + 255) / 256, 256>>>(fc1_w);
    // 7,8: fc1 on HMMA split-K + reduce
    mma_gemm<<<dim3(FP2 / 128, Bsz / 128, FS1), 256>>>(
        pFpk, pW1k, pPart, KC1, KFT, KFT, FP2, FP2,
        (long long)KC1, (long long)KC1, (long long)Bsz * FP2);
    fc1_reduce<<<(Bsz * FP2 + 255) / 256, 256>>>(fc1_b);
    // 9: K3 packing (B side)
    pack_B3<<<(N3P * HD + 255) / 256, 256>>>(W_out);
    // 10: K3 on HMMA
    mma_gemm<<<dim3(N3P / 128, (Bsz * Nn) / 128, 1), 256>>>(
        pHpk, pBpk3, pWh2, K3T, K3T, K3T, HID, HID, 0, 0, 0);
    // 11: gat2 scores
    score2_kernel<<<Bsz, 256>>>(a_out);
    // 12: gat2 HMMA fused attention (separable exp)
    av2_hmma<<<dim3(5, 1, Bsz), 256, ATT_SM>>>(adj);
    // 13: gat2 log_softmax + mean
    ls2_kernel<<<Bsz, 256>>>();
    // 14: fused head
    head_fused<<<Bsz / HB, 256>>>(
        fc2_w, fc2_b, fc_gat_w, fc_gat_b, fc_fpn_w, fc_fpn_b,
        ffn_w1, ffn_b1, ffn_w2, ffn_b2, out);
}

// round 17
// speedup vs baseline: 1.4465x; 1.0094x over previous
#include <cuda_runtime.h>
#include <cuda_bf16.h>
#include <math.h>

// Problem constants
#define Bsz 256
#define Nn  128
#define Ff  133
#define Hh  8
#define NHID 64
#define HID 300
#define FP_DIM 1489
#define FP2 512
#define HD (Hh*NHID)     // 512
#define ALPHA 0.2f

#define K1P   160
#define K1T   (3*K1P)    // 480
#define K3T   (3*HD)     // 1536
#define N3P   384
#define KF    1536
#define KFT   (3*KF)     // 4608
#define FS1   12
#define KC1   (KFT/FS1)  // 384

// ---------------- scratch (device globals) ----------------------------------------
__device__ __nv_bfloat16 g_Apk [(size_t)Bsz*Nn * K1T];
__device__ __nv_bfloat16 g_Bpk1[(size_t)HD * K1T];
__device__ float         g_Wh  [(size_t)Bsz*Nn * HD];
__device__ __nv_bfloat16 g_hpk [(size_t)Bsz*Nn * K3T];
__device__ __nv_bfloat16 g_Bpk3[(size_t)N3P * K3T];
__device__ float g_Wh2 [(size_t)Bsz*Nn * HID];
__device__ float g_ss2 [Bsz * Nn];
__device__ float g_dd2 [Bsz * Nn];
__device__ float g_O   [(size_t)Bsz*Nn * HID];
__device__ float g_gat [Bsz * HID];
__device__ __nv_bfloat16 g_fpk [(size_t)Bsz * KFT];
__device__ __nv_bfloat16 g_w1k [(size_t)FP2 * KFT];
__device__ float g_part[(size_t)FS1 * Bsz * FP2];
__device__ float g_t1  [Bsz * FP2];

// ---------------- helpers ----------------
#define FMA2(acc, a, b) \
    asm("fma.rn.f32x2 %0, %1, %2, %0;" : "+l"(acc) : "l"(a), "l"(b))

__device__ __forceinline__ unsigned long long ld2(const float* p) {
    return *reinterpret_cast<const unsigned long long*>(p);
}
__device__ __forceinline__ unsigned long long dup2(float x) {
    unsigned long long r;
    asm("mov.b64 %0, {%1, %1};" : "=l"(r) : "r"(__float_as_uint(x)));
    return r;
}
__device__ __forceinline__ float lo32(unsigned long long v) {
    return __uint_as_float((unsigned)v);
}
__device__ __forceinline__ float hi32(unsigned long long v) {
    return __uint_as_float((unsigned)(v >> 32));
}
__device__ __forceinline__ float warp_sum(float v) {
    #pragma unroll
    for (int o = 16; o; o >>= 1) v += __shfl_down_sync(0xffffffffu, v, o);
    return v;
}
__device__ __forceinline__ float warp_max(float v) {
    #pragma unroll
    for (int o = 16; o; o >>= 1) v = fmaxf(v, __shfl_down_sync(0xffffffffu, v, o));
    return v;
}
__device__ __forceinline__ unsigned smem_u32(const void* p) {
    unsigned a;
    asm("{ .reg .u64 t; cvta.to.shared.u64 t, %1; cvt.u32.u64 %0, t; }" : "=r"(a) : "l"(p));
    return a;
}
__device__ __forceinline__ void ldsm4(const __nv_bfloat16* p,
                                      unsigned& r0, unsigned& r1, unsigned& r2, unsigned& r3) {
    unsigned a = smem_u32(p);
    asm volatile("ldmatrix.sync.aligned.m8n8.x4.shared.b16 {%0,%1,%2,%3}, [%4];"
                 : "=r"(r0), "=r"(r1), "=r"(r2), "=r"(r3) : "r"(a));
}
#define MMA16816(acc, a0, a1, a2, a3, b0, b1) \
    asm volatile("mma.sync.aligned.m16n8k16.row.col.f32.bf16.bf16.f32 " \
                 "{%0,%1,%2,%3}, {%4,%5,%6,%7}, {%8,%9}, {%0,%1,%2,%3};" \
                 : "+f"((acc)[0]), "+f"((acc)[1]), "+f"((acc)[2]), "+f"((acc)[3]) \
                 : "r"(a0), "r"(a1), "r"(a2), "r"(a3), "r"(b0), "r"(b1))
__device__ __forceinline__ unsigned bfus(__nv_bfloat16 x) {
    return (unsigned)__bfloat16_as_ushort(x);
}

// ================= mma_gemm: bf16 HMMA GEMM, 128x128 tile, KC=32, ldmatrix ======
#define MSTR 40
__global__ __launch_bounds__(256) void mma_gemm(
    const __nv_bfloat16* __restrict__ A, const __nv_bfloat16* __restrict__ B,
    float* __restrict__ C, int Ktot, int lda, int ldb, int Nreal, int ldc,
    long long bA, long long bB, long long bC)
{
    __shared__ __align__(16) __nv_bfloat16 As[2][128][MSTR];
    __shared__ __align__(16) __nv_bfloat16 Bs[2][128][MSTR];

    A += (long long)blockIdx.z * bA;
    B += (long long)blockIdx.z * bB;
    C += (long long)blockIdx.z * bC;

    const int tid = threadIdx.x;
    const int wid = tid >> 5, lane = tid & 31;
    const int wy = wid & 3, wx = wid >> 2;
    const int lq = lane & 7, lg8 = (lane >> 3) & 1, lg16 = lane >> 4;
    const int fgid = lane >> 2, ftig = lane & 3;
    const int row0 = blockIdx.y * 128, col0 = blockIdx.x * 128;

    const int lr0 = tid >> 2;
    const int lcq = (tid & 3) << 3;

    uint4 va0, va1, vb0, vb1;
    auto load_g = [&](int k0) {
        va0 = *reinterpret_cast<const uint4*>(A + (size_t)(row0 + lr0) * lda + k0 + lcq);
        va1 = *reinterpret_cast<const uint4*>(A + (size_t)(row0 + lr0 + 64) * lda + k0 + lcq);
        vb0 = *reinterpret_cast<const uint4*>(B + (size_t)(col0 + lr0) * ldb + k0 + lcq);
        vb1 = *reinterpret_cast<const uint4*>(B + (size_t)(col0 + lr0 + 64) * ldb + k0 + lcq);
    };
    auto store_s = [&](int buf) {
        *reinterpret_cast<uint4*>(&As[buf][lr0][lcq])      = va0;
        *reinterpret_cast<uint4*>(&As[buf][lr0 + 64][lcq]) = va1;
        *reinterpret_cast<uint4*>(&Bs[buf][lr0][lcq])      = vb0;
        *reinterpret_cast<uint4*>(&Bs[buf][lr0 + 64][lcq]) = vb1;
    };

    float acc[2][8][4];
    #pragma unroll
    for (int mt = 0; mt < 2; mt++)
        #pragma unroll
        for (int nt = 0; nt < 8; nt++)
            #pragma unroll
            for (int q = 0; q < 4; q++) acc[mt][nt][q] = 0.f;

    const int nsteps = Ktot >> 5;
    load_g(0);
    store_s(0);
    __syncthreads();

    for (int s = 0; s < nsteps; s++) {
        const int cur = s & 1;
        if (s + 1 < nsteps) load_g((s + 1) << 5);

        #pragma unroll
        for (int kk = 0; kk < 32; kk += 16) {
            unsigned af[2][4], bfr[8][2];
            #pragma unroll
            for (int mt = 0; mt < 2; mt++) {
                const int r = wy * 32 + mt * 16 + lq + 8 * lg8;
                ldsm4(&As[cur][r][kk + 8 * lg16],
                      af[mt][0], af[mt][1], af[mt][2], af[mt][3]);
            }
            #pragma unroll
            for (int p = 0; p < 4; p++) {
                const int r = wx * 64 + p * 16 + lq + 8 * lg8;
                unsigned r0, r1, r2, r3;
                ldsm4(&Bs[cur][r][kk + 8 * lg16], r0, r1, r2, r3);
                bfr[2 * p][0] = r0; bfr[2 * p + 1][0] = r1;
                bfr[2 * p][1] = r2; bfr[2 * p + 1][1] = r3;
            }
            #pragma unroll
            for (int mt = 0; mt < 2; mt++)
                #pragma unroll
                for (int nt = 0; nt < 8; nt++)
                    MMA16816(acc[mt][nt], af[mt][0], af[mt][1], af[mt][2], af[mt][3],
                             bfr[nt][0], bfr[nt][1]);
        }

        if (s + 1 < nsteps) store_s(cur ^ 1);
        __syncthreads();
    }

    #pragma unroll
    for (int mt = 0; mt < 2; mt++) {
        const int r0 = row0 + wy * 32 + mt * 16 + fgid;
        #pragma unroll
        for (int nt = 0; nt < 8; nt++) {
            const int c = col0 + wx * 64 + nt * 8 + 2 * ftig;
            if (c < Nreal) {
                *reinterpret_cast<float2*>(C + (size_t)r0 * ldc + c) =
                    make_float2(acc[mt][nt][0], acc[mt][nt][1]);
                *reinterpret_cast<float2*>(C + (size_t)(r0 + 8) * ldc + c) =
                    make_float2(acc[mt][nt][2], acc[mt][nt][3]);
            }
        }
    }
}

// ---------------- packing kernels ------------------------------------------------
__global__ void pack_atoms(const float* __restrict__ src) {
    int t = blockIdx.x * blockDim.x + threadIdx.x;
    if (t >= Bsz * Nn * K1P) return;
    int k = t % K1P, r = t / K1P;
    float x = (k < Ff) ? src[(size_t)r * Ff + k] : 0.f;
    __nv_bfloat16 hi = __float2bfloat16(x);
    __nv_bfloat16 lo = __float2bfloat16(x - __bfloat162float(hi));
    __nv_bfloat16* row = g_Apk + (size_t)r * K1T;
    row[k] = hi; row[K1P + k] = hi; row[2 * K1P + k] = lo;
}
__global__ void pack_B1(const float* __restrict__ W_heads) {
    int t = blockIdx.x * blockDim.x + threadIdx.x;
    if (t >= HD * K1P) return;
    int k = t % K1P, n = t / K1P;
    int h = n >> 6, d = n & 63;
    float x = (k < Ff) ? W_heads[((size_t)h * Ff + k) * NHID + d] : 0.f;
    __nv_bfloat16 hi = __float2bfloat16(x);
    __nv_bfloat16 lo = __float2bfloat16(x - __bfloat162float(hi));
    __nv_bfloat16* row = g_Bpk1 + (size_t)n * K1T;
    row[k] = hi; row[K1P + k] = lo; row[2 * K1P + k] = hi;
}
// tiled transpose: W_out [HD][HID] -> g_Bpk3 [N3P][K3T] rows n, cols k
__global__ void pack_B3_t(const float* __restrict__ W_out) {
    __shared__ float tile[32][33];
    const int k0 = blockIdx.x * 32, n0 = blockIdx.y * 32;
    const int tx = threadIdx.x & 31, ty = threadIdx.x >> 5;   // 32 x 8
    #pragma unroll
    for (int i = 0; i < 32; i += 8) {
        const int k = k0 + ty + i, n = n0 + tx;
        tile[ty + i][tx] = (n < HID) ? W_out[(size_t)k * HID + n] : 0.f;
    }
    __syncthreads();
    #pragma unroll
    for (int i = 0; i < 32; i += 8) {
        const int n = n0 + ty + i, k = k0 + tx;
        const float x = tile[tx][ty + i];
        __nv_bfloat16 hi = __float2bfloat16(x);
        __nv_bfloat16 lo = __float2bfloat16(x - __bfloat162float(hi));
        __nv_bfloat16* row = g_Bpk3 + (size_t)n * K3T;
        row[k] = hi; row[HD + k] = lo; row[2 * HD + k] = hi;
    }
}
__global__ void pack_fp(const float* __restrict__ fp) {
    int t = blockIdx.x * blockDim.x + threadIdx.x;
    if (t >= Bsz * KF) return;
    int k = t % KF, r = t / KF;
    float x = (k < FP_DIM) ? fp[(size_t)r * FP_DIM + k] : 0.f;
    __nv_bfloat16 hi = __float2bfloat16(x);
    __nv_bfloat16 lo = __float2bfloat16(x - __bfloat162float(hi));
    __nv_bfloat16* row = g_fpk + (size_t)r * KFT;
    row[k] = hi; row[KF + k] = hi; row[2 * KF + k] = lo;
}
// tiled transpose: fc1_w [FP_DIM][FP2] -> g_w1k [FP2][KFT]
__global__ void pack_w1k_t(const float* __restrict__ w) {
    __shared__ float tile[32][33];
    const int k0 = blockIdx.x * 32, n0 = blockIdx.y * 32;
    const int tx = threadIdx.x & 31, ty = threadIdx.x >> 5;
    #pragma unroll
    for (int i = 0; i < 32; i += 8) {
        const int k = k0 + ty + i, n = n0 + tx;
        tile[ty + i][tx] = (k < FP_DIM) ? w[(size_t)k * FP2 + n] : 0.f;
    }
    __syncthreads();
    #pragma unroll
    for (int i = 0; i < 32; i += 8) {
        const int n = n0 + ty + i, k = k0 + tx;
        const float x = tile[tx][ty + i];
        __nv_bfloat16 hi = __float2bfloat16(x);
        __nv_bfloat16 lo = __float2bfloat16(x - __bfloat162float(hi));
        __nv_bfloat16* row = g_w1k + (size_t)n * KFT;
        row[k] = hi; row[KF + k] = lo; row[2 * KF + k] = hi;
    }
}

// ---------------- fc1 reduce ------------------------------------------------------
__global__ void fc1_reduce(const float* __restrict__ fc1_b) {
    int t = blockIdx.x * blockDim.x + threadIdx.x;
    if (t >= Bsz * FP2) return;
    float s = 0.f;
    #pragma unroll
    for (int z = 0; z < FS1; z++) s += g_part[(size_t)z * Bsz * FP2 + t];
    g_t1[t] = fmaxf(s + fc1_b[t & (FP2 - 1)], 0.f);
}

// ============ gat1_fused: separable-exp probs + FMA2 AV + elu ====================
__global__ __launch_bounds__(256) void gat1_fused(const float* __restrict__ a_heads,
                                                  const int* __restrict__ adj)
{
    __shared__ __align__(16) float Ws[128 * 68];
    __shared__ __align__(16) float As[2][16][132];
    __shared__ float ss[128], dd[128], rsum[128];
    __shared__ float E1[128], E5[128], F1[128], F5[128];

    const int z = blockIdx.x;
    const int b = z >> 3, h = z & 7;
    const int tid = threadIdx.x, warp = tid >> 5, lane = tid & 31;
    const float* whbase = g_Wh + ((size_t)b * Nn) * HD + h * NHID;

    for (int s = tid; s < 2048; s += 256) {
        int j = s >> 4, q = (s & 15) << 2;
        float4 v = *reinterpret_cast<const float4*>(whbase + (size_t)j * HD + q);
        *reinterpret_cast<float4*>(&Ws[j * 68 + q]) = v;
    }
    if (tid < 128) rsum[tid] = 0.f;
    __syncthreads();

    const float* a1 = a_heads + h * (2 * NHID);
    const float* a2v = a1 + NHID;
    for (int j = warp; j < 128; j += 8) {
        const float w0 = Ws[j * 68 + lane];
        const float w1 = Ws[j * 68 + lane + 32];
        float s1 = fmaf(w0, a1[lane], w1 * a1[lane + 32]);
        float s2 = fmaf(w0, a2v[lane], w1 * a2v[lane + 32]);
        s1 = warp_sum(s1); s2 = warp_sum(s2);
        if (lane == 0) { ss[j] = s1; dd[j] = s2; }
    }
    __syncthreads();

    if (tid < 128) {
        const float sv = ss[tid], dv = dd[tid];
        E1[tid] = __expf(sv); E5[tid] = __expf(ALPHA * sv);
        F1[tid] = __expf(dv); F5[tid] = __expf(ALPHA * dv);
    }
    __syncthreads();

    const int* adjb = adj + (size_t)b * Nn * Nn;
    const int am = tid >> 2;
    const int aq = (tid & 3) << 2;
    const float sm0 = ss[am], sm1 = ss[am + 64];
    const float e1_0 = E1[am], e5_0 = E5[am];
    const float e1_1 = E1[am + 64], e5_1 = E5[am + 64];
    float rs0 = 0.f, rs1 = 0.f;
    int mm0[4], mm1[4];

    auto loadM = [&](int k0) {
        *reinterpret_cast<int4*>(mm0) = *reinterpret_cast<const int4*>(adjb + am * Nn + k0 + aq);
        *reinterpret_cast<int4*>(mm1) = *reinterpret_cast<const int4*>(adjb + (am + 64) * Nn + k0 + aq);
    };
    auto genStore = [&](int k0, int buf) {
        #pragma unroll
        for (int q = 0; q < 4; q++) {
            const int j = k0 + aq + q;
            const float dv = dd[j];
            const float f1 = F1[j], f5 = F5[j];
            float p0 = (sm0 + dv > 0.f) ? e1_0 * f1 : e5_0 * f5;
            float p1 = (sm1 + dv > 0.f) ? e1_1 * f1 : e5_1 * f5;
            p0 = (mm0[q] > 0) ? p0 : 0.f;
            p1 = (mm1[q] > 0) ? p1 : 0.f;
            rs0 += p0; rs1 += p1;
            As[buf][aq + q][am] = p0;
            As[buf][aq + q][am + 64] = p1;
        }
    };

    const int tx = tid & 15, ty = tid >> 4;
    unsigned long long acc[8][2];
    #pragma unroll
    for (int i = 0; i < 8; i++) { acc[i][0] = 0ull; acc[i][1] = 0ull; }

    loadM(0);
    genStore(0, 0);
    __syncthreads();

    for (int s = 0; s < 8; s++) {
        const int cur = s & 1;
        if (s < 7) loadM((s + 1) << 4);
        #pragma unroll
        for (int k = 0; k < 16; k++) {
            unsigned long long aL[8], b2[2];
            #pragma unroll
            for (int ii = 0; ii < 4; ii++) {
                const unsigned long long pr = ld2(&As[cur][k][2 * ty + 32 * ii]);
                aL[2 * ii]     = dup2(lo32(pr));
                aL[2 * ii + 1] = dup2(hi32(pr));
            }
            b2[0] = ld2(&Ws[(s * 16 + k) * 68 + 2 * tx]);
            b2[1] = ld2(&Ws[(s * 16 + k) * 68 + 2 * tx + 32]);
            #pragma unroll
            for (int i = 0; i < 8; i++) {
                FMA2(acc[i][0], aL[i], b2[0]);
                FMA2(acc[i][1], aL[i], b2[1]);
            }
        }
        if (s < 7) genStore((s + 1) << 4, cur ^ 1);
        __syncthreads();
    }

    atomicAdd(&rsum[am], rs0);
    atomicAdd(&rsum[am + 64], rs1);
    __syncthreads();

    #pragma unroll
    for (int i = 0; i < 8; i++) {
        const int r = 2 * ty + 32 * (i >> 1) + (i & 1);
        const float inv = 1.f / rsum[r];
        __nv_bfloat16* rowp = g_hpk + (size_t)(b * Nn + r) * K3T + h * NHID;
        #pragma unroll
        for (int jj = 0; jj < 2; jj++) {
            const int c = 2 * (tx + 16 * jj);
            float v0 = lo32(acc[i][jj]) * inv;
            float v1 = hi32(acc[i][jj]) * inv;
            v0 = (v0 > 0.f) ? v0 : expm1f(v0);
            v1 = (v1 > 0.f) ? v1 : expm1f(v1);
            __nv_bfloat16 h0 = __float2bfloat16(v0);
            __nv_bfloat16 h1 = __float2bfloat16(v1);
            __nv_bfloat16 l0 = __float2bfloat16(v0 - __bfloat162float(h0));
            __nv_bfloat16 l1 = __float2bfloat16(v1 - __bfloat162float(h1));
            unsigned hp = bfus(h0) | (bfus(h1) << 16);
            unsigned lp = bfus(l0) | (bfus(l1) << 16);
            *reinterpret_cast<unsigned*>(rowp + c)           = hp;
            *reinterpret_cast<unsigned*>(rowp + HD + c)      = hp;
            *reinterpret_cast<unsigned*>(rowp + 2 * HD + c)  = lp;
        }
    }
}

// ---------------- score2 ----------------------------------------------------------
__global__ __launch_bounds__(256) void score2_kernel(const float* __restrict__ a_out)
{
    const int b = blockIdx.x;
    const int tid = threadIdx.x, warp = tid >> 5, lane = tid & 31;
    const float* W = g_Wh2 + (size_t)b * Nn * HID;
    for (int j = warp; j < 128; j += 8) {
        float s1 = 0.f, s2 = 0.f;
        #pragma unroll
        for (int t = 0; t < 10; t++) {
            int d = lane + 32 * t;
            if (d < HID) {
                float w = W[(size_t)j * HID + d];
                s1 = fmaf(w, a_out[d], s1);
                s2 = fmaf(w, a_out[HID + d], s2);
            }
        }
        s1 = warp_sum(s1); s2 = warp_sum(s2);
        if (lane == 0) { g_ss2[b * Nn + j] = s1; g_dd2[b * Nn + j] = s2; }
    }
}

// ============ av2_hmma: separable-exp probs + HMMA AV, grid (5,1,Bsz) ============
#define PS   136
#define AS2  24
#define ATT_SM (64*PS*2*2 + 2*128*AS2*2*2 + 3*128*4 + 4*128*4)
__global__ __launch_bounds__(256) void av2_hmma(const int* __restrict__ adj)
{
    extern __shared__ __align__(16) char smraw[];
    __nv_bfloat16* Vh = reinterpret_cast<__nv_bfloat16*>(smraw);
    __nv_bfloat16* Vl = Vh + 64 * PS;
    __nv_bfloat16* Ph = Vl + 64 * PS;
    __nv_bfloat16* Pl = Ph + 2 * 128 * AS2;
    float* ss   = reinterpret_cast<float*>(Pl + 2 * 128 * AS2);
    float* dd   = ss + 128;
    float* rsum = dd + 128;
    float* E1   = rsum + 128;
    float* E5   = E1 + 128;
    float* F1   = E5 + 128;
    float* F5   = F1 + 128;

    const int b = blockIdx.z;
    const int col0 = blockIdx.x * 64;
    const int tid = threadIdx.x, wid = tid >> 5, lane = tid & 31;
    const float* Wb = g_Wh2 + (size_t)b * Nn * HID;

    if (tid < 128) {
        const float sv = g_ss2[b * Nn + tid];
        const float dv = g_dd2[b * Nn + tid];
        ss[tid] = sv; dd[tid] = dv;
        rsum[tid] = 0.f;
        E1[tid] = __expf(sv); E5[tid] = __expf(ALPHA * sv);
        F1[tid] = __expf(dv); F5[tid] = __expf(ALPHA * dv);
    }
    for (int t = tid; t < 64 * 128; t += 256) {
        const int j = t >> 6, d = t & 63;
        const int gc = col0 + d;
        float x = (gc < HID) ? Wb[(size_t)j * HID + gc] : 0.f;
        __nv_bfloat16 hi = __float2bfloat16(x);
        Vh[d * PS + j] = hi;
        Vl[d * PS + j] = __float2bfloat16(x - __bfloat162float(hi));
    }
    __syncthreads();

    const int gi = tid >> 1;
    const int gjg = (tid & 1) << 3;
    const float ssi = ss[gi];
    const float e1i = E1[gi], e5i = E5[gi];
    const int* adjr = adj + ((size_t)b * Nn + gi) * Nn;
    int madj[8];
    float rs = 0.f;

    auto loadM = [&](int s) {
        const int j0 = (s << 4) + gjg;
        *reinterpret_cast<int4*>(madj)     = *reinterpret_cast<const int4*>(adjr + j0);
        *reinterpret_cast<int4*>(madj + 4) = *reinterpret_cast<const int4*>(adjr + j0 + 4);
    };
    auto genP = [&](int s, int buf) {
        const int j0 = (s << 4) + gjg;
        unsigned hp[4], lp[4];
        #pragma unroll
        for (int q = 0; q < 4; q++) {
            const int ja = j0 + 2 * q, jb = ja + 1;
            float p0 = (ssi + dd[ja] > 0.f) ? e1i * F1[ja] : e5i * F5[ja];
            float p1 = (ssi + dd[jb] > 0.f) ? e1i * F1[jb] : e5i * F5[jb];
            p0 = (madj[2 * q] > 0) ? p0 : 0.f;
            p1 = (madj[2 * q + 1] > 0) ? p1 : 0.f;
            rs += p0 + p1;
            __nv_bfloat16 h0 = __float2bfloat16(p0), h1 = __float2bfloat16(p1);
            hp[q] = bfus(h0) | (bfus(h1) << 16);
            lp[q] = bfus(__float2bfloat16(p0 - __bfloat162float(h0)))
                  | (bfus(__float2bfloat16(p1 - __bfloat162float(h1))) << 16);
        }
        *reinterpret_cast<uint4*>(Ph + buf * 128 * AS2 + gi * AS2 + gjg) =
            make_uint4(hp[0], hp[1], hp[2], hp[3]);
        *reinterpret_cast<uint4*>(Pl + buf * 128 * AS2 + gi * AS2 + gjg) =
            make_uint4(lp[0], lp[1], lp[2], lp[3]);
    };

    const int wy = wid & 3, wx = wid >> 2;
    const int lq = lane & 7, lg8 = (lane >> 3) & 1, lg16 = lane >> 4;
    const int fgid = lane >> 2, ftig = lane & 3;

    float acc[2][4][4];
    #pragma unroll
    for (int mt = 0; mt < 2; mt++)
        #pragma unroll
        for (int nt = 0; nt < 4; nt++)
            #pragma unroll
            for (int q = 0; q < 4; q++) acc[mt][nt][q] = 0.f;

    loadM(0);
    genP(0, 0);
    __syncthreads();

    for (int s = 0; s < 8; s++) {
        const int cur = s & 1;
        if (s < 7) loadM(s + 1);

        const __nv_bfloat16* Pc = Ph + cur * 128 * AS2;
        const __nv_bfloat16* Qc = Pl + cur * 128 * AS2;
        unsigned aH[2][4], aL[2][4], bH[4][2], bL[4][2];
        #pragma unroll
        for (int mt = 0; mt < 2; mt++) {
            const int r = wy * 32 + mt * 16 + lq + 8 * lg8;
            ldsm4(Pc + r * AS2 + 8 * lg16, aH[mt][0], aH[mt][1], aH[mt][2], aH[mt][3]);
            ldsm4(Qc + r * AS2 + 8 * lg16, aL[mt][0], aL[mt][1], aL[mt][2], aL[mt][3]);
        }
        #pragma unroll
        for (int p = 0; p < 2; p++) {
            const int rn = wx * 32 + p * 16 + lq + 8 * lg8;
            unsigned r0, r1, r2, r3;
            ldsm4(Vh + rn * PS + s * 16 + 8 * lg16, r0, r1, r2, r3);
            bH[2 * p][0] = r0; bH[2 * p + 1][0] = r1;
            bH[2 * p][1] = r2; bH[2 * p + 1][1] = r3;
            ldsm4(Vl + rn * PS + s * 16 + 8 * lg16, r0, r1, r2, r3);
            bL[2 * p][0] = r0; bL[2 * p + 1][0] = r1;
            bL[2 * p][1] = r2; bL[2 * p + 1][1] = r3;
        }
        #pragma unroll
        for (int mt = 0; mt < 2; mt++)
            #pragma unroll
            for (int nt = 0; nt < 4; nt++) {
                MMA16816(acc[mt][nt], aH[mt][0], aH[mt][1], aH[mt][2], aH[mt][3],
                         bH[nt][0], bH[nt][1]);
                MMA16816(acc[mt][nt], aH[mt][0], aH[mt][1], aH[mt][2], aH[mt][3],
                         bL[nt][0], bL[nt][1]);
                MMA16816(acc[mt][nt], aL[mt][0], aL[mt][1], aL[mt][2], aL[mt][3],
                         bH[nt][0], bH[nt][1]);
            }

        if (s < 7) genP(s + 1, cur ^ 1);
        __syncthreads();
    }

    atomicAdd(&rsum[gi], rs);
    __syncthreads();

    float* Cb = g_O + (size_t)b * Nn * HID;
    #pragma unroll
    for (int mt = 0; mt < 2; mt++) {
        const int r = wy * 32 + mt * 16 + fgid;
        const float inv0 = 1.f / rsum[r];
        const float inv8 = 1.f / rsum[r + 8];
        #pragma unroll
        for (int nt = 0; nt < 4; nt++) {
            const int c = col0 + wx * 32 + nt * 8 + 2 * ftig;
            if (c < HID) {
                float v0 = acc[mt][nt][0] * inv0, v1 = acc[mt][nt][1] * inv0;
                float v2 = acc[mt][nt][2] * inv8, v3 = acc[mt][nt][3] * inv8;
                v0 = (v0 > 0.f) ? v0 : expm1f(v0);
                v1 = (v1 > 0.f) ? v1 : expm1f(v1);
                v2 = (v2 > 0.f) ? v2 : expm1f(v2);
                v3 = (v3 > 0.f) ? v3 : expm1f(v3);
                *reinterpret_cast<float2*>(Cb + (size_t)r * HID + c)       = make_float2(v0, v1);
                *reinterpret_cast<float2*>(Cb + (size_t)(r + 8) * HID + c) = make_float2(v2, v3);
            }
        }
    }
}

// ---------------- ls2 -------------------------------------------------------------
__global__ __launch_bounds__(256) void ls2_kernel()
{
    __shared__ float acc[8 * HID];
    const int b = blockIdx.x;
    const int tid = threadIdx.x, warp = tid >> 5, lane = tid & 31;
    for (int t = tid; t < 8 * HID; t += 256) acc[t] = 0.f;
    __syncthreads();

    const float* O = g_O + (size_t)b * Nn * HID;
    float* accw = acc + warp * HID;
    for (int i = warp; i < 128; i += 8) {
        float o[10];
        #pragma unroll
        for (int t = 0; t < 10; t++) {
            int d = lane + 32 * t;
            o[t] = (d < HID) ? O[(size_t)i * HID + d] : -1e30f;
        }
        float m = o[0];
        #pragma unroll
        for (int t = 1; t < 10; t++) m = fmaxf(m, o[t]);
        m = warp_max(m);
        m = __shfl_sync(0xffffffffu, m, 0);
        float se = 0.f;
        #pragma unroll
        for (int t = 0; t < 10; t++) se += __expf(o[t] - m);
        se = warp_sum(se);
        se = __shfl_sync(0xffffffffu, se, 0);
        const float lse = m + logf(se);
        #pragma unroll
        for (int t = 0; t < 10; t++) {
            int d = lane + 32 * t;
            if (d < HID) accw[d] += o[t] - lse;
        }
    }
    __syncthreads();
    for (int d = tid; d < HID; d += 256) {
        float s = 0.f;
        #pragma unroll
        for (int w = 0; w < 8; w++) s += acc[w * HID + d];
        g_gat[b * HID + d] = s * (1.f / 128.f);
    }
}

// ---------------- head ------------------------------------------------------------
#define HB 2
__global__ __launch_bounds__(256) void head_fused(
    const float* __restrict__ fc2_w, const float* __restrict__ fc2_b,
    const float* __restrict__ Wg,    const float* __restrict__ bg,
    const float* __restrict__ Wf,    const float* __restrict__ bf,
    const float* __restrict__ W1,    const float* __restrict__ b1,
    const float* __restrict__ w2,    const float* __restrict__ b2,
    float* __restrict__ out)
{
    __shared__ float t1s [HB][512];
    __shared__ float gats[HB][HID];
    __shared__ float fpns[HB][HID];
    __shared__ float us  [HB][HID];
    __shared__ float vs  [HB][HID];
    __shared__ float ys  [HB][HID];

    const int b0 = blockIdx.x * HB;
    const int tid = threadIdx.x;

    for (int t = tid; t < HB * 512; t += 256) {
        int r = t >> 9;
        t1s[r][t & 511] = g_t1[(size_t)(b0 + r) * FP2 + (t & 511)];
    }
    for (int t = tid; t < HB * HID; t += 256) {
        int r = t / HID, c = t - r * HID;
        gats[r][c] = g_gat[(size_t)(b0 + r) * HID + c];
    }
    __syncthreads();

    for (int c = tid; c < HID; c += 256) {
        float a[HB] = {};
        #pragma unroll 4
        for (int k = 0; k < 512; k++) {
            float w = fc2_w[(size_t)k * HID + c];
            #pragma unroll
            for (int r = 0; r < HB; r++) a[r] = fmaf(t1s[r][k], w, a[r]);
        }
        float bb = fc2_b[c];
        #pragma unroll
        for (int r = 0; r < HB; r++) fpns[r][c] = a[r] + bb;
    }
    __syncthreads();

    for (int c = tid; c < HID; c += 256) {
        float a[HB] = {}, e[HB] = {};
        #pragma unroll 4
        for (int k = 0; k < HID; k++) {
            float wg = Wg[(size_t)k * HID + c];
            float wf = Wf[(size_t)k * HID + c];
            #pragma unroll
            for (int r = 0; r < HB; r++) {
                a[r] = fmaf(gats[r][k], wg, a[r]);
                e[r] = fmaf(fpns[r][k], wf, e[r]);
            }
        }
        float bbg = bg[c], bbf = bf[c];
        #pragma unroll
        for (int r = 0; r < HB; r++) {
            us[r][c] = fmaxf(a[r] + bbg, 0.f);
            vs[r][c] = fmaxf(e[r] + bbf, 0.f);
        }
    }
    __syncthreads();

    for (int c = tid; c < HID; c += 256) {
        float a[HB] = {};
        #pragma unroll 4
        for (int k = 0; k < HID; k++) {
            float w = W1[(size_t)k * HID + c];
            #pragma unroll
            for (int r = 0; r < HB; r++) a[r] = fmaf(us[r][k], w, a[r]);
        }
        #pragma unroll 4
        for (int k = 0; k < HID; k++) {
            float w = W1[(size_t)(k + HID) * HID + c];
            #pragma unroll
            for (int r = 0; r < HB; r++) a[r] = fmaf(vs[r][k], w, a[r]);
        }
        float bb = b1[c];
        #pragma unroll
        for (int r = 0; r < HB; r++) ys[r][c] = fmaxf(a[r] + bb, 0.f);
    }
    __syncthreads();

    const int warp = tid >> 5, lane = tid & 31;
    if (warp < HB) {
        float s = 0.f;
        for (int k = lane; k < HID; k += 32) s = fmaf(ys[warp][k], w2[k], s);
        s = warp_sum(s);
        if (lane == 0) out[b0 + warp] = 1.f / (1.f + expf(-(s + b2[0])));
    }
}

// ---------------- launch ----------------
extern "C" void kernel_launch(void* const* d_in, const int* in_sizes, int n_in,
                              void* d_out, int out_size)
{
    const float* atom_feats = (const float*)d_in[0];
    const float* fp         = (const float*)d_in[1];
    const float* W_heads    = (const float*)d_in[2];
    const float* a_heads    = (const float*)d_in[3];
    const float* W_out      = (const float*)d_in[4];
    const float* a_out      = (const float*)d_in[5];
    const float* fc1_w      = (const float*)d_in[6];
    const float* fc1_b      = (const float*)d_in[7];
    const float* fc2_w      = (const float*)d_in[8];
    const float* fc2_b      = (const float*)d_in[9];
    const float* fc_gat_w   = (const float*)d_in[10];
    const float* fc_gat_b   = (const float*)d_in[11];
    const float* fc_fpn_w   = (const float*)d_in[12];
    const float* fc_fpn_b   = (const float*)d_in[13];
    const float* ffn_w1     = (const float*)d_in[14];
    const float* ffn_b1     = (const float*)d_in[15];
    const float* ffn_w2     = (const float*)d_in[16];
    const float* ffn_b2     = (const float*)d_in[17];
    const int*   adj        = (const int*)  d_in[18];
    float* out = (float*)d_out;

    __nv_bfloat16 *pApk, *pBpk1, *pHpk, *pBpk3, *pFpk, *pW1k;
    float *pWh, *pWh2, *pPart;
    cudaGetSymbolAddress((void**)&pApk,  g_Apk);
    cudaGetSymbolAddress((void**)&pBpk1, g_Bpk1);
    cudaGetSymbolAddress((void**)&pWh,   g_Wh);
    cudaGetSymbolAddress((void**)&pHpk,  g_hpk);
    cudaGetSymbolAddress((void**)&pBpk3, g_Bpk3);
    cudaGetSymbolAddress((void**)&pWh2,  g_Wh2);
    cudaGetSymbolAddress((void**)&pFpk,  g_fpk);
    cudaGetSymbolAddress((void**)&pW1k,  g_w1k);
    cudaGetSymbolAddress((void**)&pPart, g_part);

    cudaFuncSetAttribute(av2_hmma, cudaFuncAttributeMaxDynamicSharedMemorySize, ATT_SM);

    // forked side stream for the independent fc1 chain (graph-capturable fork/join)
    cudaStream_t s1;
    cudaStreamCreateWithFlags(&s1, cudaStreamNonBlocking);
    cudaEvent_t e0, e1;
    cudaEventCreateWithFlags(&e0, cudaEventDisableTiming);
    cudaEventCreateWithFlags(&e1, cudaEventDisableTiming);

    cudaEventRecord(e0, 0);
    cudaStreamWaitEvent(s1, e0, 0);
    // ---- chain B (fc1 branch) on s1 ----
    pack_fp<<<(Bsz * KF + 255) / 256, 256, 0, s1>>>(fp);
    pack_w1k_t<<<dim3(KF / 32, FP2 / 32), 256, 0, s1>>>(fc1_w);
    mma_gemm<<<dim3(FP2 / 128, Bsz / 128, FS1), 256, 0, s1>>>(
        pFpk, pW1k, pPart, KC1, KFT, KFT, FP2, FP2,
        (long long)KC1, (long long)KC1, (long long)Bsz * FP2);
    fc1_reduce<<<(Bsz * FP2 + 255) / 256, 256, 0, s1>>>(fc1_b);
    cudaEventRecord(e1, s1);

    // ---- chain A (GAT) on default stream ----
    pack_atoms<<<(Bsz * Nn * K1P + 255) / 256, 256>>>(atom_feats);
    pack_B1<<<(HD * K1P + 255) / 256, 256>>>(W_heads);
    mma_gemm<<<dim3(HD / 128, (Bsz * Nn) / 128, 1), 256>>>(
        pApk, pBpk1, pWh, K1T, K1T, K1T, HD, HD, 0, 0, 0);
    gat1_fused<<<Bsz * Hh, 256>>>(a_heads, adj);
    pack_B3_t<<<dim3(HD / 32, N3P / 32), 256>>>(W_out);
    mma_gemm<<<dim3(N3P / 128, (Bsz * Nn) / 128, 1), 256>>>(
        pHpk, pBpk3, pWh2, K3T, K3T, K3T, HID, HID, 0, 0, 0);
    score2_kernel<<<Bsz, 256>>>(a_out);
    av2_hmma<<<dim3(5, 1, Bsz), 256, ATT_SM>>>(adj);
    ls2_kernel<<<Bsz, 256>>>();

    // join fc1 branch, then head
    cudaStreamWaitEvent(0, e1, 0);
    head_fused<<<Bsz / HB, 256>>>(
        fc2_w, fc2_b, fc_gat_w, fc_gat_b, fc_fpn_w, fc_fpn_b,
        ffn_w1, ffn_b1, ffn_w2, ffn_b2, out);
}